// round 1
// baseline (speedup 1.0000x reference)
#include <cuda_runtime.h>
#include <math.h>

// Problem constants
#define BB 8
#define HH 64
#define WW 64
#define CC 128
#define DD 128
#define LL 4096            // H*W
#define NPIX (BB*LL)       // 32768
#define NS 8               // D_STATE
#define RR 8               // DT_RANK

// Scratch (device globals; no allocations allowed)
__device__ float g_t1[NPIX*DD];     // grouped1x1(x,w1)
__device__ float g_xs[NPIX*DD];     // after dwconv+silu (mamba input)
__device__ float g_u0[NPIX*DD];     // in_proj u (pre conv1d)
__device__ float g_z [NPIX*DD];     // in_proj z
__device__ float g_u [NPIX*DD];     // post conv1d + silu
__device__ float g_dl[NPIX*DD];     // delta
__device__ float g_Bm[NPIX*NS];
__device__ float g_Cm[NPIX*NS];
__device__ float g_yp[NPIX*DD];     // scan output * silu(z)

__device__ __forceinline__ float siluf(float v){ return v / (1.f + __expf(-v)); }

// ---------------------------------------------------------------- K1: grouped 1x1
__global__ void k_g1(const float* __restrict__ x, const float* __restrict__ w,
                     float* __restrict__ out){
    __shared__ float ws[4096];
    for (int i = threadIdx.x; i < 4096; i += 256) ws[i] = w[i];
    __syncthreads();
    int idx = blockIdx.x * 256 + threadIdx.x;
    int c = idx & 127; int pix = idx >> 7;
    int g = c >> 5, o = c & 31;
    const float* xr = x + pix*128 + g*32;
    const float* wr = ws + (g*32 + o)*32;
    float acc = 0.f;
#pragma unroll
    for (int i = 0; i < 32; i += 4){
        float4 wv = *(const float4*)(wr + i);
        float4 xv = *(const float4*)(xr + i);
        acc = fmaf(wv.x, xv.x, acc); acc = fmaf(wv.y, xv.y, acc);
        acc = fmaf(wv.z, xv.z, acc); acc = fmaf(wv.w, xv.w, acc);
    }
    out[idx] = acc;
}

// ---------------------------------------------------------------- K2: depthwise 3x3 + silu
__global__ void k_dw(const float* __restrict__ t1, const float* __restrict__ dw,
                     float* __restrict__ out){
    int idx = blockIdx.x * 256 + threadIdx.x;
    int d = idx & 127;
    int pix = idx >> 7;
    int wc = pix & 63; int h = (pix >> 6) & 63; int b = pix >> 12;
    float acc = 0.f;
#pragma unroll
    for (int kh = 0; kh < 3; kh++){
        int hh = h + kh - 1; if (hh < 0 || hh >= 64) continue;
#pragma unroll
        for (int kw = 0; kw < 3; kw++){
            int ww = wc + kw - 1; if (ww < 0 || ww >= 64) continue;
            acc = fmaf(t1[(((b*64 + hh)*64 + ww) << 7) + d],
                       dw[(kh*3 + kw)*128 + d], acc);
        }
    }
    out[idx] = siluf(acc);
}

// ---------------------------------------------------------------- K3: in_proj (128 -> 256), split u/z
// 256 threads, 32 pixels per block
__global__ void k_inproj(const float* __restrict__ xs, const float* __restrict__ w,
                         float* __restrict__ ub, float* __restrict__ zb){
    __shared__ float xt[32*128];
    int pix0 = blockIdx.x * 32;
    for (int i = threadIdx.x; i < 32*128; i += 256) xt[i] = xs[pix0*128 + i];
    __syncthreads();
    int e = threadIdx.x;
    float acc[32];
#pragma unroll
    for (int p = 0; p < 32; p++) acc[p] = 0.f;
    const float* wr = w + e*128;
    for (int d = 0; d < 128; d += 4){
        float4 wv = *(const float4*)(wr + d);
#pragma unroll
        for (int p = 0; p < 32; p++){
            float4 xv = *(const float4*)(xt + p*128 + d);
            acc[p] = fmaf(wv.x, xv.x, acc[p]); acc[p] = fmaf(wv.y, xv.y, acc[p]);
            acc[p] = fmaf(wv.z, xv.z, acc[p]); acc[p] = fmaf(wv.w, xv.w, acc[p]);
        }
    }
    float* outb = (e < 128) ? (ub + e) : (zb + (e - 128));
#pragma unroll
    for (int p = 0; p < 32; p++) outb[(pix0 + p)*128] = acc[p];
}

// ---------------------------------------------------------------- K4: causal conv1d(k=3) + silu
__global__ void k_conv1d(const float* __restrict__ u0, const float* __restrict__ cw,
                         const float* __restrict__ cb, float* __restrict__ uo){
    int idx = blockIdx.x * 256 + threadIdx.x;
    int d = idx & 127;
    int pix = idx >> 7;
    int l = pix & (LL - 1);
    float w0 = cw[d*3], w1 = cw[d*3 + 1], w2 = cw[d*3 + 2];
    float acc = fmaf(w2, u0[idx], cb[d]);
    if (l >= 1) acc = fmaf(w1, u0[idx - 128], acc);
    if (l >= 2) acc = fmaf(w0, u0[idx - 256], acc);
    uo[idx] = siluf(acc);
}

// ---------------------------------------------------------------- K5: x_proj (128->24) + dt_proj (8->128) + softplus
// 128 threads, 8 pixels per block
__global__ void k_xproj(const float* __restrict__ u, const float* __restrict__ xpw,
                        const float* __restrict__ dtw, const float* __restrict__ dtb,
                        float* __restrict__ dl, float* __restrict__ Bb, float* __restrict__ Cb){
    __shared__ float ut[8*128];
    __shared__ float xd[8*24];
    __shared__ float wx[24*128];
    __shared__ float wd[128*8];
    int pix0 = blockIdx.x * 8;
    int t = threadIdx.x;
    for (int i = t; i < 8*128; i += 128) ut[i] = u[pix0*128 + i];
    for (int i = t; i < 24*128; i += 128) wx[i] = xpw[i];
    for (int i = t; i < 128*8; i += 128) wd[i] = dtw[i];
    __syncthreads();
    for (int o = t; o < 192; o += 128){
        int p = o / 24, j = o % 24;
        const float* wr = wx + j*128;
        const float* ur = ut + p*128;
        float acc = 0.f;
#pragma unroll
        for (int d = 0; d < 128; d += 4){
            float4 wv = *(const float4*)(wr + d);
            float4 uv = *(const float4*)(ur + d);
            acc = fmaf(wv.x, uv.x, acc); acc = fmaf(wv.y, uv.y, acc);
            acc = fmaf(wv.z, uv.z, acc); acc = fmaf(wv.w, uv.w, acc);
        }
        xd[p*24 + j] = acc;
    }
    __syncthreads();
    int d = t;
    float bias = dtb[d];
#pragma unroll
    for (int p = 0; p < 8; p++){
        float acc = bias;
#pragma unroll
        for (int r = 0; r < 8; r++) acc = fmaf(xd[p*24 + r], wd[d*8 + r], acc);
        float sp = (acc > 20.f) ? acc : log1pf(__expf(acc));
        dl[(pix0 + p)*128 + d] = sp;
    }
    if (t < 64){
        int p = t >> 3, n = t & 7;
        Bb[(pix0 + p)*8 + n] = xd[p*24 + 8 + n];
        Cb[(pix0 + p)*8 + n] = xd[p*24 + 16 + n];
    }
}

// ---------------------------------------------------------------- K6: selective scan
// grid: 8 b * 16 dblk = 128 blocks; block: 64 threads = 8 d * 8 n
__global__ void k_scan(const float* __restrict__ dl, const float* __restrict__ u,
                       const float* __restrict__ z, const float* __restrict__ Bb,
                       const float* __restrict__ Cb, const float* __restrict__ A_log,
                       const float* __restrict__ Dp, float* __restrict__ yp){
    int b = blockIdx.x >> 4;
    int dblk = blockIdx.x & 15;
    int t = threadIdx.x;
    int dsub = t >> 3, n = t & 7;
    int d = dblk*8 + dsub;
    float Av = -__expf(A_log[d*8 + n]);
    float Dv = Dp[d];
    float h = 0.f;
    int base = b*LL*128 + d;
    int nbase = b*LL*8 + n;
    float de = dl[base], uu = u[base], zz = z[base];
    float Bv = Bb[nbase], Cv = Cb[nbase];
    for (int l = 0; l < LL; l++){
        float de2 = 0.f, uu2 = 0.f, zz2 = 0.f, Bv2 = 0.f, Cv2 = 0.f;
        if (l + 1 < LL){
            int o = base + (l + 1)*128;
            de2 = dl[o]; uu2 = u[o]; zz2 = z[o];
            int o2 = nbase + (l + 1)*8;
            Bv2 = Bb[o2]; Cv2 = Cb[o2];
        }
        float dA = __expf(de * Av);
        h = fmaf(dA, h, de * uu * Bv);
        float y = h * Cv;
        y += __shfl_xor_sync(0xffffffffu, y, 1);
        y += __shfl_xor_sync(0xffffffffu, y, 2);
        y += __shfl_xor_sync(0xffffffffu, y, 4);
        if (n == 0){
            float val = fmaf(uu, Dv, y);
            yp[base + l*128] = val * siluf(zz);
        }
        de = de2; uu = uu2; zz = zz2; Bv = Bv2; Cv = Cv2;
    }
}

// ---------------------------------------------------------------- K7: out_proj + LayerNorm + gate branch + out grouped 1x1
// 128 threads, 16 pixels per block
__global__ void k_final(const float* __restrict__ yp, const float* __restrict__ opw,
                        const float* __restrict__ gamma, const float* __restrict__ beta,
                        const float* __restrict__ x, const float* __restrict__ w2,
                        const float* __restrict__ wout, float* __restrict__ out){
    const int P = 16;
    __shared__ float yt[P*128];
    __shared__ float mt[P*132];
    __shared__ float xt[P*128];
    __shared__ float fs[P*128];
    __shared__ float mus[P], rss[P];
    int pix0 = blockIdx.x * P;
    int t = threadIdx.x;
    for (int i = t; i < P*128; i += 128){
        yt[i] = yp[pix0*128 + i];
        xt[i] = x[pix0*128 + i];
    }
    __syncthreads();
    int e = t;
    float acc[P];
#pragma unroll
    for (int p = 0; p < P; p++) acc[p] = 0.f;
    const float* wr = opw + e*128;
    for (int dd = 0; dd < 128; dd += 4){
        float4 wv = *(const float4*)(wr + dd);
#pragma unroll
        for (int p = 0; p < P; p++){
            float4 yv = *(const float4*)(yt + p*128 + dd);
            acc[p] = fmaf(wv.x, yv.x, acc[p]); acc[p] = fmaf(wv.y, yv.y, acc[p]);
            acc[p] = fmaf(wv.z, yv.z, acc[p]); acc[p] = fmaf(wv.w, yv.w, acc[p]);
        }
    }
#pragma unroll
    for (int p = 0; p < P; p++) mt[p*132 + e] = acc[p];
    __syncthreads();
    if (t < P){
        float s = 0.f;
        for (int i = 0; i < 128; i++) s += mt[t*132 + i];
        float mu = s * (1.f/128.f);
        float v = 0.f;
        for (int i = 0; i < 128; i++){ float dv = mt[t*132 + i] - mu; v = fmaf(dv, dv, v); }
        mus[t] = mu;
        rss[t] = rsqrtf(v * (1.f/128.f) + 1e-5f);
    }
    __syncthreads();
    float ga = gamma[e], be = beta[e];
    int g = e >> 5;
    // w2 row for this output channel -> registers (32 floats)
    float4 w2r[8];
#pragma unroll
    for (int i = 0; i < 8; i++) w2r[i] = *(const float4*)(w2 + e*32 + i*4);
#pragma unroll 1
    for (int p = 0; p < P; p++){
        float x1n = fmaf((mt[p*132 + e] - mus[p]) * rss[p], ga, be);
        const float* xr = xt + p*128 + g*32;
        float a2 = 0.f;
#pragma unroll
        for (int i = 0; i < 8; i++){
            float4 xv = *(const float4*)(xr + i*4);
            a2 = fmaf(w2r[i].x, xv.x, a2); a2 = fmaf(w2r[i].y, xv.y, a2);
            a2 = fmaf(w2r[i].z, xv.z, a2); a2 = fmaf(w2r[i].w, xv.w, a2);
        }
        fs[p*128 + e] = x1n * siluf(a2);
    }
    __syncthreads();
    // wout row -> registers
    float4 wor[8];
#pragma unroll
    for (int i = 0; i < 8; i++) wor[i] = *(const float4*)(wout + e*32 + i*4);
#pragma unroll 1
    for (int p = 0; p < P; p++){
        const float* fr = fs + p*128 + g*32;
        float a = 0.f;
#pragma unroll
        for (int i = 0; i < 8; i++){
            float4 fv = *(const float4*)(fr + i*4);
            a = fmaf(wor[i].x, fv.x, a); a = fmaf(wor[i].y, fv.y, a);
            a = fmaf(wor[i].z, fv.z, a); a = fmaf(wor[i].w, fv.w, a);
        }
        out[(pix0 + p)*128 + e] = a;
    }
}

// ----------------------------------------------------------------
extern "C" void kernel_launch(void* const* d_in, const int* in_sizes, int n_in,
                              void* d_out, int out_size){
    const float* x        = (const float*)d_in[0];
    const float* w1       = (const float*)d_in[1];
    const float* dw       = (const float*)d_in[2];
    const float* in_proj  = (const float*)d_in[3];
    const float* conv1d_w = (const float*)d_in[4];
    const float* conv1d_b = (const float*)d_in[5];
    const float* x_proj_w = (const float*)d_in[6];
    const float* dt_proj_w= (const float*)d_in[7];
    const float* dt_proj_b= (const float*)d_in[8];
    const float* A_log    = (const float*)d_in[9];
    const float* D_param  = (const float*)d_in[10];
    const float* out_proj = (const float*)d_in[11];
    const float* gamma    = (const float*)d_in[12];
    const float* beta     = (const float*)d_in[13];
    const float* w2       = (const float*)d_in[14];
    const float* wout     = (const float*)d_in[15];
    float* out = (float*)d_out;

    float *t1, *xs, *u0, *z, *u, *dl, *Bm, *Cm, *yp;
    cudaGetSymbolAddress((void**)&t1, g_t1);
    cudaGetSymbolAddress((void**)&xs, g_xs);
    cudaGetSymbolAddress((void**)&u0, g_u0);
    cudaGetSymbolAddress((void**)&z,  g_z);
    cudaGetSymbolAddress((void**)&u,  g_u);
    cudaGetSymbolAddress((void**)&dl, g_dl);
    cudaGetSymbolAddress((void**)&Bm, g_Bm);
    cudaGetSymbolAddress((void**)&Cm, g_Cm);
    cudaGetSymbolAddress((void**)&yp, g_yp);

    int nelem = NPIX * DD;
    k_g1<<<nelem/256, 256>>>(x, w1, t1);
    k_dw<<<nelem/256, 256>>>(t1, dw, xs);
    k_inproj<<<NPIX/32, 256>>>(xs, in_proj, u0, z);
    k_conv1d<<<nelem/256, 256>>>(u0, conv1d_w, conv1d_b, u);
    k_xproj<<<NPIX/8, 128>>>(u, x_proj_w, dt_proj_w, dt_proj_b, dl, Bm, Cm);
    k_scan<<<128, 64>>>(dl, u, z, Bm, Cm, A_log, D_param, yp);
    k_final<<<NPIX/16, 128>>>(yp, out_proj, gamma, beta, x, w2, wout, out);
}

// round 2
// speedup vs baseline: 3.4665x; 3.4665x over previous
#include <cuda_runtime.h>
#include <math.h>

// Problem constants
#define BB 8
#define HH 64
#define WW 64
#define CC 128
#define DD 128
#define LL 4096            // H*W
#define NPIX (BB*LL)       // 32768
#define NS 8               // D_STATE
#define RR 8               // DT_RANK

#define CS 64              // chunk size (steps)
#define NC (LL/CS)         // 64 chunks per batch

// Scratch (device globals; no allocations allowed)
__device__ float g_t1[NPIX*DD];     // grouped1x1(x,w1)
__device__ float g_xs[NPIX*DD];     // after dwconv+silu (mamba input)
__device__ float g_u0[NPIX*DD];     // in_proj u (pre conv1d)
__device__ float g_z [NPIX*DD];     // in_proj z
__device__ float g_u [NPIX*DD];     // post conv1d + silu
__device__ float g_dl[NPIX*DD];     // delta
__device__ float g_Bm[NPIX*NS];
__device__ float g_Cm[NPIX*NS];
__device__ float g_yp[NPIX*DD];     // scan output * silu(z)
// chunked-scan state: [b][chunk][dn=1024]
__device__ float g_P [BB*NC*1024];
__device__ float g_hE[BB*NC*1024];
__device__ float g_h0[BB*NC*1024];

__device__ __forceinline__ float siluf(float v){ return v / (1.f + __expf(-v)); }

// ---------------------------------------------------------------- K1: grouped 1x1
__global__ void k_g1(const float* __restrict__ x, const float* __restrict__ w,
                     float* __restrict__ out){
    __shared__ float ws[4096];
    for (int i = threadIdx.x; i < 4096; i += 256) ws[i] = w[i];
    __syncthreads();
    int idx = blockIdx.x * 256 + threadIdx.x;
    int c = idx & 127; int pix = idx >> 7;
    int g = c >> 5, o = c & 31;
    const float* xr = x + pix*128 + g*32;
    const float* wr = ws + (g*32 + o)*32;
    float acc = 0.f;
#pragma unroll
    for (int i = 0; i < 32; i += 4){
        float4 wv = *(const float4*)(wr + i);
        float4 xv = *(const float4*)(xr + i);
        acc = fmaf(wv.x, xv.x, acc); acc = fmaf(wv.y, xv.y, acc);
        acc = fmaf(wv.z, xv.z, acc); acc = fmaf(wv.w, xv.w, acc);
    }
    out[idx] = acc;
}

// ---------------------------------------------------------------- K2: depthwise 3x3 + silu
__global__ void k_dw(const float* __restrict__ t1, const float* __restrict__ dw,
                     float* __restrict__ out){
    int idx = blockIdx.x * 256 + threadIdx.x;
    int d = idx & 127;
    int pix = idx >> 7;
    int wc = pix & 63; int h = (pix >> 6) & 63; int b = pix >> 12;
    float acc = 0.f;
#pragma unroll
    for (int kh = 0; kh < 3; kh++){
        int hh = h + kh - 1; if (hh < 0 || hh >= 64) continue;
#pragma unroll
        for (int kw = 0; kw < 3; kw++){
            int ww = wc + kw - 1; if (ww < 0 || ww >= 64) continue;
            acc = fmaf(t1[(((b*64 + hh)*64 + ww) << 7) + d],
                       dw[(kh*3 + kw)*128 + d], acc);
        }
    }
    out[idx] = siluf(acc);
}

// ---------------------------------------------------------------- K3: in_proj (128 -> 256), split u/z
__global__ void k_inproj(const float* __restrict__ xs, const float* __restrict__ w,
                         float* __restrict__ ub, float* __restrict__ zb){
    __shared__ float xt[32*128];
    int pix0 = blockIdx.x * 32;
    for (int i = threadIdx.x; i < 32*128; i += 256) xt[i] = xs[pix0*128 + i];
    __syncthreads();
    int e = threadIdx.x;
    float acc[32];
#pragma unroll
    for (int p = 0; p < 32; p++) acc[p] = 0.f;
    const float* wr = w + e*128;
    for (int d = 0; d < 128; d += 4){
        float4 wv = *(const float4*)(wr + d);
#pragma unroll
        for (int p = 0; p < 32; p++){
            float4 xv = *(const float4*)(xt + p*128 + d);
            acc[p] = fmaf(wv.x, xv.x, acc[p]); acc[p] = fmaf(wv.y, xv.y, acc[p]);
            acc[p] = fmaf(wv.z, xv.z, acc[p]); acc[p] = fmaf(wv.w, xv.w, acc[p]);
        }
    }
    float* outb = (e < 128) ? (ub + e) : (zb + (e - 128));
#pragma unroll
    for (int p = 0; p < 32; p++) outb[(pix0 + p)*128] = acc[p];
}

// ---------------------------------------------------------------- K4: causal conv1d(k=3) + silu
__global__ void k_conv1d(const float* __restrict__ u0, const float* __restrict__ cw,
                         const float* __restrict__ cb, float* __restrict__ uo){
    int idx = blockIdx.x * 256 + threadIdx.x;
    int d = idx & 127;
    int pix = idx >> 7;
    int l = pix & (LL - 1);
    float w0 = cw[d*3], w1 = cw[d*3 + 1], w2 = cw[d*3 + 2];
    float acc = fmaf(w2, u0[idx], cb[d]);
    if (l >= 1) acc = fmaf(w1, u0[idx - 128], acc);
    if (l >= 2) acc = fmaf(w0, u0[idx - 256], acc);
    uo[idx] = siluf(acc);
}

// ---------------------------------------------------------------- K5: x_proj + dt_proj + softplus
__global__ void k_xproj(const float* __restrict__ u, const float* __restrict__ xpw,
                        const float* __restrict__ dtw, const float* __restrict__ dtb,
                        float* __restrict__ dl, float* __restrict__ Bb, float* __restrict__ Cb){
    __shared__ float ut[8*128];
    __shared__ float xd[8*24];
    __shared__ float wx[24*128];
    __shared__ float wd[128*8];
    int pix0 = blockIdx.x * 8;
    int t = threadIdx.x;
    for (int i = t; i < 8*128; i += 128) ut[i] = u[pix0*128 + i];
    for (int i = t; i < 24*128; i += 128) wx[i] = xpw[i];
    for (int i = t; i < 128*8; i += 128) wd[i] = dtw[i];
    __syncthreads();
    for (int o = t; o < 192; o += 128){
        int p = o / 24, j = o % 24;
        const float* wr = wx + j*128;
        const float* ur = ut + p*128;
        float acc = 0.f;
#pragma unroll
        for (int d = 0; d < 128; d += 4){
            float4 wv = *(const float4*)(wr + d);
            float4 uv = *(const float4*)(ur + d);
            acc = fmaf(wv.x, uv.x, acc); acc = fmaf(wv.y, uv.y, acc);
            acc = fmaf(wv.z, uv.z, acc); acc = fmaf(wv.w, uv.w, acc);
        }
        xd[p*24 + j] = acc;
    }
    __syncthreads();
    int d = t;
    float bias = dtb[d];
#pragma unroll
    for (int p = 0; p < 8; p++){
        float acc = bias;
#pragma unroll
        for (int r = 0; r < 8; r++) acc = fmaf(xd[p*24 + r], wd[d*8 + r], acc);
        float sp = (acc > 20.f) ? acc : log1pf(__expf(acc));
        dl[(pix0 + p)*128 + d] = sp;
    }
    if (t < 64){
        int p = t >> 3, n = t & 7;
        Bb[(pix0 + p)*8 + n] = xd[p*24 + 8 + n];
        Cb[(pix0 + p)*8 + n] = xd[p*24 + 16 + n];
    }
}

// ---------------------------------------------------------------- K6a: chunked scan, phase A
// grid = BB*NC blocks of 1024 threads (128 d x 8 n). Each block: one (b, chunk).
// Computes per-lane local decay product P and local end state hE (h0 = 0).
__global__ void k_scanA(const float* __restrict__ dl, const float* __restrict__ u,
                        const float* __restrict__ Bb, const float* __restrict__ A_log,
                        float* __restrict__ Pg, float* __restrict__ hEg){
    extern __shared__ float sm[];
    float* sdl = sm;            // CS*128
    float* su  = sm + CS*128;   // CS*128
    float* sB  = sm + 2*CS*128; // CS*8
    int b = blockIdx.x >> 6;
    int c = blockIdx.x & (NC - 1);
    int t = threadIdx.x;
    int base = (b*LL + c*CS)*128;
    for (int i = t; i < CS*128; i += 1024){
        sdl[i] = dl[base + i];
        su[i]  = u[base + i];
    }
    int nb = (b*LL + c*CS)*8;
    if (t < CS*8) sB[t] = Bb[nb + t];
    __syncthreads();
    int d = t >> 3, n = t & 7;
    float Av = -__expf(A_log[d*8 + n]);
    float h = 0.f, P = 1.f;
#pragma unroll 8
    for (int l = 0; l < CS; l++){
        float de = sdl[l*128 + d];
        float uu = su[l*128 + d];
        float dA = __expf(de * Av);
        P *= dA;
        h = fmaf(dA, h, de * uu * sB[l*8 + n]);
    }
    int oidx = (b*NC + c)*1024 + t;
    Pg[oidx] = P;
    hEg[oidx] = h;
}

// ---------------------------------------------------------------- K6b: chunk combine (sequential over NC)
// 8192 threads, one per (b, d, n) lane; h0[c] = exclusive scan of (P, hE).
__global__ void k_scanB(const float* __restrict__ Pg, const float* __restrict__ hEg,
                        float* __restrict__ h0g){
    int j = blockIdx.x * 1024 + threadIdx.x;
    int b = j >> 10, dn = j & 1023;
    float h = 0.f;
#pragma unroll 8
    for (int c = 0; c < NC; c++){
        int idx = (b*NC + c)*1024 + dn;
        h0g[idx] = h;
        h = fmaf(Pg[idx], h, hEg[idx]);
    }
}

// ---------------------------------------------------------------- K6c: chunked scan, phase C
// Recompute local scan from h0, reduce y over n, fuse +u*D and *silu(z), write yp.
__global__ void k_scanC(const float* __restrict__ dl, const float* __restrict__ u,
                        const float* __restrict__ z, const float* __restrict__ Bb,
                        const float* __restrict__ Cb, const float* __restrict__ A_log,
                        const float* __restrict__ Dp, const float* __restrict__ h0g,
                        float* __restrict__ yp){
    extern __shared__ float sm[];
    float* sdl = sm;              // CS*128
    float* su  = sm + CS*128;     // CS*128
    float* sy  = sm + 2*CS*128;   // CS*128
    float* sB  = sm + 3*CS*128;   // CS*8
    float* sC  = sm + 3*CS*128 + CS*8; // CS*8
    int b = blockIdx.x >> 6;
    int c = blockIdx.x & (NC - 1);
    int t = threadIdx.x;
    int base = (b*LL + c*CS)*128;
    for (int i = t; i < CS*128; i += 1024){
        sdl[i] = dl[base + i];
        su[i]  = u[base + i];
    }
    int nb = (b*LL + c*CS)*8;
    if (t < CS*8){
        sB[t] = Bb[nb + t];
        sC[t] = Cb[nb + t];
    }
    __syncthreads();
    int d = t >> 3, n = t & 7;
    float Av = -__expf(A_log[d*8 + n]);
    float h = h0g[(b*NC + c)*1024 + t];
#pragma unroll 4
    for (int l = 0; l < CS; l++){
        float de = sdl[l*128 + d];
        float uu = su[l*128 + d];
        float dA = __expf(de * Av);
        h = fmaf(dA, h, de * uu * sB[l*8 + n]);
        float y = h * sC[l*8 + n];
        y += __shfl_xor_sync(0xffffffffu, y, 1);
        y += __shfl_xor_sync(0xffffffffu, y, 2);
        y += __shfl_xor_sync(0xffffffffu, y, 4);
        if (n == 0) sy[l*128 + d] = y;
    }
    __syncthreads();
    for (int i = t; i < CS*128; i += 1024){
        int dd = i & 127;
        float val = fmaf(su[i], Dp[dd], sy[i]);
        float zz = z[base + i];
        yp[base + i] = val * siluf(zz);
    }
}

// ---------------------------------------------------------------- K7: out_proj + LayerNorm + gate + out g1x1
__global__ void k_final(const float* __restrict__ yp, const float* __restrict__ opw,
                        const float* __restrict__ gamma, const float* __restrict__ beta,
                        const float* __restrict__ x, const float* __restrict__ w2,
                        const float* __restrict__ wout, float* __restrict__ out){
    const int P = 16;
    __shared__ float yt[P*128];
    __shared__ float mt[P*132];
    __shared__ float xt[P*128];
    __shared__ float fs[P*128];
    __shared__ float mus[P], rss[P];
    int pix0 = blockIdx.x * P;
    int t = threadIdx.x;
    for (int i = t; i < P*128; i += 128){
        yt[i] = yp[pix0*128 + i];
        xt[i] = x[pix0*128 + i];
    }
    __syncthreads();
    int e = t;
    float acc[P];
#pragma unroll
    for (int p = 0; p < P; p++) acc[p] = 0.f;
    const float* wr = opw + e*128;
    for (int dd = 0; dd < 128; dd += 4){
        float4 wv = *(const float4*)(wr + dd);
#pragma unroll
        for (int p = 0; p < P; p++){
            float4 yv = *(const float4*)(yt + p*128 + dd);
            acc[p] = fmaf(wv.x, yv.x, acc[p]); acc[p] = fmaf(wv.y, yv.y, acc[p]);
            acc[p] = fmaf(wv.z, yv.z, acc[p]); acc[p] = fmaf(wv.w, yv.w, acc[p]);
        }
    }
#pragma unroll
    for (int p = 0; p < P; p++) mt[p*132 + e] = acc[p];
    __syncthreads();
    if (t < P){
        float s = 0.f;
        for (int i = 0; i < 128; i++) s += mt[t*132 + i];
        float mu = s * (1.f/128.f);
        float v = 0.f;
        for (int i = 0; i < 128; i++){ float dv = mt[t*132 + i] - mu; v = fmaf(dv, dv, v); }
        mus[t] = mu;
        rss[t] = rsqrtf(v * (1.f/128.f) + 1e-5f);
    }
    __syncthreads();
    float ga = gamma[e], be = beta[e];
    int g = e >> 5;
    float4 w2r[8];
#pragma unroll
    for (int i = 0; i < 8; i++) w2r[i] = *(const float4*)(w2 + e*32 + i*4);
#pragma unroll 1
    for (int p = 0; p < P; p++){
        float x1n = fmaf((mt[p*132 + e] - mus[p]) * rss[p], ga, be);
        const float* xr = xt + p*128 + g*32;
        float a2 = 0.f;
#pragma unroll
        for (int i = 0; i < 8; i++){
            float4 xv = *(const float4*)(xr + i*4);
            a2 = fmaf(w2r[i].x, xv.x, a2); a2 = fmaf(w2r[i].y, xv.y, a2);
            a2 = fmaf(w2r[i].z, xv.z, a2); a2 = fmaf(w2r[i].w, xv.w, a2);
        }
        fs[p*128 + e] = x1n * siluf(a2);
    }
    __syncthreads();
    float4 wor[8];
#pragma unroll
    for (int i = 0; i < 8; i++) wor[i] = *(const float4*)(wout + e*32 + i*4);
#pragma unroll 1
    for (int p = 0; p < P; p++){
        const float* fr = fs + p*128 + g*32;
        float a = 0.f;
#pragma unroll
        for (int i = 0; i < 8; i++){
            float4 fv = *(const float4*)(fr + i*4);
            a = fmaf(wor[i].x, fv.x, a); a = fmaf(wor[i].y, fv.y, a);
            a = fmaf(wor[i].z, fv.z, a); a = fmaf(wor[i].w, fv.w, a);
        }
        out[(pix0 + p)*128 + e] = a;
    }
}

// ----------------------------------------------------------------
extern "C" void kernel_launch(void* const* d_in, const int* in_sizes, int n_in,
                              void* d_out, int out_size){
    const float* x        = (const float*)d_in[0];
    const float* w1       = (const float*)d_in[1];
    const float* dw       = (const float*)d_in[2];
    const float* in_proj  = (const float*)d_in[3];
    const float* conv1d_w = (const float*)d_in[4];
    const float* conv1d_b = (const float*)d_in[5];
    const float* x_proj_w = (const float*)d_in[6];
    const float* dt_proj_w= (const float*)d_in[7];
    const float* dt_proj_b= (const float*)d_in[8];
    const float* A_log    = (const float*)d_in[9];
    const float* D_param  = (const float*)d_in[10];
    const float* out_proj = (const float*)d_in[11];
    const float* gamma    = (const float*)d_in[12];
    const float* beta     = (const float*)d_in[13];
    const float* w2       = (const float*)d_in[14];
    const float* wout     = (const float*)d_in[15];
    float* out = (float*)d_out;

    float *t1, *xs, *u0, *z, *u, *dl, *Bm, *Cm, *yp, *Pg, *hE, *h0;
    cudaGetSymbolAddress((void**)&t1, g_t1);
    cudaGetSymbolAddress((void**)&xs, g_xs);
    cudaGetSymbolAddress((void**)&u0, g_u0);
    cudaGetSymbolAddress((void**)&z,  g_z);
    cudaGetSymbolAddress((void**)&u,  g_u);
    cudaGetSymbolAddress((void**)&dl, g_dl);
    cudaGetSymbolAddress((void**)&Bm, g_Bm);
    cudaGetSymbolAddress((void**)&Cm, g_Cm);
    cudaGetSymbolAddress((void**)&yp, g_yp);
    cudaGetSymbolAddress((void**)&Pg, g_P);
    cudaGetSymbolAddress((void**)&hE, g_hE);
    cudaGetSymbolAddress((void**)&h0, g_h0);

    // dynamic smem sizes (>48KB needs opt-in; idempotent, not a stream op)
    const int smemA = (2*CS*128 + CS*8) * sizeof(float);            // 66.5 KB
    const int smemC = (3*CS*128 + 2*CS*8) * sizeof(float);          // 100.5 KB
    static int attr_done = 0;
    if (!attr_done){
        cudaFuncSetAttribute(k_scanA, cudaFuncAttributeMaxDynamicSharedMemorySize, smemA);
        cudaFuncSetAttribute(k_scanC, cudaFuncAttributeMaxDynamicSharedMemorySize, smemC);
        attr_done = 1;
    }

    int nelem = NPIX * DD;
    k_g1<<<nelem/256, 256>>>(x, w1, t1);
    k_dw<<<nelem/256, 256>>>(t1, dw, xs);
    k_inproj<<<NPIX/32, 256>>>(xs, in_proj, u0, z);
    k_conv1d<<<nelem/256, 256>>>(u0, conv1d_w, conv1d_b, u);
    k_xproj<<<NPIX/8, 128>>>(u, x_proj_w, dt_proj_w, dt_proj_b, dl, Bm, Cm);
    k_scanA<<<BB*NC, 1024, smemA>>>(dl, u, Bm, A_log, Pg, hE);
    k_scanB<<<8, 1024>>>(Pg, hE, h0);
    k_scanC<<<BB*NC, 1024, smemC>>>(dl, u, z, Bm, Cm, A_log, D_param, h0, yp);
    k_final<<<NPIX/16, 128>>>(yp, out_proj, gamma, beta, x, w2, wout, out);
}

// round 3
// speedup vs baseline: 3.5873x; 1.0349x over previous
#include <cuda_runtime.h>
#include <math.h>
#include <stdint.h>

// Problem constants
#define BB 8
#define HH 64
#define WW 64
#define CC 128
#define DD 128
#define LL 4096            // H*W
#define NPIX (BB*LL)       // 32768
#define NS 8               // D_STATE
#define RR 8               // DT_RANK

#define CS 64              // chunk size (steps)
#define NC (LL/CS)         // 64 chunks per batch

// Scratch (device globals; no allocations allowed)
__device__ float g_t1[NPIX*DD];
__device__ float g_xs[NPIX*DD];
__device__ float g_u0[NPIX*DD];
__device__ float g_z [NPIX*DD];
__device__ float g_u [NPIX*DD];
__device__ float g_dl[NPIX*DD];
__device__ float g_Bm[NPIX*NS];
__device__ float g_Cm[NPIX*NS];
__device__ float g_yp[NPIX*DD];
__device__ float g_P [BB*NC*1024];
__device__ float g_hE[BB*NC*1024];
__device__ float g_h0[BB*NC*1024];

__device__ __forceinline__ float siluf(float v){ return v / (1.f + __expf(-v)); }

__device__ __forceinline__ uint32_t f2tf(float x){
    uint32_t r; asm("cvt.rna.tf32.f32 %0, %1;" : "=r"(r) : "f"(x)); return r;
}
__device__ __forceinline__ void mma8(float4& c, uint32_t a0, uint32_t a1, uint32_t a2, uint32_t a3,
                                     uint32_t b0, uint32_t b1){
    asm volatile("mma.sync.aligned.m16n8k8.row.col.f32.tf32.tf32.f32 "
                 "{%0,%1,%2,%3},{%4,%5,%6,%7},{%8,%9},{%0,%1,%2,%3};\n"
                 : "+f"(c.x), "+f"(c.y), "+f"(c.z), "+f"(c.w)
                 : "r"(a0), "r"(a1), "r"(a2), "r"(a3), "r"(b0), "r"(b1));
}

// ---------------------------------------------------------------- K1: grouped 1x1 (x @ w1)
__global__ void k_g1(const float* __restrict__ x, const float* __restrict__ w,
                     float* __restrict__ out){
    __shared__ float ws[4096];
    for (int i = threadIdx.x; i < 4096; i += 256) ws[i] = w[i];
    __syncthreads();
    int idx = blockIdx.x * 256 + threadIdx.x;
    int c = idx & 127; int pix = idx >> 7;
    int g = c >> 5, o = c & 31;
    const float* xr = x + pix*128 + g*32;
    const float* wr = ws + (g*32 + o)*32;
    float acc = 0.f;
#pragma unroll
    for (int i = 0; i < 32; i += 4){
        float4 wv = *(const float4*)(wr + i);
        float4 xv = *(const float4*)(xr + i);
        acc = fmaf(wv.x, xv.x, acc); acc = fmaf(wv.y, xv.y, acc);
        acc = fmaf(wv.z, xv.z, acc); acc = fmaf(wv.w, xv.w, acc);
    }
    out[idx] = acc;
}

// ---------------------------------------------------------------- K2: depthwise 3x3 + silu (float4/thread)
__global__ void k_dw(const float* __restrict__ t1, const float* __restrict__ dw,
                     float* __restrict__ out){
    int idx = blockIdx.x * 256 + threadIdx.x;     // NPIX*32 total
    int d4 = idx & 31; int pix = idx >> 5;
    int wc = pix & 63; int h = (pix >> 6) & 63; int b = pix >> 12;
    int d = d4 << 2;
    float4 acc = make_float4(0.f, 0.f, 0.f, 0.f);
#pragma unroll
    for (int kh = 0; kh < 3; kh++){
        int hh = h + kh - 1; if (hh < 0 || hh >= 64) continue;
#pragma unroll
        for (int kw = 0; kw < 3; kw++){
            int ww = wc + kw - 1; if (ww < 0 || ww >= 64) continue;
            float4 tv = *(const float4*)(t1 + (((b*64 + hh)*64 + ww) << 7) + d);
            float4 wv = *(const float4*)(dw + (kh*3 + kw)*128 + d);
            acc.x = fmaf(tv.x, wv.x, acc.x); acc.y = fmaf(tv.y, wv.y, acc.y);
            acc.z = fmaf(tv.z, wv.z, acc.z); acc.w = fmaf(tv.w, wv.w, acc.w);
        }
    }
    float4 r; r.x = siluf(acc.x); r.y = siluf(acc.y); r.z = siluf(acc.z); r.w = siluf(acc.w);
    *(float4*)(out + (size_t)pix*128 + d) = r;
}

// ---------------------------------------------------------------- K3: in_proj via tf32 mma (split weights)
// block = 256 thr (8 warps), 128 pixels. smem: xt[128][132] (tf32), ws[256][132] (fp32)
__global__ void __launch_bounds__(256, 1) k_inproj(const float* __restrict__ xs,
                                                   const float* __restrict__ w,
                                                   float* __restrict__ ub, float* __restrict__ zb){
    extern __shared__ float sm[];
    float* xt = sm;            // 128*132
    float* ws = sm + 128*132;  // 256*132
    int tid = threadIdx.x;
    int pix0 = blockIdx.x * 128;
    {
        const float4* xs4 = (const float4*)(xs + (size_t)pix0*128);
        for (int i = tid; i < 128*32; i += 256){
            int p = i >> 5, q = i & 31;
            float4 v = xs4[i];
            v.x = __uint_as_float(f2tf(v.x)); v.y = __uint_as_float(f2tf(v.y));
            v.z = __uint_as_float(f2tf(v.z)); v.w = __uint_as_float(f2tf(v.w));
            *(float4*)(xt + p*132 + q*4) = v;
        }
        const float4* w4 = (const float4*)w;
        for (int i = tid; i < 256*32; i += 256){
            int e = i >> 5, q = i & 31;
            *(float4*)(ws + e*132 + q*4) = w4[i];
        }
    }
    __syncthreads();
    int warp = tid >> 5, lane = tid & 31;
    int row_ = lane >> 2, col_ = lane & 3;
    int p0 = warp * 16;
    const float* xrA = xt + (p0 + row_)*132 + col_;
    const float* xrB = xt + (p0 + row_ + 8)*132 + col_;
#pragma unroll 1
    for (int g = 0; g < 4; g++){
        float4 acc[8];
#pragma unroll
        for (int t = 0; t < 8; t++) acc[t] = make_float4(0.f,0.f,0.f,0.f);
#pragma unroll 4
        for (int k = 0; k < 16; k++){
            int k8 = k*8;
            uint32_t a0 = __float_as_uint(xrA[k8]);
            uint32_t a1 = __float_as_uint(xrB[k8]);
            uint32_t a2 = __float_as_uint(xrA[k8 + 4]);
            uint32_t a3 = __float_as_uint(xrB[k8 + 4]);
#pragma unroll
            for (int t = 0; t < 8; t++){
                int e0 = g*64 + t*8;
                float b0r = ws[(e0 + row_)*132 + k8 + col_];
                float b1r = ws[(e0 + row_)*132 + k8 + col_ + 4];
                uint32_t bh0 = f2tf(b0r);
                uint32_t bl0 = f2tf(b0r - __uint_as_float(bh0));
                uint32_t bh1 = f2tf(b1r);
                uint32_t bl1 = f2tf(b1r - __uint_as_float(bh1));
                mma8(acc[t], a0, a1, a2, a3, bh0, bh1);
                mma8(acc[t], a0, a1, a2, a3, bl0, bl1);
            }
        }
        int pixA = pix0 + p0 + row_;
        int pixB = pixA + 8;
#pragma unroll
        for (int t = 0; t < 8; t++){
            int e0 = g*64 + t*8 + 2*col_;
            float* base = (g < 2) ? (ub + e0) : (zb + e0 - 128);
            *(float2*)(base + (size_t)pixA*128) = make_float2(acc[t].x, acc[t].y);
            *(float2*)(base + (size_t)pixB*128) = make_float2(acc[t].z, acc[t].w);
        }
    }
}

// ---------------------------------------------------------------- K4: causal conv1d(k=3) + silu (float4/thread)
__global__ void k_conv1d(const float* __restrict__ u0, const float* __restrict__ cw,
                         const float* __restrict__ cb, float* __restrict__ uo){
    int idx = blockIdx.x * 256 + threadIdx.x;   // NPIX*32 total
    int d4 = idx & 31; int pix = idx >> 5;
    int l = pix & (LL - 1);
    int d = d4 << 2;
    const float4* cwv = (const float4*)(cw + d*3);
    float4 Aq = cwv[0], Bq = cwv[1], Cq = cwv[2];
    float4 b4 = *(const float4*)(cb + d);
    const float* up = u0 + (size_t)pix*128 + d;
    float4 x0 = *(const float4*)up;
    float4 x1 = make_float4(0,0,0,0), x2 = make_float4(0,0,0,0);
    if (l >= 1) x1 = *(const float4*)(up - 128);
    if (l >= 2) x2 = *(const float4*)(up - 256);
    float4 r;
    r.x = fmaf(Aq.x, x2.x, fmaf(Aq.y, x1.x, fmaf(Aq.z, x0.x, b4.x)));
    r.y = fmaf(Aq.w, x2.y, fmaf(Bq.x, x1.y, fmaf(Bq.y, x0.y, b4.y)));
    r.z = fmaf(Bq.z, x2.z, fmaf(Bq.w, x1.z, fmaf(Cq.x, x0.z, b4.z)));
    r.w = fmaf(Cq.y, x2.w, fmaf(Cq.z, x1.w, fmaf(Cq.w, x0.w, b4.w)));
    r.x = siluf(r.x); r.y = siluf(r.y); r.z = siluf(r.z); r.w = siluf(r.w);
    *(float4*)(uo + (size_t)pix*128 + d) = r;
}

// ---------------------------------------------------------------- K5: x_proj + dt_proj + softplus
__global__ void k_xproj(const float* __restrict__ u, const float* __restrict__ xpw,
                        const float* __restrict__ dtw, const float* __restrict__ dtb,
                        float* __restrict__ dl, float* __restrict__ Bb, float* __restrict__ Cb){
    __shared__ float ut[8*128];
    __shared__ float xd[8*24];
    __shared__ float wx[24*128];
    __shared__ float wd[128*8];
    int pix0 = blockIdx.x * 8;
    int t = threadIdx.x;
    for (int i = t; i < 8*128; i += 128) ut[i] = u[(size_t)pix0*128 + i];
    for (int i = t; i < 24*128; i += 128) wx[i] = xpw[i];
    for (int i = t; i < 128*8; i += 128) wd[i] = dtw[i];
    __syncthreads();
    for (int o = t; o < 192; o += 128){
        int p = o / 24, j = o % 24;
        const float* wr = wx + j*128;
        const float* ur = ut + p*128;
        float acc = 0.f;
#pragma unroll
        for (int d = 0; d < 128; d += 4){
            float4 wv = *(const float4*)(wr + d);
            float4 uv = *(const float4*)(ur + d);
            acc = fmaf(wv.x, uv.x, acc); acc = fmaf(wv.y, uv.y, acc);
            acc = fmaf(wv.z, uv.z, acc); acc = fmaf(wv.w, uv.w, acc);
        }
        xd[p*24 + j] = acc;
    }
    __syncthreads();
    int d = t;
    float bias = dtb[d];
#pragma unroll
    for (int p = 0; p < 8; p++){
        float acc = bias;
#pragma unroll
        for (int r = 0; r < 8; r++) acc = fmaf(xd[p*24 + r], wd[d*8 + r], acc);
        float sp = (acc > 20.f) ? acc : log1pf(__expf(acc));
        dl[(size_t)(pix0 + p)*128 + d] = sp;
    }
    if (t < 64){
        int p = t >> 3, n = t & 7;
        Bb[(pix0 + p)*8 + n] = xd[p*24 + 8 + n];
        Cb[(pix0 + p)*8 + n] = xd[p*24 + 16 + n];
    }
}

// ---------------------------------------------------------------- K6a: chunked scan, phase A
__global__ void k_scanA(const float* __restrict__ dl, const float* __restrict__ u,
                        const float* __restrict__ Bb, const float* __restrict__ A_log,
                        float* __restrict__ Pg, float* __restrict__ hEg){
    extern __shared__ float sm[];
    float* sdl = sm;            // CS*128
    float* su  = sm + CS*128;   // CS*128
    float* sB  = sm + 2*CS*128; // CS*8
    int b = blockIdx.x >> 6;
    int c = blockIdx.x & (NC - 1);
    int t = threadIdx.x;
    size_t base = ((size_t)b*LL + c*CS)*128;
    {
        const float4* dl4 = (const float4*)(dl + base);
        const float4* u4  = (const float4*)(u + base);
        for (int i = t; i < CS*32; i += 1024){
            ((float4*)sdl)[i] = dl4[i];
            ((float4*)su)[i]  = u4[i];
        }
    }
    int nb = (b*LL + c*CS)*8;
    if (t < CS*8) sB[t] = Bb[nb + t];
    __syncthreads();
    int d = t >> 3, n = t & 7;
    float Av = -__expf(A_log[d*8 + n]);
    float h = 0.f, P = 1.f;
#pragma unroll 8
    for (int l = 0; l < CS; l++){
        float de = sdl[l*128 + d];
        float uu = su[l*128 + d];
        float dA = __expf(de * Av);
        P *= dA;
        h = fmaf(dA, h, de * uu * sB[l*8 + n]);
    }
    int oidx = (b*NC + c)*1024 + t;
    Pg[oidx] = P;
    hEg[oidx] = h;
}

// ---------------------------------------------------------------- K6b: chunk combine
__global__ void k_scanB(const float* __restrict__ Pg, const float* __restrict__ hEg,
                        float* __restrict__ h0g){
    int j = blockIdx.x * 1024 + threadIdx.x;
    int b = j >> 10, dn = j & 1023;
    float h = 0.f;
#pragma unroll 8
    for (int c = 0; c < NC; c++){
        int idx = (b*NC + c)*1024 + dn;
        h0g[idx] = h;
        h = fmaf(Pg[idx], h, hEg[idx]);
    }
}

// ---------------------------------------------------------------- K6c: chunked scan, phase C
__global__ void k_scanC(const float* __restrict__ dl, const float* __restrict__ u,
                        const float* __restrict__ z, const float* __restrict__ Bb,
                        const float* __restrict__ Cb, const float* __restrict__ A_log,
                        const float* __restrict__ Dp, const float* __restrict__ h0g,
                        float* __restrict__ yp){
    extern __shared__ float sm[];
    float* sdl = sm;              // CS*128
    float* su  = sm + CS*128;     // CS*128
    float* sy  = sm + 2*CS*128;   // CS*128
    float* sB  = sm + 3*CS*128;   // CS*8
    float* sC  = sm + 3*CS*128 + CS*8; // CS*8
    int b = blockIdx.x >> 6;
    int c = blockIdx.x & (NC - 1);
    int t = threadIdx.x;
    size_t base = ((size_t)b*LL + c*CS)*128;
    {
        const float4* dl4 = (const float4*)(dl + base);
        const float4* u4  = (const float4*)(u + base);
        for (int i = t; i < CS*32; i += 1024){
            ((float4*)sdl)[i] = dl4[i];
            ((float4*)su)[i]  = u4[i];
        }
    }
    int nb = (b*LL + c*CS)*8;
    if (t < CS*8){
        sB[t] = Bb[nb + t];
        sC[t] = Cb[nb + t];
    }
    __syncthreads();
    int d = t >> 3, n = t & 7;
    float Av = -__expf(A_log[d*8 + n]);
    float h = h0g[(b*NC + c)*1024 + t];
#pragma unroll 4
    for (int l = 0; l < CS; l++){
        float de = sdl[l*128 + d];
        float uu = su[l*128 + d];
        float dA = __expf(de * Av);
        h = fmaf(dA, h, de * uu * sB[l*8 + n]);
        float y = h * sC[l*8 + n];
        y += __shfl_xor_sync(0xffffffffu, y, 1);
        y += __shfl_xor_sync(0xffffffffu, y, 2);
        y += __shfl_xor_sync(0xffffffffu, y, 4);
        if (n == 0) sy[l*128 + d] = y;
    }
    __syncthreads();
    {
        const float4* z4 = (const float4*)(z + base);
        float4* yp4 = (float4*)(yp + base);
        for (int i = t; i < CS*32; i += 1024){
            float4 sv = ((float4*)sy)[i];
            float4 uv = ((float4*)su)[i];
            float4 zv = z4[i];
            float4 Dv = *(const float4*)(Dp + ((i & 31) << 2));
            float4 r;
            r.x = fmaf(uv.x, Dv.x, sv.x) * siluf(zv.x);
            r.y = fmaf(uv.y, Dv.y, sv.y) * siluf(zv.y);
            r.z = fmaf(uv.z, Dv.z, sv.z) * siluf(zv.z);
            r.w = fmaf(uv.w, Dv.w, sv.w) * siluf(zv.w);
            yp4[i] = r;
        }
    }
}

// ---------------------------------------------------------------- K7: out_proj (tf32 mma) + LN + gating + out g1x1
// block = 128 thr (4 warps), 64 pixels.
__global__ void __launch_bounds__(128, 1) k_final(const float* __restrict__ yp,
                        const float* __restrict__ opw,
                        const float* __restrict__ gamma, const float* __restrict__ beta,
                        const float* __restrict__ x, const float* __restrict__ w2,
                        const float* __restrict__ wout, float* __restrict__ out){
    extern __shared__ float sm[];
    float* yt   = sm;                   // 64*132 (tf32 A); later reused as fs (64*128)
    float* wsop = sm + 64*132;          // 128*132 (fp32 weights)
    float* mt   = wsop + 128*132;       // 64*132
    float* xt   = mt + 64*132;          // 64*128
    float* mus  = xt + 64*128;          // 64
    float* rss  = mus + 64;             // 64
    float* fs   = yt;                   // alias (yt dead after GEMM)
    int tid = threadIdx.x;
    int pix0 = blockIdx.x * 64;
    {
        const float4* y4 = (const float4*)(yp + (size_t)pix0*128);
        const float4* x4 = (const float4*)(x + (size_t)pix0*128);
        for (int i = tid; i < 64*32; i += 128){
            int p = i >> 5, q = i & 31;
            float4 v = y4[i];
            v.x = __uint_as_float(f2tf(v.x)); v.y = __uint_as_float(f2tf(v.y));
            v.z = __uint_as_float(f2tf(v.z)); v.w = __uint_as_float(f2tf(v.w));
            *(float4*)(yt + p*132 + q*4) = v;
            *(float4*)(xt + p*128 + q*4) = x4[i];
        }
        const float4* w4 = (const float4*)opw;
        for (int i = tid; i < 128*32; i += 128){
            int e = i >> 5, q = i & 31;
            *(float4*)(wsop + e*132 + q*4) = w4[i];
        }
    }
    __syncthreads();
    int warp = tid >> 5, lane = tid & 31;
    int row_ = lane >> 2, col_ = lane & 3;
    {
        int p0 = warp * 16;
        const float* yrA = yt + (p0 + row_)*132 + col_;
        const float* yrB = yt + (p0 + row_ + 8)*132 + col_;
        float4 acc[16];
#pragma unroll
        for (int t = 0; t < 16; t++) acc[t] = make_float4(0.f,0.f,0.f,0.f);
#pragma unroll 2
        for (int k = 0; k < 16; k++){
            int k8 = k*8;
            uint32_t a0 = __float_as_uint(yrA[k8]);
            uint32_t a1 = __float_as_uint(yrB[k8]);
            uint32_t a2 = __float_as_uint(yrA[k8 + 4]);
            uint32_t a3 = __float_as_uint(yrB[k8 + 4]);
#pragma unroll
            for (int t = 0; t < 16; t++){
                int e0 = t*8;
                float b0r = wsop[(e0 + row_)*132 + k8 + col_];
                float b1r = wsop[(e0 + row_)*132 + k8 + col_ + 4];
                uint32_t bh0 = f2tf(b0r);
                uint32_t bl0 = f2tf(b0r - __uint_as_float(bh0));
                uint32_t bh1 = f2tf(b1r);
                uint32_t bl1 = f2tf(b1r - __uint_as_float(bh1));
                mma8(acc[t], a0, a1, a2, a3, bh0, bh1);
                mma8(acc[t], a0, a1, a2, a3, bl0, bl1);
            }
        }
        int pA = p0 + row_, pB = p0 + row_ + 8;
#pragma unroll
        for (int t = 0; t < 16; t++){
            int e = t*8 + 2*col_;
            *(float2*)(mt + pA*132 + e) = make_float2(acc[t].x, acc[t].y);
            *(float2*)(mt + pB*132 + e) = make_float2(acc[t].z, acc[t].w);
        }
    }
    __syncthreads();
    // LayerNorm stats: warp handles 16 pixels, lanes reduce over 128 channels
    for (int p = warp*16; p < warp*16 + 16; p++){
        float4 v = *(const float4*)(mt + p*132 + lane*4);
        float s = v.x + v.y + v.z + v.w;
        s += __shfl_xor_sync(0xffffffffu, s, 16);
        s += __shfl_xor_sync(0xffffffffu, s, 8);
        s += __shfl_xor_sync(0xffffffffu, s, 4);
        s += __shfl_xor_sync(0xffffffffu, s, 2);
        s += __shfl_xor_sync(0xffffffffu, s, 1);
        float mu = s * (1.f/128.f);
        float dx = v.x - mu, dy = v.y - mu, dz = v.z - mu, dww = v.w - mu;
        float q = dx*dx + dy*dy + dz*dz + dww*dww;
        q += __shfl_xor_sync(0xffffffffu, q, 16);
        q += __shfl_xor_sync(0xffffffffu, q, 8);
        q += __shfl_xor_sync(0xffffffffu, q, 4);
        q += __shfl_xor_sync(0xffffffffu, q, 2);
        q += __shfl_xor_sync(0xffffffffu, q, 1);
        if (lane == 0){
            mus[p] = mu;
            rss[p] = rsqrtf(q * (1.f/128.f) + 1e-5f);
        }
    }
    __syncthreads();
    int e = tid;
    float ga = gamma[e], be = beta[e];
    int g = e >> 5;
    float4 w2r[8];
#pragma unroll
    for (int i = 0; i < 8; i++) w2r[i] = *(const float4*)(w2 + e*32 + i*4);
    float x1n[64];
#pragma unroll 1
    for (int p = 0; p < 64; p++){
        x1n[p] = fmaf((mt[p*132 + e] - mus[p]) * rss[p], ga, be);
    }
    __syncthreads();   // mt reads done; fs (alias of yt) can now be written? (yt already dead)
#pragma unroll 1
    for (int p = 0; p < 64; p++){
        const float* xr = xt + p*128 + g*32;
        float a2 = 0.f;
#pragma unroll
        for (int i = 0; i < 8; i++){
            float4 xv = *(const float4*)(xr + i*4);
            a2 = fmaf(w2r[i].x, xv.x, a2); a2 = fmaf(w2r[i].y, xv.y, a2);
            a2 = fmaf(w2r[i].z, xv.z, a2); a2 = fmaf(w2r[i].w, xv.w, a2);
        }
        fs[p*128 + e] = x1n[p] * siluf(a2);
    }
    __syncthreads();
    float4 wor[8];
#pragma unroll
    for (int i = 0; i < 8; i++) wor[i] = *(const float4*)(wout + e*32 + i*4);
#pragma unroll 1
    for (int p = 0; p < 64; p++){
        const float* fr = fs + p*128 + g*32;
        float a = 0.f;
#pragma unroll
        for (int i = 0; i < 8; i++){
            float4 fv = *(const float4*)(fr + i*4);
            a = fmaf(wor[i].x, fv.x, a); a = fmaf(wor[i].y, fv.y, a);
            a = fmaf(wor[i].z, fv.z, a); a = fmaf(wor[i].w, fv.w, a);
        }
        out[(size_t)(pix0 + p)*128 + e] = a;
    }
}

// ----------------------------------------------------------------
extern "C" void kernel_launch(void* const* d_in, const int* in_sizes, int n_in,
                              void* d_out, int out_size){
    const float* x        = (const float*)d_in[0];
    const float* w1       = (const float*)d_in[1];
    const float* dw       = (const float*)d_in[2];
    const float* in_proj  = (const float*)d_in[3];
    const float* conv1d_w = (const float*)d_in[4];
    const float* conv1d_b = (const float*)d_in[5];
    const float* x_proj_w = (const float*)d_in[6];
    const float* dt_proj_w= (const float*)d_in[7];
    const float* dt_proj_b= (const float*)d_in[8];
    const float* A_log    = (const float*)d_in[9];
    const float* D_param  = (const float*)d_in[10];
    const float* out_proj = (const float*)d_in[11];
    const float* gamma    = (const float*)d_in[12];
    const float* beta     = (const float*)d_in[13];
    const float* w2       = (const float*)d_in[14];
    const float* wout     = (const float*)d_in[15];
    float* out = (float*)d_out;

    float *t1, *xs, *u0, *z, *u, *dl, *Bm, *Cm, *yp, *Pg, *hE, *h0;
    cudaGetSymbolAddress((void**)&t1, g_t1);
    cudaGetSymbolAddress((void**)&xs, g_xs);
    cudaGetSymbolAddress((void**)&u0, g_u0);
    cudaGetSymbolAddress((void**)&z,  g_z);
    cudaGetSymbolAddress((void**)&u,  g_u);
    cudaGetSymbolAddress((void**)&dl, g_dl);
    cudaGetSymbolAddress((void**)&Bm, g_Bm);
    cudaGetSymbolAddress((void**)&Cm, g_Cm);
    cudaGetSymbolAddress((void**)&yp, g_yp);
    cudaGetSymbolAddress((void**)&Pg, g_P);
    cudaGetSymbolAddress((void**)&hE, g_hE);
    cudaGetSymbolAddress((void**)&h0, g_h0);

    const int smemA = (2*CS*128 + CS*8) * sizeof(float);
    const int smemC = (3*CS*128 + 2*CS*8) * sizeof(float);
    const int smemI = (128*132 + 256*132) * sizeof(float);
    const int smemF = (64*132 + 128*132 + 64*132 + 64*128 + 128) * sizeof(float);
    static int attr_done = 0;
    if (!attr_done){
        cudaFuncSetAttribute(k_scanA, cudaFuncAttributeMaxDynamicSharedMemorySize, smemA);
        cudaFuncSetAttribute(k_scanC, cudaFuncAttributeMaxDynamicSharedMemorySize, smemC);
        cudaFuncSetAttribute(k_inproj, cudaFuncAttributeMaxDynamicSharedMemorySize, smemI);
        cudaFuncSetAttribute(k_final, cudaFuncAttributeMaxDynamicSharedMemorySize, smemF);
        attr_done = 1;
    }

    k_g1<<<NPIX*128/256, 256>>>(x, w1, t1);
    k_dw<<<NPIX*32/256, 256>>>(t1, dw, xs);
    k_inproj<<<NPIX/128, 256, smemI>>>(xs, in_proj, u0, z);
    k_conv1d<<<NPIX*32/256, 256>>>(u0, conv1d_w, conv1d_b, u);
    k_xproj<<<NPIX/8, 128>>>(u, x_proj_w, dt_proj_w, dt_proj_b, dl, Bm, Cm);
    k_scanA<<<BB*NC, 1024, smemA>>>(dl, u, Bm, A_log, Pg, hE);
    k_scanB<<<8, 1024>>>(Pg, hE, h0);
    k_scanC<<<BB*NC, 1024, smemC>>>(dl, u, z, Bm, Cm, A_log, D_param, h0, yp);
    k_final<<<NPIX/64, 128, smemF>>>(yp, out_proj, gamma, beta, x, w2, wout, out);
}

// round 4
// speedup vs baseline: 6.4094x; 1.7867x over previous
#include <cuda_runtime.h>
#include <math.h>
#include <stdint.h>

// Problem constants
#define BB 8
#define HH 64
#define WW 64
#define CC 128
#define DD 128
#define LL 4096            // H*W
#define NPIX (BB*LL)       // 32768
#define NS 8               // D_STATE
#define RR 8               // DT_RANK

#define CS 64              // chunk size (steps)
#define NC (LL/CS)         // 64 chunks per batch

// Scratch (device globals; no allocations allowed)
__device__ float g_t1[NPIX*DD];
__device__ float g_xs[NPIX*DD];
__device__ float g_u0[NPIX*DD];
__device__ float g_z [NPIX*DD];
__device__ float g_u [NPIX*DD];
__device__ float g_dl[NPIX*DD];
__device__ float g_Bm[NPIX*NS];
__device__ float g_Cm[NPIX*NS];
__device__ float g_yp[NPIX*DD];
__device__ float g_P [BB*NC*1024];
__device__ float g_hE[BB*NC*1024];
__device__ float g_h0[BB*NC*1024];

__device__ __forceinline__ float siluf(float v){ return v / (1.f + __expf(-v)); }

__device__ __forceinline__ uint32_t f2tf(float x){
    uint32_t r; asm("cvt.rna.tf32.f32 %0, %1;" : "=r"(r) : "f"(x)); return r;
}
__device__ __forceinline__ void mma8(float4& c, uint32_t a0, uint32_t a1, uint32_t a2, uint32_t a3,
                                     uint32_t b0, uint32_t b1){
    asm volatile("mma.sync.aligned.m16n8k8.row.col.f32.tf32.tf32.f32 "
                 "{%0,%1,%2,%3},{%4,%5,%6,%7},{%8,%9},{%0,%1,%2,%3};\n"
                 : "+f"(c.x), "+f"(c.y), "+f"(c.z), "+f"(c.w)
                 : "r"(a0), "r"(a1), "r"(a2), "r"(a3), "r"(b0), "r"(b1));
}

// ---------------------------------------------------------------- K1: grouped 1x1 (x @ w1)
// 256 thr, 32 pixels/block. Weights per output channel -> registers (L1-hot LDG),
// x tile in smem read via warp-broadcast (conflict-free).
__global__ void __launch_bounds__(256) k_g1(const float* __restrict__ x,
                                            const float* __restrict__ w,
                                            float* __restrict__ out){
    __shared__ float xt[32*128];
    int pix0 = blockIdx.x * 32;
    const float4* x4 = (const float4*)(x + (size_t)pix0*128);
    for (int i = threadIdx.x; i < 32*32; i += 256) ((float4*)xt)[i] = x4[i];
    __syncthreads();
    int t = threadIdx.x;
    int c = t & 127, half = t >> 7;
    int g = c >> 5;
    float4 wr[8];
#pragma unroll
    for (int i = 0; i < 8; i++) wr[i] = ((const float4*)(w + c*32))[i];
    const float* xb = xt + (half*16)*128 + g*32;
    float* ob = out + ((size_t)pix0 + half*16)*128 + c;
#pragma unroll
    for (int p = 0; p < 16; p++){
        const float* xr = xb + p*128;
        float a = 0.f;
#pragma unroll
        for (int i = 0; i < 8; i++){
            float4 xv = *(const float4*)(xr + i*4);
            a = fmaf(wr[i].x, xv.x, a); a = fmaf(wr[i].y, xv.y, a);
            a = fmaf(wr[i].z, xv.z, a); a = fmaf(wr[i].w, xv.w, a);
        }
        ob[(size_t)p*128] = a;
    }
}

// ---------------------------------------------------------------- K2: depthwise 3x3 + silu (float4/thread)
__global__ void k_dw(const float* __restrict__ t1, const float* __restrict__ dw,
                     float* __restrict__ out){
    int idx = blockIdx.x * 256 + threadIdx.x;     // NPIX*32 total
    int d4 = idx & 31; int pix = idx >> 5;
    int wc = pix & 63; int h = (pix >> 6) & 63; int b = pix >> 12;
    int d = d4 << 2;
    float4 acc = make_float4(0.f, 0.f, 0.f, 0.f);
#pragma unroll
    for (int kh = 0; kh < 3; kh++){
        int hh = h + kh - 1; if (hh < 0 || hh >= 64) continue;
#pragma unroll
        for (int kw = 0; kw < 3; kw++){
            int ww = wc + kw - 1; if (ww < 0 || ww >= 64) continue;
            float4 tv = *(const float4*)(t1 + (((b*64 + hh)*64 + ww) << 7) + d);
            float4 wv = *(const float4*)(dw + (kh*3 + kw)*128 + d);
            acc.x = fmaf(tv.x, wv.x, acc.x); acc.y = fmaf(tv.y, wv.y, acc.y);
            acc.z = fmaf(tv.z, wv.z, acc.z); acc.w = fmaf(tv.w, wv.w, acc.w);
        }
    }
    float4 r; r.x = siluf(acc.x); r.y = siluf(acc.y); r.z = siluf(acc.z); r.w = siluf(acc.w);
    *(float4*)(out + (size_t)pix*128 + d) = r;
}

// ---------------------------------------------------------------- K3: in_proj via tf32 mma (split weights)
__global__ void __launch_bounds__(256, 1) k_inproj(const float* __restrict__ xs,
                                                   const float* __restrict__ w,
                                                   float* __restrict__ ub, float* __restrict__ zb){
    extern __shared__ float sm[];
    float* xt = sm;            // 128*132
    float* ws = sm + 128*132;  // 256*132
    int tid = threadIdx.x;
    int pix0 = blockIdx.x * 128;
    {
        const float4* xs4 = (const float4*)(xs + (size_t)pix0*128);
        for (int i = tid; i < 128*32; i += 256){
            int p = i >> 5, q = i & 31;
            float4 v = xs4[i];
            v.x = __uint_as_float(f2tf(v.x)); v.y = __uint_as_float(f2tf(v.y));
            v.z = __uint_as_float(f2tf(v.z)); v.w = __uint_as_float(f2tf(v.w));
            *(float4*)(xt + p*132 + q*4) = v;
        }
        const float4* w4 = (const float4*)w;
        for (int i = tid; i < 256*32; i += 256){
            int e = i >> 5, q = i & 31;
            *(float4*)(ws + e*132 + q*4) = w4[i];
        }
    }
    __syncthreads();
    int warp = tid >> 5, lane = tid & 31;
    int row_ = lane >> 2, col_ = lane & 3;
    int p0 = warp * 16;
    const float* xrA = xt + (p0 + row_)*132 + col_;
    const float* xrB = xt + (p0 + row_ + 8)*132 + col_;
#pragma unroll 1
    for (int g = 0; g < 4; g++){
        float4 acc[8];
#pragma unroll
        for (int t = 0; t < 8; t++) acc[t] = make_float4(0.f,0.f,0.f,0.f);
#pragma unroll 4
        for (int k = 0; k < 16; k++){
            int k8 = k*8;
            uint32_t a0 = __float_as_uint(xrA[k8]);
            uint32_t a1 = __float_as_uint(xrB[k8]);
            uint32_t a2 = __float_as_uint(xrA[k8 + 4]);
            uint32_t a3 = __float_as_uint(xrB[k8 + 4]);
#pragma unroll
            for (int t = 0; t < 8; t++){
                int e0 = g*64 + t*8;
                float b0r = ws[(e0 + row_)*132 + k8 + col_];
                float b1r = ws[(e0 + row_)*132 + k8 + col_ + 4];
                uint32_t bh0 = f2tf(b0r);
                uint32_t bl0 = f2tf(b0r - __uint_as_float(bh0));
                uint32_t bh1 = f2tf(b1r);
                uint32_t bl1 = f2tf(b1r - __uint_as_float(bh1));
                mma8(acc[t], a0, a1, a2, a3, bh0, bh1);
                mma8(acc[t], a0, a1, a2, a3, bl0, bl1);
            }
        }
        int pixA = pix0 + p0 + row_;
        int pixB = pixA + 8;
#pragma unroll
        for (int t = 0; t < 8; t++){
            int e0 = g*64 + t*8 + 2*col_;
            float* base = (g < 2) ? (ub + e0) : (zb + e0 - 128);
            *(float2*)(base + (size_t)pixA*128) = make_float2(acc[t].x, acc[t].y);
            *(float2*)(base + (size_t)pixB*128) = make_float2(acc[t].z, acc[t].w);
        }
    }
}

// ---------------------------------------------------------------- K4: causal conv1d(k=3) + silu (float4/thread)
__global__ void k_conv1d(const float* __restrict__ u0, const float* __restrict__ cw,
                         const float* __restrict__ cb, float* __restrict__ uo){
    int idx = blockIdx.x * 256 + threadIdx.x;   // NPIX*32 total
    int d4 = idx & 31; int pix = idx >> 5;
    int l = pix & (LL - 1);
    int d = d4 << 2;
    const float4* cwv = (const float4*)(cw + d*3);
    float4 Aq = cwv[0], Bq = cwv[1], Cq = cwv[2];
    float4 b4 = *(const float4*)(cb + d);
    const float* up = u0 + (size_t)pix*128 + d;
    float4 x0 = *(const float4*)up;
    float4 x1 = make_float4(0,0,0,0), x2 = make_float4(0,0,0,0);
    if (l >= 1) x1 = *(const float4*)(up - 128);
    if (l >= 2) x2 = *(const float4*)(up - 256);
    float4 r;
    r.x = fmaf(Aq.x, x2.x, fmaf(Aq.y, x1.x, fmaf(Aq.z, x0.x, b4.x)));
    r.y = fmaf(Aq.w, x2.y, fmaf(Bq.x, x1.y, fmaf(Bq.y, x0.y, b4.y)));
    r.z = fmaf(Bq.z, x2.z, fmaf(Bq.w, x1.z, fmaf(Cq.x, x0.z, b4.z)));
    r.w = fmaf(Cq.y, x2.w, fmaf(Cq.z, x1.w, fmaf(Cq.w, x0.w, b4.w)));
    r.x = siluf(r.x); r.y = siluf(r.y); r.z = siluf(r.z); r.w = siluf(r.w);
    *(float4*)(uo + (size_t)pix*128 + d) = r;
}

// ---------------------------------------------------------------- K5: x_proj + dt_proj + softplus
// 256 thr, 32 pixels/block. Shuffle-reduction GEMM (conflict-free LDS).
__global__ void __launch_bounds__(256) k_xproj(const float* __restrict__ u,
                        const float* __restrict__ xpw,
                        const float* __restrict__ dtw, const float* __restrict__ dtb,
                        float* __restrict__ dl, float* __restrict__ Bb, float* __restrict__ Cb){
    __shared__ float ut[32*128];
    __shared__ float wx[24*128];
    __shared__ float xd[32*24];
    int pix0 = blockIdx.x * 32;
    int t = threadIdx.x, warp = t >> 5, lane = t & 31;
    {
        const float4* u4 = (const float4*)(u + (size_t)pix0*128);
        for (int i = t; i < 32*32; i += 256) ((float4*)ut)[i] = u4[i];
        const float4* w4 = (const float4*)xpw;
        for (int i = t; i < 24*32; i += 256) ((float4*)wx)[i] = w4[i];
    }
    __syncthreads();
    // x_dbl = u @ x_proj_w^T : lanes split K (consecutive float4 -> no conflicts)
    for (int p = warp; p < 32; p += 8){
        float4 uv = ((const float4*)(ut + p*128))[lane];
#pragma unroll
        for (int j = 0; j < 24; j++){
            float4 wv = ((const float4*)(wx + j*128))[lane];
            float s = uv.x*wv.x + uv.y*wv.y + uv.z*wv.z + uv.w*wv.w;
            s += __shfl_xor_sync(0xffffffffu, s, 16);
            s += __shfl_xor_sync(0xffffffffu, s, 8);
            s += __shfl_xor_sync(0xffffffffu, s, 4);
            s += __shfl_xor_sync(0xffffffffu, s, 2);
            s += __shfl_xor_sync(0xffffffffu, s, 1);
            if (lane == 0) xd[p*24 + j] = s;
        }
    }
    __syncthreads();
    // dt_proj + softplus: thread = (half, d); wd row in registers
    int d = t & 127, ph = t >> 7;
    float4 wa = ((const float4*)(dtw + d*8))[0];
    float4 wb = ((const float4*)(dtw + d*8))[1];
    float bias = dtb[d];
#pragma unroll
    for (int p = ph*16; p < ph*16 + 16; p++){
        const float* xr = xd + p*24;
        float a = bias;
        a = fmaf(xr[0], wa.x, a); a = fmaf(xr[1], wa.y, a);
        a = fmaf(xr[2], wa.z, a); a = fmaf(xr[3], wa.w, a);
        a = fmaf(xr[4], wb.x, a); a = fmaf(xr[5], wb.y, a);
        a = fmaf(xr[6], wb.z, a); a = fmaf(xr[7], wb.w, a);
        float sp = (a > 20.f) ? a : log1pf(__expf(a));
        dl[(size_t)(pix0 + p)*128 + d] = sp;
    }
    // B/C: 32 pix x 8 n = 256 = blockDim
    {
        int p = t >> 3, n = t & 7;
        Bb[(pix0 + p)*8 + n] = xd[p*24 + 8 + n];
        Cb[(pix0 + p)*8 + n] = xd[p*24 + 16 + n];
    }
}

// ---------------------------------------------------------------- K6a: chunked scan, phase A
__global__ void k_scanA(const float* __restrict__ dl, const float* __restrict__ u,
                        const float* __restrict__ Bb, const float* __restrict__ A_log,
                        float* __restrict__ Pg, float* __restrict__ hEg){
    extern __shared__ float sm[];
    float* sdl = sm;            // CS*128
    float* su  = sm + CS*128;   // CS*128
    float* sB  = sm + 2*CS*128; // CS*8
    int b = blockIdx.x >> 6;
    int c = blockIdx.x & (NC - 1);
    int t = threadIdx.x;
    size_t base = ((size_t)b*LL + c*CS)*128;
    {
        const float4* dl4 = (const float4*)(dl + base);
        const float4* u4  = (const float4*)(u + base);
        for (int i = t; i < CS*32; i += 1024){
            ((float4*)sdl)[i] = dl4[i];
            ((float4*)su)[i]  = u4[i];
        }
    }
    int nb = (b*LL + c*CS)*8;
    if (t < CS*8) sB[t] = Bb[nb + t];
    __syncthreads();
    int d = t >> 3, n = t & 7;
    float Av = -__expf(A_log[d*8 + n]);
    float h = 0.f, P = 1.f;
#pragma unroll 8
    for (int l = 0; l < CS; l++){
        float de = sdl[l*128 + d];
        float uu = su[l*128 + d];
        float dA = __expf(de * Av);
        P *= dA;
        h = fmaf(dA, h, de * uu * sB[l*8 + n]);
    }
    int oidx = (b*NC + c)*1024 + t;
    Pg[oidx] = P;
    hEg[oidx] = h;
}

// ---------------------------------------------------------------- K6b: chunk combine
__global__ void k_scanB(const float* __restrict__ Pg, const float* __restrict__ hEg,
                        float* __restrict__ h0g){
    int j = blockIdx.x * 1024 + threadIdx.x;
    int b = j >> 10, dn = j & 1023;
    float h = 0.f;
#pragma unroll 8
    for (int c = 0; c < NC; c++){
        int idx = (b*NC + c)*1024 + dn;
        h0g[idx] = h;
        h = fmaf(Pg[idx], h, hEg[idx]);
    }
}

// ---------------------------------------------------------------- K6c: chunked scan, phase C
__global__ void k_scanC(const float* __restrict__ dl, const float* __restrict__ u,
                        const float* __restrict__ z, const float* __restrict__ Bb,
                        const float* __restrict__ Cb, const float* __restrict__ A_log,
                        const float* __restrict__ Dp, const float* __restrict__ h0g,
                        float* __restrict__ yp){
    extern __shared__ float sm[];
    float* sdl = sm;              // CS*128
    float* su  = sm + CS*128;     // CS*128
    float* sy  = sm + 2*CS*128;   // CS*128
    float* sB  = sm + 3*CS*128;   // CS*8
    float* sC  = sm + 3*CS*128 + CS*8; // CS*8
    int b = blockIdx.x >> 6;
    int c = blockIdx.x & (NC - 1);
    int t = threadIdx.x;
    size_t base = ((size_t)b*LL + c*CS)*128;
    {
        const float4* dl4 = (const float4*)(dl + base);
        const float4* u4  = (const float4*)(u + base);
        for (int i = t; i < CS*32; i += 1024){
            ((float4*)sdl)[i] = dl4[i];
            ((float4*)su)[i]  = u4[i];
        }
    }
    int nb = (b*LL + c*CS)*8;
    if (t < CS*8){
        sB[t] = Bb[nb + t];
        sC[t] = Cb[nb + t];
    }
    __syncthreads();
    int d = t >> 3, n = t & 7;
    float Av = -__expf(A_log[d*8 + n]);
    float h = h0g[(b*NC + c)*1024 + t];
#pragma unroll 4
    for (int l = 0; l < CS; l++){
        float de = sdl[l*128 + d];
        float uu = su[l*128 + d];
        float dA = __expf(de * Av);
        h = fmaf(dA, h, de * uu * sB[l*8 + n]);
        float y = h * sC[l*8 + n];
        y += __shfl_xor_sync(0xffffffffu, y, 1);
        y += __shfl_xor_sync(0xffffffffu, y, 2);
        y += __shfl_xor_sync(0xffffffffu, y, 4);
        if (n == 0) sy[l*128 + d] = y;
    }
    __syncthreads();
    {
        const float4* z4 = (const float4*)(z + base);
        float4* yp4 = (float4*)(yp + base);
        for (int i = t; i < CS*32; i += 1024){
            float4 sv = ((float4*)sy)[i];
            float4 uv = ((float4*)su)[i];
            float4 zv = z4[i];
            float4 Dv = *(const float4*)(Dp + ((i & 31) << 2));
            float4 r;
            r.x = fmaf(uv.x, Dv.x, sv.x) * siluf(zv.x);
            r.y = fmaf(uv.y, Dv.y, sv.y) * siluf(zv.y);
            r.z = fmaf(uv.z, Dv.z, sv.z) * siluf(zv.z);
            r.w = fmaf(uv.w, Dv.w, sv.w) * siluf(zv.w);
            yp4[i] = r;
        }
    }
}

// ---------------------------------------------------------------- K7: out_proj (tf32 mma) + LN + gating + out g1x1
// 256 thr (8 warps), 64 pixels/block. smem aliased: ws->xt, yt->fs. 135.7 KB.
__global__ void __launch_bounds__(256, 1) k_final(const float* __restrict__ yp,
                        const float* __restrict__ opw,
                        const float* __restrict__ gamma, const float* __restrict__ beta,
                        const float* __restrict__ x, const float* __restrict__ w2,
                        const float* __restrict__ wout, float* __restrict__ out){
    extern __shared__ float sm[];
    float* yt   = sm;                   // 64*132 tf32 A; reused as fs
    float* ws   = sm + 64*132;          // 128*132 weights; reused as xt (64*128)
    float* mt   = ws + 128*132;         // 64*132
    float* mus  = mt + 64*132;          // 64
    float* rss  = mus + 64;             // 64
    float* fs   = yt;
    float* xt   = ws;
    int t = threadIdx.x, warp = t >> 5, lane = t & 31;
    int pix0 = blockIdx.x * 64;
    {
        const float4* y4 = (const float4*)(yp + (size_t)pix0*128);
        for (int i = t; i < 64*32; i += 256){
            int p = i >> 5, q = i & 31;
            float4 v = y4[i];
            v.x = __uint_as_float(f2tf(v.x)); v.y = __uint_as_float(f2tf(v.y));
            v.z = __uint_as_float(f2tf(v.z)); v.w = __uint_as_float(f2tf(v.w));
            *(float4*)(yt + p*132 + q*4) = v;
        }
        const float4* w4 = (const float4*)opw;
        for (int i = t; i < 128*32; i += 256){
            int e = i >> 5, q = i & 31;
            *(float4*)(ws + e*132 + q*4) = w4[i];
        }
    }
    __syncthreads();
    // GEMM: warp -> (mtile = warp>>1 : 16 pixels, nhalf = warp&1 : 64 channels)
    {
        int row_ = lane >> 2, col_ = lane & 3;
        int p0 = (warp >> 1) * 16;
        int e00 = (warp & 1) * 64;
        const float* yrA = yt + (p0 + row_)*132 + col_;
        const float* yrB = yrA + 8*132;
        float4 acc[8];
#pragma unroll
        for (int tt = 0; tt < 8; tt++) acc[tt] = make_float4(0.f,0.f,0.f,0.f);
#pragma unroll 4
        for (int k = 0; k < 16; k++){
            int k8 = k*8;
            uint32_t a0 = __float_as_uint(yrA[k8]);
            uint32_t a1 = __float_as_uint(yrB[k8]);
            uint32_t a2 = __float_as_uint(yrA[k8 + 4]);
            uint32_t a3 = __float_as_uint(yrB[k8 + 4]);
#pragma unroll
            for (int tt = 0; tt < 8; tt++){
                int e0 = e00 + tt*8;
                float b0r = ws[(e0 + row_)*132 + k8 + col_];
                float b1r = ws[(e0 + row_)*132 + k8 + col_ + 4];
                uint32_t bh0 = f2tf(b0r);
                uint32_t bl0 = f2tf(b0r - __uint_as_float(bh0));
                uint32_t bh1 = f2tf(b1r);
                uint32_t bl1 = f2tf(b1r - __uint_as_float(bh1));
                mma8(acc[tt], a0, a1, a2, a3, bh0, bh1);
                mma8(acc[tt], a0, a1, a2, a3, bl0, bl1);
            }
        }
        int pA = p0 + row_, pB = pA + 8;
#pragma unroll
        for (int tt = 0; tt < 8; tt++){
            int e = e00 + tt*8 + 2*col_;
            *(float2*)(mt + pA*132 + e) = make_float2(acc[tt].x, acc[tt].y);
            *(float2*)(mt + pB*132 + e) = make_float2(acc[tt].z, acc[tt].w);
        }
    }
    __syncthreads();   // GEMM done: ws dead, mt valid
    // load xt (aliases ws), LN stats from mt (8 pixels per warp)
    {
        const float4* x4 = (const float4*)(x + (size_t)pix0*128);
        for (int i = t; i < 64*32; i += 256){
            int p = i >> 5, q = i & 31;
            *(float4*)(xt + p*128 + q*4) = x4[i];
        }
    }
    for (int p = warp*8; p < warp*8 + 8; p++){
        float4 v = *(const float4*)(mt + p*132 + lane*4);
        float s = v.x + v.y + v.z + v.w;
        s += __shfl_xor_sync(0xffffffffu, s, 16);
        s += __shfl_xor_sync(0xffffffffu, s, 8);
        s += __shfl_xor_sync(0xffffffffu, s, 4);
        s += __shfl_xor_sync(0xffffffffu, s, 2);
        s += __shfl_xor_sync(0xffffffffu, s, 1);
        float mu = s * (1.f/128.f);
        float dx = v.x - mu, dy = v.y - mu, dz = v.z - mu, dww = v.w - mu;
        float q = dx*dx + dy*dy + dz*dz + dww*dww;
        q += __shfl_xor_sync(0xffffffffu, q, 16);
        q += __shfl_xor_sync(0xffffffffu, q, 8);
        q += __shfl_xor_sync(0xffffffffu, q, 4);
        q += __shfl_xor_sync(0xffffffffu, q, 2);
        q += __shfl_xor_sync(0xffffffffu, q, 1);
        if (lane == 0){
            mus[p] = mu;
            rss[p] = rsqrtf(q * (1.f/128.f) + 1e-5f);
        }
    }
    __syncthreads();
    // gating: thread = (half, e); 32 pixels each
    int e = t & 127, ph = t >> 7;
    int g = e >> 5;
    float ga = gamma[e], be = beta[e];
    {
        float4 w2r[8];
#pragma unroll
        for (int i = 0; i < 8; i++) w2r[i] = *(const float4*)(w2 + e*32 + i*4);
#pragma unroll 1
        for (int p = ph*32; p < ph*32 + 32; p++){
            float x1n = fmaf((mt[p*132 + e] - mus[p]) * rss[p], ga, be);
            const float* xr = xt + p*128 + g*32;
            float a2 = 0.f;
#pragma unroll
            for (int i = 0; i < 8; i++){
                float4 xv = *(const float4*)(xr + i*4);
                a2 = fmaf(w2r[i].x, xv.x, a2); a2 = fmaf(w2r[i].y, xv.y, a2);
                a2 = fmaf(w2r[i].z, xv.z, a2); a2 = fmaf(w2r[i].w, xv.w, a2);
            }
            fs[p*128 + e] = x1n * siluf(a2);
        }
    }
    __syncthreads();
    {
        float4 wor[8];
#pragma unroll
        for (int i = 0; i < 8; i++) wor[i] = *(const float4*)(wout + e*32 + i*4);
#pragma unroll 1
        for (int p = ph*32; p < ph*32 + 32; p++){
            const float* fr = fs + p*128 + g*32;
            float a = 0.f;
#pragma unroll
            for (int i = 0; i < 8; i++){
                float4 fv = *(const float4*)(fr + i*4);
                a = fmaf(wor[i].x, fv.x, a); a = fmaf(wor[i].y, fv.y, a);
                a = fmaf(wor[i].z, fv.z, a); a = fmaf(wor[i].w, fv.w, a);
            }
            out[(size_t)(pix0 + p)*128 + e] = a;
        }
    }
}

// ----------------------------------------------------------------
extern "C" void kernel_launch(void* const* d_in, const int* in_sizes, int n_in,
                              void* d_out, int out_size){
    const float* x        = (const float*)d_in[0];
    const float* w1       = (const float*)d_in[1];
    const float* dw       = (const float*)d_in[2];
    const float* in_proj  = (const float*)d_in[3];
    const float* conv1d_w = (const float*)d_in[4];
    const float* conv1d_b = (const float*)d_in[5];
    const float* x_proj_w = (const float*)d_in[6];
    const float* dt_proj_w= (const float*)d_in[7];
    const float* dt_proj_b= (const float*)d_in[8];
    const float* A_log    = (const float*)d_in[9];
    const float* D_param  = (const float*)d_in[10];
    const float* out_proj = (const float*)d_in[11];
    const float* gamma    = (const float*)d_in[12];
    const float* beta     = (const float*)d_in[13];
    const float* w2       = (const float*)d_in[14];
    const float* wout     = (const float*)d_in[15];
    float* out = (float*)d_out;

    float *t1, *xs, *u0, *z, *u, *dl, *Bm, *Cm, *yp, *Pg, *hE, *h0;
    cudaGetSymbolAddress((void**)&t1, g_t1);
    cudaGetSymbolAddress((void**)&xs, g_xs);
    cudaGetSymbolAddress((void**)&u0, g_u0);
    cudaGetSymbolAddress((void**)&z,  g_z);
    cudaGetSymbolAddress((void**)&u,  g_u);
    cudaGetSymbolAddress((void**)&dl, g_dl);
    cudaGetSymbolAddress((void**)&Bm, g_Bm);
    cudaGetSymbolAddress((void**)&Cm, g_Cm);
    cudaGetSymbolAddress((void**)&yp, g_yp);
    cudaGetSymbolAddress((void**)&Pg, g_P);
    cudaGetSymbolAddress((void**)&hE, g_hE);
    cudaGetSymbolAddress((void**)&h0, g_h0);

    const int smemA = (2*CS*128 + CS*8) * sizeof(float);
    const int smemC = (3*CS*128 + 2*CS*8) * sizeof(float);
    const int smemI = (128*132 + 256*132) * sizeof(float);
    const int smemF = (64*132 + 128*132 + 64*132 + 128) * sizeof(float);
    static int attr_done = 0;
    if (!attr_done){
        cudaFuncSetAttribute(k_scanA, cudaFuncAttributeMaxDynamicSharedMemorySize, smemA);
        cudaFuncSetAttribute(k_scanC, cudaFuncAttributeMaxDynamicSharedMemorySize, smemC);
        cudaFuncSetAttribute(k_inproj, cudaFuncAttributeMaxDynamicSharedMemorySize, smemI);
        cudaFuncSetAttribute(k_final, cudaFuncAttributeMaxDynamicSharedMemorySize, smemF);
        attr_done = 1;
    }

    k_g1<<<NPIX/32, 256>>>(x, w1, t1);
    k_dw<<<NPIX*32/256, 256>>>(t1, dw, xs);
    k_inproj<<<NPIX/128, 256, smemI>>>(xs, in_proj, u0, z);
    k_conv1d<<<NPIX*32/256, 256>>>(u0, conv1d_w, conv1d_b, u);
    k_xproj<<<NPIX/32, 256>>>(u, x_proj_w, dt_proj_w, dt_proj_b, dl, Bm, Cm);
    k_scanA<<<BB*NC, 1024, smemA>>>(dl, u, Bm, A_log, Pg, hE);
    k_scanB<<<8, 1024>>>(Pg, hE, h0);
    k_scanC<<<BB*NC, 1024, smemC>>>(dl, u, z, Bm, Cm, A_log, D_param, h0, yp);
    k_final<<<NPIX/64, 256, smemF>>>(yp, out_proj, gamma, beta, x, w2, wout, out);
}

// round 5
// speedup vs baseline: 6.4804x; 1.0111x over previous
#include <cuda_runtime.h>
#include <math.h>
#include <stdint.h>

// Problem constants
#define BB 8
#define HH 64
#define WW 64
#define CC 128
#define DD 128
#define LL 4096            // H*W
#define NPIX (BB*LL)       // 32768
#define NS 8               // D_STATE
#define RR 8               // DT_RANK

#define CS 64              // chunk size (steps)
#define NC (LL/CS)         // 64 chunks per batch

// Scratch (device globals; no allocations allowed)
__device__ float g_xs[NPIX*DD];
__device__ float g_u0[NPIX*DD];
__device__ float g_z [NPIX*DD];
__device__ float g_u [NPIX*DD];
__device__ float g_dl[NPIX*DD];
__device__ float g_Bm[NPIX*NS];
__device__ float g_Cm[NPIX*NS];
__device__ float g_yp[NPIX*DD];
__device__ float g_P [BB*NC*1024];
__device__ float g_hE[BB*NC*1024];
__device__ float g_h0[BB*NC*1024];
// pre-split tf32 weights
__device__ float g_wih[256*128];
__device__ float g_wil[256*128];
__device__ float g_woh[128*128];
__device__ float g_wol[128*128];
__device__ float g_w2h[128*32];
__device__ float g_w2l[128*32];
__device__ float g_wth[128*32];
__device__ float g_wtl[128*32];

__device__ __forceinline__ float siluf(float v){ return v / (1.f + __expf(-v)); }

__device__ __forceinline__ uint32_t f2tf(float x){
    uint32_t r; asm("cvt.rna.tf32.f32 %0, %1;" : "=r"(r) : "f"(x)); return r;
}
__device__ __forceinline__ void mma8(float4& c, uint32_t a0, uint32_t a1, uint32_t a2, uint32_t a3,
                                     uint32_t b0, uint32_t b1){
    asm volatile("mma.sync.aligned.m16n8k8.row.col.f32.tf32.tf32.f32 "
                 "{%0,%1,%2,%3},{%4,%5,%6,%7},{%8,%9},{%0,%1,%2,%3};\n"
                 : "+f"(c.x), "+f"(c.y), "+f"(c.z), "+f"(c.w)
                 : "r"(a0), "r"(a1), "r"(a2), "r"(a3), "r"(b0), "r"(b1));
}

// ---------------------------------------------------------------- K0: weight split prep
__global__ void k_prep(const float* __restrict__ wi, const float* __restrict__ wo,
                       const float* __restrict__ w2, const float* __restrict__ wt,
                       float* wih, float* wil, float* woh, float* wol,
                       float* w2h, float* w2l, float* wth, float* wtl){
    int i = blockIdx.x * 256 + threadIdx.x;
    const float* src; float* dh; float* dlo; int off;
    if (i < 32768){ src = wi; dh = wih; dlo = wil; off = i; }
    else if (i < 49152){ src = wo; dh = woh; dlo = wol; off = i - 32768; }
    else if (i < 53248){ src = w2; dh = w2h; dlo = w2l; off = i - 49152; }
    else { src = wt; dh = wth; dlo = wtl; off = i - 53248; }
    float v = src[off];
    float h = __uint_as_float(f2tf(v));
    dh[off] = h; dlo[off] = v - h;
}

// ---------------------------------------------------------------- K1: fused grouped1x1 + depthwise3x3 + silu
// 512 blocks (8 b x 64 tiles of 8x8), 256 threads. smem: x halo, t1 halo, dw weights.
__global__ void __launch_bounds__(256, 1) k_g1dw(const float* __restrict__ x,
                       const float* __restrict__ w1, const float* __restrict__ dw,
                       float* __restrict__ xs){
    extern __shared__ float sm[];
    float* xh  = sm;              // 100*128
    float* t1s = sm + 100*128;    // 100*128
    float* dws = t1s + 100*128;   // 9*128
    int b = blockIdx.x >> 6;
    int tile = blockIdx.x & 63;
    int ty0 = (tile >> 3) * 8, tx0 = (tile & 7) * 8;
    int t = threadIdx.x;
    for (int i = t; i < 9*32; i += 256) ((float4*)dws)[i] = ((const float4*)dw)[i];
    for (int i = t; i < 100*32; i += 256){
        int p = i >> 5, q = i & 31;
        int hy = ty0 + p/10 - 1, hx = tx0 + (p - (p/10)*10) - 1;
        float4 v = make_float4(0.f,0.f,0.f,0.f);
        if (hy >= 0 && hy < 64 && hx >= 0 && hx < 64)
            v = ((const float4*)x)[(size_t)((b*64 + hy)*64 + hx)*32 + q];
        ((float4*)xh)[p*32 + q] = v;
    }
    __syncthreads();
    // grouped 1x1 over 100 halo pixels
    {
        int c = t & 127, pp = t >> 7;
        int g = c >> 5;
        float4 wr[8];
#pragma unroll
        for (int i = 0; i < 8; i++) wr[i] = ((const float4*)(w1 + c*32))[i];
#pragma unroll 1
        for (int it = 0; it < 50; it++){
            int p = it*2 + pp;
            const float* xr = xh + p*128 + g*32;
            float a = 0.f;
#pragma unroll
            for (int i = 0; i < 8; i++){
                float4 xv = *(const float4*)(xr + i*4);
                a = fmaf(wr[i].x, xv.x, a); a = fmaf(wr[i].y, xv.y, a);
                a = fmaf(wr[i].z, xv.z, a); a = fmaf(wr[i].w, xv.w, a);
            }
            t1s[p*128 + c] = a;
        }
    }
    __syncthreads();
    // depthwise 3x3 + silu over 64 interior pixels
    {
        int d4 = t & 31, pp = t >> 5;
        int d = d4 << 2;
#pragma unroll 1
        for (int it = 0; it < 8; it++){
            int p = pp*8 + it;
            int py = p >> 3, px = p & 7;
            int hr = (py + 1)*10 + px + 1;
            float4 acc = make_float4(0.f,0.f,0.f,0.f);
#pragma unroll
            for (int ky = 0; ky < 3; ky++){
#pragma unroll
                for (int kx = 0; kx < 3; kx++){
                    float4 tv = *(const float4*)(t1s + (hr + (ky-1)*10 + (kx-1))*128 + d);
                    float4 wv = *(const float4*)(dws + (ky*3 + kx)*128 + d);
                    acc.x = fmaf(tv.x, wv.x, acc.x); acc.y = fmaf(tv.y, wv.y, acc.y);
                    acc.z = fmaf(tv.z, wv.z, acc.z); acc.w = fmaf(tv.w, wv.w, acc.w);
                }
            }
            float4 r; r.x = siluf(acc.x); r.y = siluf(acc.y); r.z = siluf(acc.z); r.w = siluf(acc.w);
            *(float4*)(xs + (size_t)((b*64 + ty0 + py)*64 + tx0 + px)*128 + d) = r;
        }
    }
}

// ---------------------------------------------------------------- K2: in_proj via tf32 mma (pre-split weights)
// 256 thr, 128 pixels/block. Per-group weight staging (hi/lo).
__global__ void __launch_bounds__(256, 1) k_inproj(const float* __restrict__ xs,
                       const float* __restrict__ wih, const float* __restrict__ wil,
                       float* __restrict__ ub, float* __restrict__ zb){
    extern __shared__ float sm[];
    float* xt  = sm;             // 128*132
    float* whs = sm + 128*132;   // 64*132
    float* wls = whs + 64*132;   // 64*132
    int tid = threadIdx.x;
    int pix0 = blockIdx.x * 128;
    {
        const float4* xs4 = (const float4*)(xs + (size_t)pix0*128);
        for (int i = tid; i < 128*32; i += 256){
            int p = i >> 5, q = i & 31;
            float4 v = xs4[i];
            v.x = __uint_as_float(f2tf(v.x)); v.y = __uint_as_float(f2tf(v.y));
            v.z = __uint_as_float(f2tf(v.z)); v.w = __uint_as_float(f2tf(v.w));
            *(float4*)(xt + p*132 + q*4) = v;
        }
    }
    int warp = tid >> 5, lane = tid & 31;
    int row_ = lane >> 2, col_ = lane & 3;
    int p0 = warp * 16;
    const float* xrA = xt + (p0 + row_)*132 + col_;
    const float* xrB = xrA + 8*132;
#pragma unroll 1
    for (int g = 0; g < 4; g++){
        __syncthreads();
        {
            const float4* h4 = (const float4*)(wih + g*64*128);
            const float4* l4 = (const float4*)(wil + g*64*128);
            for (int i = tid; i < 64*32; i += 256){
                int r = i >> 5, q = i & 31;
                *(float4*)(whs + r*132 + q*4) = h4[i];
                *(float4*)(wls + r*132 + q*4) = l4[i];
            }
        }
        __syncthreads();
        float4 acc[8];
#pragma unroll
        for (int t = 0; t < 8; t++) acc[t] = make_float4(0.f,0.f,0.f,0.f);
#pragma unroll 4
        for (int k = 0; k < 16; k++){
            int k8 = k*8;
            uint32_t a0 = __float_as_uint(xrA[k8]);
            uint32_t a1 = __float_as_uint(xrB[k8]);
            uint32_t a2 = __float_as_uint(xrA[k8 + 4]);
            uint32_t a3 = __float_as_uint(xrB[k8 + 4]);
#pragma unroll
            for (int t = 0; t < 8; t++){
                int lt = t*8;
                uint32_t bh0 = __float_as_uint(whs[(lt + row_)*132 + k8 + col_]);
                uint32_t bh1 = __float_as_uint(whs[(lt + row_)*132 + k8 + col_ + 4]);
                uint32_t bl0 = __float_as_uint(wls[(lt + row_)*132 + k8 + col_]);
                uint32_t bl1 = __float_as_uint(wls[(lt + row_)*132 + k8 + col_ + 4]);
                mma8(acc[t], a0, a1, a2, a3, bh0, bh1);
                mma8(acc[t], a0, a1, a2, a3, bl0, bl1);
            }
        }
        int pixA = pix0 + p0 + row_;
        int pixB = pixA + 8;
#pragma unroll
        for (int t = 0; t < 8; t++){
            int e0 = g*64 + t*8 + 2*col_;
            float* base = (g < 2) ? (ub + e0) : (zb + e0 - 128);
            *(float2*)(base + (size_t)pixA*128) = make_float2(acc[t].x, acc[t].y);
            *(float2*)(base + (size_t)pixB*128) = make_float2(acc[t].z, acc[t].w);
        }
    }
}

// ---------------------------------------------------------------- K3: fused conv1d + x_proj + dt_proj + softplus
// 256 thr, 32 pixels/block.
__global__ void __launch_bounds__(256) k_cxp(const float* __restrict__ u0,
                        const float* __restrict__ cw, const float* __restrict__ cb,
                        const float* __restrict__ xpw,
                        const float* __restrict__ dtw, const float* __restrict__ dtb,
                        float* __restrict__ ug,
                        float* __restrict__ dl, float* __restrict__ Bb, float* __restrict__ Cb){
    __shared__ float u0s[34*128];          // also aliased by xd (32*24) later
    __shared__ float ut[32*128];
    __shared__ float wx[24*128];
    float* xd = u0s;
    int pix0 = blockIdx.x * 32;
    int l0 = pix0 & (LL - 1);
    int t = threadIdx.x, warp = t >> 5, lane = t & 31;
    {
        const float4* u4 = (const float4*)(u0 + ((size_t)pix0 - 2)*128);
        for (int i = t; i < 34*32; i += 256){
            int p = i >> 5;
            float4 v = make_float4(0.f,0.f,0.f,0.f);
            if (!(l0 == 0 && p < 2)) v = u4[i];
            ((float4*)u0s)[i] = v;
        }
        const float4* w4 = (const float4*)xpw;
        for (int i = t; i < 24*32; i += 256) ((float4*)wx)[i] = w4[i];
    }
    __syncthreads();
    // causal conv1d + silu -> ut (smem) + ug (global)
    {
        int d = t & 127, ph = t >> 7;
        float w0 = cw[d*3], w1c = cw[d*3 + 1], w2c = cw[d*3 + 2];
        float bias = cb[d];
#pragma unroll
        for (int p = ph*16; p < ph*16 + 16; p++){
            float a = fmaf(w2c, u0s[(p + 2)*128 + d],
                      fmaf(w1c, u0s[(p + 1)*128 + d],
                      fmaf(w0,  u0s[p*128 + d], bias)));
            a = siluf(a);
            ut[p*128 + d] = a;
            ug[(size_t)(pix0 + p)*128 + d] = a;
        }
    }
    __syncthreads();
    // x_dbl = u @ x_proj_w^T (shuffle reduction)
    for (int p = warp; p < 32; p += 8){
        float4 uv = ((const float4*)(ut + p*128))[lane];
#pragma unroll
        for (int j = 0; j < 24; j++){
            float4 wv = ((const float4*)(wx + j*128))[lane];
            float s = uv.x*wv.x + uv.y*wv.y + uv.z*wv.z + uv.w*wv.w;
            s += __shfl_xor_sync(0xffffffffu, s, 16);
            s += __shfl_xor_sync(0xffffffffu, s, 8);
            s += __shfl_xor_sync(0xffffffffu, s, 4);
            s += __shfl_xor_sync(0xffffffffu, s, 2);
            s += __shfl_xor_sync(0xffffffffu, s, 1);
            if (lane == 0) xd[p*24 + j] = s;
        }
    }
    __syncthreads();
    // dt_proj + softplus
    {
        int d = t & 127, ph = t >> 7;
        float4 wa = ((const float4*)(dtw + d*8))[0];
        float4 wb = ((const float4*)(dtw + d*8))[1];
        float bias = dtb[d];
#pragma unroll
        for (int p = ph*16; p < ph*16 + 16; p++){
            const float* xr = xd + p*24;
            float a = bias;
            a = fmaf(xr[0], wa.x, a); a = fmaf(xr[1], wa.y, a);
            a = fmaf(xr[2], wa.z, a); a = fmaf(xr[3], wa.w, a);
            a = fmaf(xr[4], wb.x, a); a = fmaf(xr[5], wb.y, a);
            a = fmaf(xr[6], wb.z, a); a = fmaf(xr[7], wb.w, a);
            float sp = (a > 20.f) ? a : log1pf(__expf(a));
            dl[(size_t)(pix0 + p)*128 + d] = sp;
        }
    }
    {
        int p = t >> 3, n = t & 7;
        Bb[(pix0 + p)*8 + n] = xd[p*24 + 8 + n];
        Cb[(pix0 + p)*8 + n] = xd[p*24 + 16 + n];
    }
}

// ---------------------------------------------------------------- K4: chunked scan, phase A
__global__ void k_scanA(const float* __restrict__ dl, const float* __restrict__ u,
                        const float* __restrict__ Bb, const float* __restrict__ A_log,
                        float* __restrict__ Pg, float* __restrict__ hEg){
    extern __shared__ float sm[];
    float* sdl = sm;            // CS*128
    float* su  = sm + CS*128;   // CS*128
    float* sB  = sm + 2*CS*128; // CS*8
    int b = blockIdx.x >> 6;
    int c = blockIdx.x & (NC - 1);
    int t = threadIdx.x;
    size_t base = ((size_t)b*LL + c*CS)*128;
    {
        const float4* dl4 = (const float4*)(dl + base);
        const float4* u4  = (const float4*)(u + base);
        for (int i = t; i < CS*32; i += 1024){
            ((float4*)sdl)[i] = dl4[i];
            ((float4*)su)[i]  = u4[i];
        }
    }
    int nb = (b*LL + c*CS)*8;
    if (t < CS*8) sB[t] = Bb[nb + t];
    __syncthreads();
    int d = t >> 3, n = t & 7;
    float Av = -__expf(A_log[d*8 + n]);
    float h = 0.f, P = 1.f;
#pragma unroll 8
    for (int l = 0; l < CS; l++){
        float de = sdl[l*128 + d];
        float uu = su[l*128 + d];
        float dA = __expf(de * Av);
        P *= dA;
        h = fmaf(dA, h, de * uu * sB[l*8 + n]);
    }
    int oidx = (b*NC + c)*1024 + t;
    Pg[oidx] = P;
    hEg[oidx] = h;
}

// ---------------------------------------------------------------- K5: chunk combine
__global__ void k_scanB(const float* __restrict__ Pg, const float* __restrict__ hEg,
                        float* __restrict__ h0g){
    int j = blockIdx.x * 1024 + threadIdx.x;
    int b = j >> 10, dn = j & 1023;
    float h = 0.f;
#pragma unroll 8
    for (int c = 0; c < NC; c++){
        int idx = (b*NC + c)*1024 + dn;
        h0g[idx] = h;
        h = fmaf(Pg[idx], h, hEg[idx]);
    }
}

// ---------------------------------------------------------------- K6: chunked scan, phase C
__global__ void k_scanC(const float* __restrict__ dl, const float* __restrict__ u,
                        const float* __restrict__ z, const float* __restrict__ Bb,
                        const float* __restrict__ Cb, const float* __restrict__ A_log,
                        const float* __restrict__ Dp, const float* __restrict__ h0g,
                        float* __restrict__ yp){
    extern __shared__ float sm[];
    float* sdl = sm;              // CS*128
    float* su  = sm + CS*128;     // CS*128
    float* sy  = sm + 2*CS*128;   // CS*128
    float* sB  = sm + 3*CS*128;   // CS*8
    float* sC  = sm + 3*CS*128 + CS*8; // CS*8
    int b = blockIdx.x >> 6;
    int c = blockIdx.x & (NC - 1);
    int t = threadIdx.x;
    size_t base = ((size_t)b*LL + c*CS)*128;
    {
        const float4* dl4 = (const float4*)(dl + base);
        const float4* u4  = (const float4*)(u + base);
        for (int i = t; i < CS*32; i += 1024){
            ((float4*)sdl)[i] = dl4[i];
            ((float4*)su)[i]  = u4[i];
        }
    }
    int nb = (b*LL + c*CS)*8;
    if (t < CS*8){
        sB[t] = Bb[nb + t];
        sC[t] = Cb[nb + t];
    }
    __syncthreads();
    int d = t >> 3, n = t & 7;
    float Av = -__expf(A_log[d*8 + n]);
    float h = h0g[(b*NC + c)*1024 + t];
#pragma unroll 4
    for (int l = 0; l < CS; l++){
        float de = sdl[l*128 + d];
        float uu = su[l*128 + d];
        float dA = __expf(de * Av);
        h = fmaf(dA, h, de * uu * sB[l*8 + n]);
        float y = h * sC[l*8 + n];
        y += __shfl_xor_sync(0xffffffffu, y, 1);
        y += __shfl_xor_sync(0xffffffffu, y, 2);
        y += __shfl_xor_sync(0xffffffffu, y, 4);
        if (n == 0) sy[l*128 + d] = y;
    }
    __syncthreads();
    {
        const float4* z4 = (const float4*)(z + base);
        float4* yp4 = (float4*)(yp + base);
        for (int i = t; i < CS*32; i += 1024){
            float4 sv = ((float4*)sy)[i];
            float4 uv = ((float4*)su)[i];
            float4 zv = z4[i];
            float4 Dv = *(const float4*)(Dp + ((i & 31) << 2));
            float4 r;
            r.x = fmaf(uv.x, Dv.x, sv.x) * siluf(zv.x);
            r.y = fmaf(uv.y, Dv.y, sv.y) * siluf(zv.y);
            r.z = fmaf(uv.z, Dv.z, sv.z) * siluf(zv.z);
            r.w = fmaf(uv.w, Dv.w, sv.w) * siluf(zv.w);
            yp4[i] = r;
        }
    }
}

// ---------------------------------------------------------------- K7: out_proj + LN + both gate GEMMs, all tf32 mma
// 256 thr (8 warps), 64 pixels/block.
#define GWS 33   // gate-weight smem stride
__global__ void __launch_bounds__(256, 1) k_final(const float* __restrict__ yp,
                        const float* __restrict__ woh, const float* __restrict__ wol,
                        const float* __restrict__ gamma, const float* __restrict__ beta,
                        const float* __restrict__ x,
                        const float* __restrict__ w2h, const float* __restrict__ w2l,
                        const float* __restrict__ wth, const float* __restrict__ wtl,
                        float* __restrict__ out){
    extern __shared__ float sm[];
    float* yt  = sm;                 // 64*132 tf32; aliased by fs
    float* wA  = sm + 64*132;        // 128*132 (wo hi); aliased by xt (64*132 tf32)
    float* wB  = wA + 128*132;       // 128*132 (wo lo); aliased by gate weights 4 x 128*GWS
    float* mt  = wB + 128*132;       // 64*132
    float* mus = mt + 64*132;        // 64
    float* rss = mus + 64;           // 64
    float* gb  = rss + 64;           // 256 (gamma, beta)
    float* fs  = yt;
    float* xt  = wA;
    float* s2h = wB;                 // 128*GWS
    float* s2l = wB + 128*GWS;
    float* sth = wB + 2*128*GWS;
    float* stl = wB + 3*128*GWS;
    int t = threadIdx.x, warp = t >> 5, lane = t & 31;
    int row_ = lane >> 2, col_ = lane & 3;
    int pix0 = blockIdx.x * 64;
    {
        const float4* y4 = (const float4*)(yp + (size_t)pix0*128);
        for (int i = t; i < 64*32; i += 256){
            int p = i >> 5, q = i & 31;
            float4 v = y4[i];
            v.x = __uint_as_float(f2tf(v.x)); v.y = __uint_as_float(f2tf(v.y));
            v.z = __uint_as_float(f2tf(v.z)); v.w = __uint_as_float(f2tf(v.w));
            *(float4*)(yt + p*132 + q*4) = v;
        }
        const float4* h4 = (const float4*)woh;
        const float4* l4 = (const float4*)wol;
        for (int i = t; i < 128*32; i += 256){
            int e = i >> 5, q = i & 31;
            *(float4*)(wA + e*132 + q*4) = h4[i];
            *(float4*)(wB + e*132 + q*4) = l4[i];
        }
        if (t < 128){ gb[t] = gamma[t]; gb[128 + t] = beta[t]; }
    }
    __syncthreads();
    // out_proj GEMM
    {
        int p0 = (warp >> 1) * 16;
        int e00 = (warp & 1) * 64;
        const float* yrA = yt + (p0 + row_)*132 + col_;
        const float* yrB = yrA + 8*132;
        float4 acc[8];
#pragma unroll
        for (int tt = 0; tt < 8; tt++) acc[tt] = make_float4(0.f,0.f,0.f,0.f);
#pragma unroll 4
        for (int k = 0; k < 16; k++){
            int k8 = k*8;
            uint32_t a0 = __float_as_uint(yrA[k8]);
            uint32_t a1 = __float_as_uint(yrB[k8]);
            uint32_t a2 = __float_as_uint(yrA[k8 + 4]);
            uint32_t a3 = __float_as_uint(yrB[k8 + 4]);
#pragma unroll
            for (int tt = 0; tt < 8; tt++){
                int e0 = e00 + tt*8;
                uint32_t bh0 = __float_as_uint(wA[(e0 + row_)*132 + k8 + col_]);
                uint32_t bh1 = __float_as_uint(wA[(e0 + row_)*132 + k8 + col_ + 4]);
                uint32_t bl0 = __float_as_uint(wB[(e0 + row_)*132 + k8 + col_]);
                uint32_t bl1 = __float_as_uint(wB[(e0 + row_)*132 + k8 + col_ + 4]);
                mma8(acc[tt], a0, a1, a2, a3, bh0, bh1);
                mma8(acc[tt], a0, a1, a2, a3, bl0, bl1);
            }
        }
        int pA = p0 + row_, pB = pA + 8;
#pragma unroll
        for (int tt = 0; tt < 8; tt++){
            int e = e00 + tt*8 + 2*col_;
            *(float2*)(mt + pA*132 + e) = make_float2(acc[tt].x, acc[tt].y);
            *(float2*)(mt + pB*132 + e) = make_float2(acc[tt].z, acc[tt].w);
        }
    }
    __syncthreads();   // wA/wB dead, mt valid
    // stage xt (tf32), gate weights; LN stats
    {
        const float4* x4 = (const float4*)(x + (size_t)pix0*128);
        for (int i = t; i < 64*32; i += 256){
            int p = i >> 5, q = i & 31;
            float4 v = x4[i];
            v.x = __uint_as_float(f2tf(v.x)); v.y = __uint_as_float(f2tf(v.y));
            v.z = __uint_as_float(f2tf(v.z)); v.w = __uint_as_float(f2tf(v.w));
            *(float4*)(xt + p*132 + q*4) = v;
        }
        for (int i = t; i < 128*32; i += 256){
            int r = i >> 5, q = i & 31;
            s2h[r*GWS + q] = w2h[i];
            s2l[r*GWS + q] = w2l[i];
            sth[r*GWS + q] = wth[i];
            stl[r*GWS + q] = wtl[i];
        }
    }
    for (int p = warp*8; p < warp*8 + 8; p++){
        float4 v = *(const float4*)(mt + p*132 + lane*4);
        float s = v.x + v.y + v.z + v.w;
        s += __shfl_xor_sync(0xffffffffu, s, 16);
        s += __shfl_xor_sync(0xffffffffu, s, 8);
        s += __shfl_xor_sync(0xffffffffu, s, 4);
        s += __shfl_xor_sync(0xffffffffu, s, 2);
        s += __shfl_xor_sync(0xffffffffu, s, 1);
        float mu = s * (1.f/128.f);
        float dx = v.x - mu, dy = v.y - mu, dz = v.z - mu, dww = v.w - mu;
        float q = dx*dx + dy*dy + dz*dz + dww*dww;
        q += __shfl_xor_sync(0xffffffffu, q, 16);
        q += __shfl_xor_sync(0xffffffffu, q, 8);
        q += __shfl_xor_sync(0xffffffffu, q, 4);
        q += __shfl_xor_sync(0xffffffffu, q, 2);
        q += __shfl_xor_sync(0xffffffffu, q, 1);
        if (lane == 0){
            mus[p] = mu;
            rss[p] = rsqrtf(q * (1.f/128.f) + 1e-5f);
        }
    }
    __syncthreads();
    int p0 = (warp >> 1) * 16;
    int chalf = warp & 1;
    int pA = p0 + row_, pB = pA + 8;
    // gate GEMM: x2 = grouped1x1(x, w2); fs = LN(mt)*silu(x2)  (tf32 into fs)
#pragma unroll 1
    for (int nt = 0; nt < 8; nt++){
        int c0 = chalf*64 + nt*8;
        int kb = (c0 >> 5) << 5;
        float4 acc = make_float4(0.f,0.f,0.f,0.f);
#pragma unroll
        for (int k = 0; k < 4; k++){
            int kc = kb + k*8;
            const float* xrA = xt + pA*132 + kc + col_;
            uint32_t a0 = __float_as_uint(xrA[0]);
            uint32_t a1 = __float_as_uint(xrA[8*132]);
            uint32_t a2 = __float_as_uint(xrA[4]);
            uint32_t a3 = __float_as_uint(xrA[8*132 + 4]);
            int wi = (c0 + row_)*GWS + k*8 + col_;
            mma8(acc, a0, a1, a2, a3, __float_as_uint(s2h[wi]), __float_as_uint(s2h[wi + 4]));
            mma8(acc, a0, a1, a2, a3, __float_as_uint(s2l[wi]), __float_as_uint(s2l[wi + 4]));
        }
        int cc = c0 + 2*col_;
        float g0 = gb[cc], g1 = gb[cc + 1], b0 = gb[128 + cc], b1 = gb[128 + cc + 1];
        float vx = fmaf((mt[pA*132 + cc]     - mus[pA]) * rss[pA], g0, b0) * siluf(acc.x);
        float vy = fmaf((mt[pA*132 + cc + 1] - mus[pA]) * rss[pA], g1, b1) * siluf(acc.y);
        float vz = fmaf((mt[pB*132 + cc]     - mus[pB]) * rss[pB], g0, b0) * siluf(acc.z);
        float vw = fmaf((mt[pB*132 + cc + 1] - mus[pB]) * rss[pB], g1, b1) * siluf(acc.w);
        *(float2*)(fs + pA*132 + cc) = make_float2(__uint_as_float(f2tf(vx)), __uint_as_float(f2tf(vy)));
        *(float2*)(fs + pB*132 + cc) = make_float2(__uint_as_float(f2tf(vz)), __uint_as_float(f2tf(vw)));
    }
    __syncwarp();
    // final grouped1x1: out = fs @ wout
#pragma unroll 1
    for (int nt = 0; nt < 8; nt++){
        int c0 = chalf*64 + nt*8;
        int kb = (c0 >> 5) << 5;
        float4 acc = make_float4(0.f,0.f,0.f,0.f);
#pragma unroll
        for (int k = 0; k < 4; k++){
            int kc = kb + k*8;
            const float* frA = fs + pA*132 + kc + col_;
            uint32_t a0 = __float_as_uint(frA[0]);
            uint32_t a1 = __float_as_uint(frA[8*132]);
            uint32_t a2 = __float_as_uint(frA[4]);
            uint32_t a3 = __float_as_uint(frA[8*132 + 4]);
            int wi = (c0 + row_)*GWS + k*8 + col_;
            mma8(acc, a0, a1, a2, a3, __float_as_uint(sth[wi]), __float_as_uint(sth[wi + 4]));
            mma8(acc, a0, a1, a2, a3, __float_as_uint(stl[wi]), __float_as_uint(stl[wi + 4]));
        }
        int cc = c0 + 2*col_;
        *(float2*)(out + (size_t)(pix0 + pA)*128 + cc) = make_float2(acc.x, acc.y);
        *(float2*)(out + (size_t)(pix0 + pB)*128 + cc) = make_float2(acc.z, acc.w);
    }
}

// ----------------------------------------------------------------
extern "C" void kernel_launch(void* const* d_in, const int* in_sizes, int n_in,
                              void* d_out, int out_size){
    const float* x        = (const float*)d_in[0];
    const float* w1       = (const float*)d_in[1];
    const float* dw       = (const float*)d_in[2];
    const float* in_proj  = (const float*)d_in[3];
    const float* conv1d_w = (const float*)d_in[4];
    const float* conv1d_b = (const float*)d_in[5];
    const float* x_proj_w = (const float*)d_in[6];
    const float* dt_proj_w= (const float*)d_in[7];
    const float* dt_proj_b= (const float*)d_in[8];
    const float* A_log    = (const float*)d_in[9];
    const float* D_param  = (const float*)d_in[10];
    const float* out_proj = (const float*)d_in[11];
    const float* gamma    = (const float*)d_in[12];
    const float* beta     = (const float*)d_in[13];
    const float* w2       = (const float*)d_in[14];
    const float* wout     = (const float*)d_in[15];
    float* out = (float*)d_out;

    float *xs, *u0, *z, *u, *dl, *Bm, *Cm, *yp, *Pg, *hE, *h0;
    float *wih, *wil, *woh, *wol, *w2h, *w2l, *wth, *wtl;
    cudaGetSymbolAddress((void**)&xs, g_xs);
    cudaGetSymbolAddress((void**)&u0, g_u0);
    cudaGetSymbolAddress((void**)&z,  g_z);
    cudaGetSymbolAddress((void**)&u,  g_u);
    cudaGetSymbolAddress((void**)&dl, g_dl);
    cudaGetSymbolAddress((void**)&Bm, g_Bm);
    cudaGetSymbolAddress((void**)&Cm, g_Cm);
    cudaGetSymbolAddress((void**)&yp, g_yp);
    cudaGetSymbolAddress((void**)&Pg, g_P);
    cudaGetSymbolAddress((void**)&hE, g_hE);
    cudaGetSymbolAddress((void**)&h0, g_h0);
    cudaGetSymbolAddress((void**)&wih, g_wih);
    cudaGetSymbolAddress((void**)&wil, g_wil);
    cudaGetSymbolAddress((void**)&woh, g_woh);
    cudaGetSymbolAddress((void**)&wol, g_wol);
    cudaGetSymbolAddress((void**)&w2h, g_w2h);
    cudaGetSymbolAddress((void**)&w2l, g_w2l);
    cudaGetSymbolAddress((void**)&wth, g_wth);
    cudaGetSymbolAddress((void**)&wtl, g_wtl);

    const int smemA = (2*CS*128 + CS*8) * sizeof(float);
    const int smemC = (3*CS*128 + 2*CS*8) * sizeof(float);
    const int smemG = (2*100*128 + 9*128) * sizeof(float);
    const int smemI = (128*132 + 2*64*132) * sizeof(float);
    const int smemF = (64*132 + 2*128*132 + 64*132 + 64 + 64 + 256) * sizeof(float);
    static int attr_done = 0;
    if (!attr_done){
        cudaFuncSetAttribute(k_scanA, cudaFuncAttributeMaxDynamicSharedMemorySize, smemA);
        cudaFuncSetAttribute(k_scanC, cudaFuncAttributeMaxDynamicSharedMemorySize, smemC);
        cudaFuncSetAttribute(k_g1dw,  cudaFuncAttributeMaxDynamicSharedMemorySize, smemG);
        cudaFuncSetAttribute(k_inproj, cudaFuncAttributeMaxDynamicSharedMemorySize, smemI);
        cudaFuncSetAttribute(k_final, cudaFuncAttributeMaxDynamicSharedMemorySize, smemF);
        attr_done = 1;
    }

    k_prep<<<224, 256>>>(in_proj, out_proj, w2, wout, wih, wil, woh, wol, w2h, w2l, wth, wtl);
    k_g1dw<<<512, 256, smemG>>>(x, w1, dw, xs);
    k_inproj<<<NPIX/128, 256, smemI>>>(xs, wih, wil, u0, z);
    k_cxp<<<NPIX/32, 256>>>(u0, conv1d_w, conv1d_b, x_proj_w, dt_proj_w, dt_proj_b, u, dl, Bm, Cm);
    k_scanA<<<BB*NC, 1024, smemA>>>(dl, u, Bm, A_log, Pg, hE);
    k_scanB<<<8, 1024>>>(Pg, hE, h0);
    k_scanC<<<BB*NC, 1024, smemC>>>(dl, u, z, Bm, Cm, A_log, D_param, h0, yp);
    k_final<<<NPIX/64, 256, smemF>>>(yp, woh, wol, gamma, beta, x, w2h, w2l, wth, wtl, out);
}

// round 6
// speedup vs baseline: 6.8638x; 1.0592x over previous
#include <cuda_runtime.h>
#include <math.h>
#include <stdint.h>

// Problem constants
#define BB 8
#define HH 64
#define WW 64
#define CC 128
#define DD 128
#define LL 4096            // H*W
#define NPIX (BB*LL)       // 32768
#define NS 8               // D_STATE
#define RR 8               // DT_RANK

#define CS 64              // chunk size (steps)
#define NC (LL/CS)         // 64 chunks per batch

// Scratch (device globals; no allocations allowed)
__device__ float g_xs[NPIX*DD];
__device__ float g_u0[NPIX*DD];
__device__ float g_z [NPIX*DD];
__device__ float g_u [NPIX*DD];
__device__ float g_dl[NPIX*DD];
__device__ float g_Bm[NPIX*NS];
__device__ float g_Cm[NPIX*NS];
__device__ float g_yp[NPIX*DD];
__device__ float g_P [BB*NC*1024];
__device__ float g_hE[BB*NC*1024];
__device__ float g_h0[BB*NC*1024];
// pre-split tf32 weights
__device__ float g_wih[256*128];
__device__ float g_wil[256*128];
__device__ float g_woh[128*128];
__device__ float g_wol[128*128];
__device__ float g_w2h[128*32];
__device__ float g_w2l[128*32];
__device__ float g_wth[128*32];
__device__ float g_wtl[128*32];
__device__ float g_wxh[24*128];
__device__ float g_wxl[24*128];

__device__ __forceinline__ float siluf(float v){ return v / (1.f + __expf(-v)); }

__device__ __forceinline__ uint32_t f2tf(float x){
    uint32_t r; asm("cvt.rna.tf32.f32 %0, %1;" : "=r"(r) : "f"(x)); return r;
}
__device__ __forceinline__ void mma8(float4& c, uint32_t a0, uint32_t a1, uint32_t a2, uint32_t a3,
                                     uint32_t b0, uint32_t b1){
    asm volatile("mma.sync.aligned.m16n8k8.row.col.f32.tf32.tf32.f32 "
                 "{%0,%1,%2,%3},{%4,%5,%6,%7},{%8,%9},{%0,%1,%2,%3};\n"
                 : "+f"(c.x), "+f"(c.y), "+f"(c.z), "+f"(c.w)
                 : "r"(a0), "r"(a1), "r"(a2), "r"(a3), "r"(b0), "r"(b1));
}

// ---------------------------------------------------------------- K0: weight split prep
// segments: in_proj 32768 | out_proj 16384 | w2 4096 | wout 4096 | x_proj 3072  = 60416
__global__ void k_prep(const float* __restrict__ wi, const float* __restrict__ wo,
                       const float* __restrict__ w2, const float* __restrict__ wt,
                       const float* __restrict__ wx,
                       float* wih, float* wil, float* woh, float* wol,
                       float* w2h, float* w2l, float* wth, float* wtl,
                       float* wxh, float* wxl){
    int i = blockIdx.x * 256 + threadIdx.x;
    if (i >= 60416) return;
    const float* src; float* dh; float* dlo; int off;
    if (i < 32768){ src = wi; dh = wih; dlo = wil; off = i; }
    else if (i < 49152){ src = wo; dh = woh; dlo = wol; off = i - 32768; }
    else if (i < 53248){ src = w2; dh = w2h; dlo = w2l; off = i - 49152; }
    else if (i < 57344){ src = wt; dh = wth; dlo = wtl; off = i - 53248; }
    else { src = wx; dh = wxh; dlo = wxl; off = i - 57344; }
    float v = src[off];
    float h = __uint_as_float(f2tf(v));
    dh[off] = h; dlo[off] = v - h;
}

// ---------------------------------------------------------------- K1: fused grouped1x1 + depthwise3x3 + silu
__global__ void __launch_bounds__(256, 1) k_g1dw(const float* __restrict__ x,
                       const float* __restrict__ w1, const float* __restrict__ dw,
                       float* __restrict__ xs){
    extern __shared__ float sm[];
    float* xh  = sm;              // 100*128
    float* t1s = sm + 100*128;    // 100*128
    float* dws = t1s + 100*128;   // 9*128
    int b = blockIdx.x >> 6;
    int tile = blockIdx.x & 63;
    int ty0 = (tile >> 3) * 8, tx0 = (tile & 7) * 8;
    int t = threadIdx.x;
    for (int i = t; i < 9*32; i += 256) ((float4*)dws)[i] = ((const float4*)dw)[i];
    for (int i = t; i < 100*32; i += 256){
        int p = i >> 5, q = i & 31;
        int hy = ty0 + p/10 - 1, hx = tx0 + (p - (p/10)*10) - 1;
        float4 v = make_float4(0.f,0.f,0.f,0.f);
        if (hy >= 0 && hy < 64 && hx >= 0 && hx < 64)
            v = ((const float4*)x)[(size_t)((b*64 + hy)*64 + hx)*32 + q];
        ((float4*)xh)[p*32 + q] = v;
    }
    __syncthreads();
    {
        int c = t & 127, pp = t >> 7;
        int g = c >> 5;
        float4 wr[8];
#pragma unroll
        for (int i = 0; i < 8; i++) wr[i] = ((const float4*)(w1 + c*32))[i];
#pragma unroll 1
        for (int it = 0; it < 50; it++){
            int p = it*2 + pp;
            const float* xr = xh + p*128 + g*32;
            float a = 0.f;
#pragma unroll
            for (int i = 0; i < 8; i++){
                float4 xv = *(const float4*)(xr + i*4);
                a = fmaf(wr[i].x, xv.x, a); a = fmaf(wr[i].y, xv.y, a);
                a = fmaf(wr[i].z, xv.z, a); a = fmaf(wr[i].w, xv.w, a);
            }
            t1s[p*128 + c] = a;
        }
    }
    __syncthreads();
    {
        int d4 = t & 31, pp = t >> 5;
        int d = d4 << 2;
#pragma unroll 1
        for (int it = 0; it < 8; it++){
            int p = pp*8 + it;
            int py = p >> 3, px = p & 7;
            int hr = (py + 1)*10 + px + 1;
            float4 acc = make_float4(0.f,0.f,0.f,0.f);
#pragma unroll
            for (int ky = 0; ky < 3; ky++){
#pragma unroll
                for (int kx = 0; kx < 3; kx++){
                    float4 tv = *(const float4*)(t1s + (hr + (ky-1)*10 + (kx-1))*128 + d);
                    float4 wv = *(const float4*)(dws + (ky*3 + kx)*128 + d);
                    acc.x = fmaf(tv.x, wv.x, acc.x); acc.y = fmaf(tv.y, wv.y, acc.y);
                    acc.z = fmaf(tv.z, wv.z, acc.z); acc.w = fmaf(tv.w, wv.w, acc.w);
                }
            }
            float4 r; r.x = siluf(acc.x); r.y = siluf(acc.y); r.z = siluf(acc.z); r.w = siluf(acc.w);
            *(float4*)(xs + (size_t)((b*64 + ty0 + py)*64 + tx0 + px)*128 + d) = r;
        }
    }
}

// ---------------------------------------------------------------- K2: in_proj via tf32 mma (pre-split weights)
__global__ void __launch_bounds__(256, 1) k_inproj(const float* __restrict__ xs,
                       const float* __restrict__ wih, const float* __restrict__ wil,
                       float* __restrict__ ub, float* __restrict__ zb){
    extern __shared__ float sm[];
    float* xt  = sm;             // 128*132
    float* whs = sm + 128*132;   // 64*132
    float* wls = whs + 64*132;   // 64*132
    int tid = threadIdx.x;
    int pix0 = blockIdx.x * 128;
    {
        const float4* xs4 = (const float4*)(xs + (size_t)pix0*128);
        for (int i = tid; i < 128*32; i += 256){
            int p = i >> 5, q = i & 31;
            float4 v = xs4[i];
            v.x = __uint_as_float(f2tf(v.x)); v.y = __uint_as_float(f2tf(v.y));
            v.z = __uint_as_float(f2tf(v.z)); v.w = __uint_as_float(f2tf(v.w));
            *(float4*)(xt + p*132 + q*4) = v;
        }
    }
    int warp = tid >> 5, lane = tid & 31;
    int row_ = lane >> 2, col_ = lane & 3;
    int p0 = warp * 16;
    const float* xrA = xt + (p0 + row_)*132 + col_;
    const float* xrB = xrA + 8*132;
#pragma unroll 1
    for (int g = 0; g < 4; g++){
        __syncthreads();
        {
            const float4* h4 = (const float4*)(wih + g*64*128);
            const float4* l4 = (const float4*)(wil + g*64*128);
            for (int i = tid; i < 64*32; i += 256){
                int r = i >> 5, q = i & 31;
                *(float4*)(whs + r*132 + q*4) = h4[i];
                *(float4*)(wls + r*132 + q*4) = l4[i];
            }
        }
        __syncthreads();
        float4 acc[8];
#pragma unroll
        for (int t = 0; t < 8; t++) acc[t] = make_float4(0.f,0.f,0.f,0.f);
#pragma unroll 4
        for (int k = 0; k < 16; k++){
            int k8 = k*8;
            uint32_t a0 = __float_as_uint(xrA[k8]);
            uint32_t a1 = __float_as_uint(xrB[k8]);
            uint32_t a2 = __float_as_uint(xrA[k8 + 4]);
            uint32_t a3 = __float_as_uint(xrB[k8 + 4]);
#pragma unroll
            for (int t = 0; t < 8; t++){
                int lt = t*8;
                uint32_t bh0 = __float_as_uint(whs[(lt + row_)*132 + k8 + col_]);
                uint32_t bh1 = __float_as_uint(whs[(lt + row_)*132 + k8 + col_ + 4]);
                uint32_t bl0 = __float_as_uint(wls[(lt + row_)*132 + k8 + col_]);
                uint32_t bl1 = __float_as_uint(wls[(lt + row_)*132 + k8 + col_ + 4]);
                mma8(acc[t], a0, a1, a2, a3, bh0, bh1);
                mma8(acc[t], a0, a1, a2, a3, bl0, bl1);
            }
        }
        int pixA = pix0 + p0 + row_;
        int pixB = pixA + 8;
#pragma unroll
        for (int t = 0; t < 8; t++){
            int e0 = g*64 + t*8 + 2*col_;
            float* base = (g < 2) ? (ub + e0) : (zb + e0 - 128);
            *(float2*)(base + (size_t)pixA*128) = make_float2(acc[t].x, acc[t].y);
            *(float2*)(base + (size_t)pixB*128) = make_float2(acc[t].z, acc[t].w);
        }
    }
}

// ---------------------------------------------------------------- K3: fused conv1d + x_proj(mma) + dt_proj + softplus
// 256 thr, 32 pixels/block.
#define XDS 26
__global__ void __launch_bounds__(256, 2) k_cxp(const float* __restrict__ u0,
                        const float* __restrict__ cw, const float* __restrict__ cb,
                        const float* __restrict__ wxh, const float* __restrict__ wxl,
                        const float* __restrict__ dtw, const float* __restrict__ dtb,
                        float* __restrict__ ug,
                        float* __restrict__ dl, float* __restrict__ Bb, float* __restrict__ Cb){
    extern __shared__ float sm[];
    float* u0s = sm;                 // 34*128
    float* uh  = u0s + 34*128;       // 32*132
    float* ul  = uh + 32*132;        // 32*132
    float* sxh = ul + 32*132;        // 24*132
    float* sxl = sxh + 24*132;       // 24*132
    float* xd  = sxl + 24*132;       // 32*XDS
    int pix0 = blockIdx.x * 32;
    int l0 = pix0 & (LL - 1);
    int t = threadIdx.x, warp = t >> 5, lane = t & 31;
    {
        const float4* u4 = (const float4*)(u0 + ((size_t)pix0 - 2)*128);
        for (int i = t; i < 34*32; i += 256){
            int p = i >> 5;
            float4 v = make_float4(0.f,0.f,0.f,0.f);
            if (!(l0 == 0 && p < 2)) v = u4[i];
            ((float4*)u0s)[i] = v;
        }
        const float4* h4 = (const float4*)wxh;
        const float4* l4 = (const float4*)wxl;
        for (int i = t; i < 24*32; i += 256){
            int r = i >> 5, q = i & 31;
            *(float4*)(sxh + r*132 + q*4) = h4[i];
            *(float4*)(sxl + r*132 + q*4) = l4[i];
        }
    }
    __syncthreads();
    // causal conv1d + silu -> uh/ul (tf32 split, smem) + ug (global fp32)
    {
        int d = t & 127, ph = t >> 7;
        float w0 = cw[d*3], w1c = cw[d*3 + 1], w2c = cw[d*3 + 2];
        float bias = cb[d];
#pragma unroll
        for (int p = ph*16; p < ph*16 + 16; p++){
            float a = fmaf(w2c, u0s[(p + 2)*128 + d],
                      fmaf(w1c, u0s[(p + 1)*128 + d],
                      fmaf(w0,  u0s[p*128 + d], bias)));
            a = siluf(a);
            ug[(size_t)(pix0 + p)*128 + d] = a;
            float hi = __uint_as_float(f2tf(a));
            uh[p*132 + d] = hi;
            ul[p*132 + d] = a - hi;
        }
    }
    __syncthreads();
    // x_dbl = u @ x_proj_w^T via mma; 6 warp-tiles (2 M x 3 N)
    if (warp < 6){
        int m0 = (warp & 1) * 16;
        int n0 = (warp >> 1) * 8;
        int row_ = lane >> 2, col_ = lane & 3;
        const float* ahA = uh + (m0 + row_)*132 + col_;
        const float* ahB = ahA + 8*132;
        const float* alA = ul + (m0 + row_)*132 + col_;
        const float* alB = alA + 8*132;
        float4 acc = make_float4(0.f,0.f,0.f,0.f);
#pragma unroll 4
        for (int k = 0; k < 16; k++){
            int k8 = k*8;
            uint32_t h0 = __float_as_uint(ahA[k8]);
            uint32_t h1 = __float_as_uint(ahB[k8]);
            uint32_t h2 = __float_as_uint(ahA[k8 + 4]);
            uint32_t h3 = __float_as_uint(ahB[k8 + 4]);
            uint32_t l0_ = __float_as_uint(alA[k8]);
            uint32_t l1 = __float_as_uint(alB[k8]);
            uint32_t l2 = __float_as_uint(alA[k8 + 4]);
            uint32_t l3 = __float_as_uint(alB[k8 + 4]);
            uint32_t bh0 = __float_as_uint(sxh[(n0 + row_)*132 + k8 + col_]);
            uint32_t bh1 = __float_as_uint(sxh[(n0 + row_)*132 + k8 + col_ + 4]);
            uint32_t bl0 = __float_as_uint(sxl[(n0 + row_)*132 + k8 + col_]);
            uint32_t bl1 = __float_as_uint(sxl[(n0 + row_)*132 + k8 + col_ + 4]);
            mma8(acc, h0, h1, h2, h3, bh0, bh1);
            mma8(acc, h0, h1, h2, h3, bl0, bl1);
            mma8(acc, l0_, l1, l2, l3, bh0, bh1);
        }
        int pA = m0 + row_, pB = pA + 8;
        int cc = n0 + 2*col_;
        *(float2*)(xd + pA*XDS + cc) = make_float2(acc.x, acc.y);
        *(float2*)(xd + pB*XDS + cc) = make_float2(acc.z, acc.w);
    }
    __syncthreads();
    // dt_proj + softplus
    {
        int d = t & 127, ph = t >> 7;
        float4 wa = ((const float4*)(dtw + d*8))[0];
        float4 wb = ((const float4*)(dtw + d*8))[1];
        float bias = dtb[d];
#pragma unroll
        for (int p = ph*16; p < ph*16 + 16; p++){
            const float* xr = xd + p*XDS;
            float a = bias;
            a = fmaf(xr[0], wa.x, a); a = fmaf(xr[1], wa.y, a);
            a = fmaf(xr[2], wa.z, a); a = fmaf(xr[3], wa.w, a);
            a = fmaf(xr[4], wb.x, a); a = fmaf(xr[5], wb.y, a);
            a = fmaf(xr[6], wb.z, a); a = fmaf(xr[7], wb.w, a);
            float sp = (a > 20.f) ? a : log1pf(__expf(a));
            dl[(size_t)(pix0 + p)*128 + d] = sp;
        }
    }
    {
        int p = t >> 3, n = t & 7;
        Bb[(pix0 + p)*8 + n] = xd[p*XDS + 8 + n];
        Cb[(pix0 + p)*8 + n] = xd[p*XDS + 16 + n];
    }
}

// ---------------------------------------------------------------- K4: chunked scan, phase A
__global__ void k_scanA(const float* __restrict__ dl, const float* __restrict__ u,
                        const float* __restrict__ Bb, const float* __restrict__ A_log,
                        float* __restrict__ Pg, float* __restrict__ hEg){
    extern __shared__ float sm[];
    float* sdl = sm;            // CS*128
    float* su  = sm + CS*128;   // CS*128
    float* sB  = sm + 2*CS*128; // CS*8
    int b = blockIdx.x >> 6;
    int c = blockIdx.x & (NC - 1);
    int t = threadIdx.x;
    size_t base = ((size_t)b*LL + c*CS)*128;
    {
        const float4* dl4 = (const float4*)(dl + base);
        const float4* u4  = (const float4*)(u + base);
        for (int i = t; i < CS*32; i += 1024){
            ((float4*)sdl)[i] = dl4[i];
            ((float4*)su)[i]  = u4[i];
        }
    }
    int nb = (b*LL + c*CS)*8;
    if (t < CS*8) sB[t] = Bb[nb + t];
    __syncthreads();
    int d = t >> 3, n = t & 7;
    float Av = -__expf(A_log[d*8 + n]);
    float h = 0.f, P = 1.f;
#pragma unroll 8
    for (int l = 0; l < CS; l++){
        float de = sdl[l*128 + d];
        float uu = su[l*128 + d];
        float dA = __expf(de * Av);
        P *= dA;
        h = fmaf(dA, h, de * uu * sB[l*8 + n]);
    }
    int oidx = (b*NC + c)*1024 + t;
    Pg[oidx] = P;
    hEg[oidx] = h;
}

// ---------------------------------------------------------------- K5: chunk combine
__global__ void k_scanB(const float* __restrict__ Pg, const float* __restrict__ hEg,
                        float* __restrict__ h0g){
    int j = blockIdx.x * 128 + threadIdx.x;
    int b = j >> 10, dn = j & 1023;
    float h = 0.f;
#pragma unroll 8
    for (int c = 0; c < NC; c++){
        int idx = (b*NC + c)*1024 + dn;
        h0g[idx] = h;
        h = fmaf(Pg[idx], h, hEg[idx]);
    }
}

// ---------------------------------------------------------------- K6: chunked scan, phase C
__global__ void k_scanC(const float* __restrict__ dl, const float* __restrict__ u,
                        const float* __restrict__ z, const float* __restrict__ Bb,
                        const float* __restrict__ Cb, const float* __restrict__ A_log,
                        const float* __restrict__ Dp, const float* __restrict__ h0g,
                        float* __restrict__ yp){
    extern __shared__ float sm[];
    float* sdl = sm;              // CS*128
    float* su  = sm + CS*128;     // CS*128
    float* sy  = sm + 2*CS*128;   // CS*128
    float* sB  = sm + 3*CS*128;   // CS*8
    float* sC  = sm + 3*CS*128 + CS*8; // CS*8
    int b = blockIdx.x >> 6;
    int c = blockIdx.x & (NC - 1);
    int t = threadIdx.x;
    size_t base = ((size_t)b*LL + c*CS)*128;
    {
        const float4* dl4 = (const float4*)(dl + base);
        const float4* u4  = (const float4*)(u + base);
        for (int i = t; i < CS*32; i += 1024){
            ((float4*)sdl)[i] = dl4[i];
            ((float4*)su)[i]  = u4[i];
        }
    }
    int nb = (b*LL + c*CS)*8;
    if (t < CS*8){
        sB[t] = Bb[nb + t];
        sC[t] = Cb[nb + t];
    }
    __syncthreads();
    int d = t >> 3, n = t & 7;
    float Av = -__expf(A_log[d*8 + n]);
    float h = h0g[(b*NC + c)*1024 + t];
#pragma unroll 4
    for (int l = 0; l < CS; l++){
        float de = sdl[l*128 + d];
        float uu = su[l*128 + d];
        float dA = __expf(de * Av);
        h = fmaf(dA, h, de * uu * sB[l*8 + n]);
        float y = h * sC[l*8 + n];
        y += __shfl_xor_sync(0xffffffffu, y, 1);
        y += __shfl_xor_sync(0xffffffffu, y, 2);
        y += __shfl_xor_sync(0xffffffffu, y, 4);
        if (n == 0) sy[l*128 + d] = y;
    }
    __syncthreads();
    {
        const float4* z4 = (const float4*)(z + base);
        float4* yp4 = (float4*)(yp + base);
        for (int i = t; i < CS*32; i += 1024){
            float4 sv = ((float4*)sy)[i];
            float4 uv = ((float4*)su)[i];
            float4 zv = z4[i];
            float4 Dv = *(const float4*)(Dp + ((i & 31) << 2));
            float4 r;
            r.x = fmaf(uv.x, Dv.x, sv.x) * siluf(zv.x);
            r.y = fmaf(uv.y, Dv.y, sv.y) * siluf(zv.y);
            r.z = fmaf(uv.z, Dv.z, sv.z) * siluf(zv.z);
            r.w = fmaf(uv.w, Dv.w, sv.w) * siluf(zv.w);
            yp4[i] = r;
        }
    }
}

// ---------------------------------------------------------------- K7: out_proj + LN + both gate GEMMs, all tf32 mma
#define GWS 33
__global__ void __launch_bounds__(256, 1) k_final(const float* __restrict__ yp,
                        const float* __restrict__ woh, const float* __restrict__ wol,
                        const float* __restrict__ gamma, const float* __restrict__ beta,
                        const float* __restrict__ x,
                        const float* __restrict__ w2h, const float* __restrict__ w2l,
                        const float* __restrict__ wth, const float* __restrict__ wtl,
                        float* __restrict__ out){
    extern __shared__ float sm[];
    float* yt  = sm;                 // 64*132 tf32; aliased by fs
    float* wA  = sm + 64*132;        // 128*132 (wo hi); aliased by xt (64*132 tf32)
    float* wB  = wA + 128*132;       // 128*132 (wo lo); aliased by gate weights 4 x 128*GWS
    float* mt  = wB + 128*132;       // 64*132
    float* mus = mt + 64*132;        // 64
    float* rss = mus + 64;           // 64
    float* gb  = rss + 64;           // 256
    float* fs  = yt;
    float* xt  = wA;
    float* s2h = wB;
    float* s2l = wB + 128*GWS;
    float* sth = wB + 2*128*GWS;
    float* stl = wB + 3*128*GWS;
    int t = threadIdx.x, warp = t >> 5, lane = t & 31;
    int row_ = lane >> 2, col_ = lane & 3;
    int pix0 = blockIdx.x * 64;
    {
        const float4* y4 = (const float4*)(yp + (size_t)pix0*128);
        for (int i = t; i < 64*32; i += 256){
            int p = i >> 5, q = i & 31;
            float4 v = y4[i];
            v.x = __uint_as_float(f2tf(v.x)); v.y = __uint_as_float(f2tf(v.y));
            v.z = __uint_as_float(f2tf(v.z)); v.w = __uint_as_float(f2tf(v.w));
            *(float4*)(yt + p*132 + q*4) = v;
        }
        const float4* h4 = (const float4*)woh;
        const float4* l4 = (const float4*)wol;
        for (int i = t; i < 128*32; i += 256){
            int e = i >> 5, q = i & 31;
            *(float4*)(wA + e*132 + q*4) = h4[i];
            *(float4*)(wB + e*132 + q*4) = l4[i];
        }
        if (t < 128){ gb[t] = gamma[t]; gb[128 + t] = beta[t]; }
    }
    __syncthreads();
    {
        int p0 = (warp >> 1) * 16;
        int e00 = (warp & 1) * 64;
        const float* yrA = yt + (p0 + row_)*132 + col_;
        const float* yrB = yrA + 8*132;
        float4 acc[8];
#pragma unroll
        for (int tt = 0; tt < 8; tt++) acc[tt] = make_float4(0.f,0.f,0.f,0.f);
#pragma unroll 4
        for (int k = 0; k < 16; k++){
            int k8 = k*8;
            uint32_t a0 = __float_as_uint(yrA[k8]);
            uint32_t a1 = __float_as_uint(yrB[k8]);
            uint32_t a2 = __float_as_uint(yrA[k8 + 4]);
            uint32_t a3 = __float_as_uint(yrB[k8 + 4]);
#pragma unroll
            for (int tt = 0; tt < 8; tt++){
                int e0 = e00 + tt*8;
                uint32_t bh0 = __float_as_uint(wA[(e0 + row_)*132 + k8 + col_]);
                uint32_t bh1 = __float_as_uint(wA[(e0 + row_)*132 + k8 + col_ + 4]);
                uint32_t bl0 = __float_as_uint(wB[(e0 + row_)*132 + k8 + col_]);
                uint32_t bl1 = __float_as_uint(wB[(e0 + row_)*132 + k8 + col_ + 4]);
                mma8(acc[tt], a0, a1, a2, a3, bh0, bh1);
                mma8(acc[tt], a0, a1, a2, a3, bl0, bl1);
            }
        }
        int pA = p0 + row_, pB = pA + 8;
#pragma unroll
        for (int tt = 0; tt < 8; tt++){
            int e = e00 + tt*8 + 2*col_;
            *(float2*)(mt + pA*132 + e) = make_float2(acc[tt].x, acc[tt].y);
            *(float2*)(mt + pB*132 + e) = make_float2(acc[tt].z, acc[tt].w);
        }
    }
    __syncthreads();
    {
        const float4* x4 = (const float4*)(x + (size_t)pix0*128);
        for (int i = t; i < 64*32; i += 256){
            int p = i >> 5, q = i & 31;
            float4 v = x4[i];
            v.x = __uint_as_float(f2tf(v.x)); v.y = __uint_as_float(f2tf(v.y));
            v.z = __uint_as_float(f2tf(v.z)); v.w = __uint_as_float(f2tf(v.w));
            *(float4*)(xt + p*132 + q*4) = v;
        }
        for (int i = t; i < 128*32; i += 256){
            int r = i >> 5, q = i & 31;
            s2h[r*GWS + q] = w2h[i];
            s2l[r*GWS + q] = w2l[i];
            sth[r*GWS + q] = wth[i];
            stl[r*GWS + q] = wtl[i];
        }
    }
    for (int p = warp*8; p < warp*8 + 8; p++){
        float4 v = *(const float4*)(mt + p*132 + lane*4);
        float s = v.x + v.y + v.z + v.w;
        s += __shfl_xor_sync(0xffffffffu, s, 16);
        s += __shfl_xor_sync(0xffffffffu, s, 8);
        s += __shfl_xor_sync(0xffffffffu, s, 4);
        s += __shfl_xor_sync(0xffffffffu, s, 2);
        s += __shfl_xor_sync(0xffffffffu, s, 1);
        float mu = s * (1.f/128.f);
        float dx = v.x - mu, dy = v.y - mu, dz = v.z - mu, dww = v.w - mu;
        float q = dx*dx + dy*dy + dz*dz + dww*dww;
        q += __shfl_xor_sync(0xffffffffu, q, 16);
        q += __shfl_xor_sync(0xffffffffu, q, 8);
        q += __shfl_xor_sync(0xffffffffu, q, 4);
        q += __shfl_xor_sync(0xffffffffu, q, 2);
        q += __shfl_xor_sync(0xffffffffu, q, 1);
        if (lane == 0){
            mus[p] = mu;
            rss[p] = rsqrtf(q * (1.f/128.f) + 1e-5f);
        }
    }
    __syncthreads();
    int p0 = (warp >> 1) * 16;
    int chalf = warp & 1;
    int pA = p0 + row_, pB = pA + 8;
#pragma unroll 1
    for (int nt = 0; nt < 8; nt++){
        int c0 = chalf*64 + nt*8;
        int kb = (c0 >> 5) << 5;
        float4 acc = make_float4(0.f,0.f,0.f,0.f);
#pragma unroll
        for (int k = 0; k < 4; k++){
            int kc = kb + k*8;
            const float* xrA = xt + pA*132 + kc + col_;
            uint32_t a0 = __float_as_uint(xrA[0]);
            uint32_t a1 = __float_as_uint(xrA[8*132]);
            uint32_t a2 = __float_as_uint(xrA[4]);
            uint32_t a3 = __float_as_uint(xrA[8*132 + 4]);
            int wi = (c0 + row_)*GWS + k*8 + col_;
            mma8(acc, a0, a1, a2, a3, __float_as_uint(s2h[wi]), __float_as_uint(s2h[wi + 4]));
            mma8(acc, a0, a1, a2, a3, __float_as_uint(s2l[wi]), __float_as_uint(s2l[wi + 4]));
        }
        int cc = c0 + 2*col_;
        float g0 = gb[cc], g1 = gb[cc + 1], b0 = gb[128 + cc], b1 = gb[128 + cc + 1];
        float vx = fmaf((mt[pA*132 + cc]     - mus[pA]) * rss[pA], g0, b0) * siluf(acc.x);
        float vy = fmaf((mt[pA*132 + cc + 1] - mus[pA]) * rss[pA], g1, b1) * siluf(acc.y);
        float vz = fmaf((mt[pB*132 + cc]     - mus[pB]) * rss[pB], g0, b0) * siluf(acc.z);
        float vw = fmaf((mt[pB*132 + cc + 1] - mus[pB]) * rss[pB], g1, b1) * siluf(acc.w);
        *(float2*)(fs + pA*132 + cc) = make_float2(__uint_as_float(f2tf(vx)), __uint_as_float(f2tf(vy)));
        *(float2*)(fs + pB*132 + cc) = make_float2(__uint_as_float(f2tf(vz)), __uint_as_float(f2tf(vw)));
    }
    __syncwarp();
#pragma unroll 1
    for (int nt = 0; nt < 8; nt++){
        int c0 = chalf*64 + nt*8;
        int kb = (c0 >> 5) << 5;
        float4 acc = make_float4(0.f,0.f,0.f,0.f);
#pragma unroll
        for (int k = 0; k < 4; k++){
            int kc = kb + k*8;
            const float* frA = fs + pA*132 + kc + col_;
            uint32_t a0 = __float_as_uint(frA[0]);
            uint32_t a1 = __float_as_uint(frA[8*132]);
            uint32_t a2 = __float_as_uint(frA[4]);
            uint32_t a3 = __float_as_uint(frA[8*132 + 4]);
            int wi = (c0 + row_)*GWS + k*8 + col_;
            mma8(acc, a0, a1, a2, a3, __float_as_uint(sth[wi]), __float_as_uint(sth[wi + 4]));
            mma8(acc, a0, a1, a2, a3, __float_as_uint(stl[wi]), __float_as_uint(stl[wi + 4]));
        }
        int cc = c0 + 2*col_;
        *(float2*)(out + (size_t)(pix0 + pA)*128 + cc) = make_float2(acc.x, acc.y);
        *(float2*)(out + (size_t)(pix0 + pB)*128 + cc) = make_float2(acc.z, acc.w);
    }
}

// ----------------------------------------------------------------
extern "C" void kernel_launch(void* const* d_in, const int* in_sizes, int n_in,
                              void* d_out, int out_size){
    const float* x        = (const float*)d_in[0];
    const float* w1       = (const float*)d_in[1];
    const float* dw       = (const float*)d_in[2];
    const float* in_proj  = (const float*)d_in[3];
    const float* conv1d_w = (const float*)d_in[4];
    const float* conv1d_b = (const float*)d_in[5];
    const float* x_proj_w = (const float*)d_in[6];
    const float* dt_proj_w= (const float*)d_in[7];
    const float* dt_proj_b= (const float*)d_in[8];
    const float* A_log    = (const float*)d_in[9];
    const float* D_param  = (const float*)d_in[10];
    const float* out_proj = (const float*)d_in[11];
    const float* gamma    = (const float*)d_in[12];
    const float* beta     = (const float*)d_in[13];
    const float* w2       = (const float*)d_in[14];
    const float* wout     = (const float*)d_in[15];
    float* out = (float*)d_out;

    float *xs, *u0, *z, *u, *dl, *Bm, *Cm, *yp, *Pg, *hE, *h0;
    float *wih, *wil, *woh, *wol, *w2h, *w2l, *wth, *wtl, *wxh, *wxl;
    cudaGetSymbolAddress((void**)&xs, g_xs);
    cudaGetSymbolAddress((void**)&u0, g_u0);
    cudaGetSymbolAddress((void**)&z,  g_z);
    cudaGetSymbolAddress((void**)&u,  g_u);
    cudaGetSymbolAddress((void**)&dl, g_dl);
    cudaGetSymbolAddress((void**)&Bm, g_Bm);
    cudaGetSymbolAddress((void**)&Cm, g_Cm);
    cudaGetSymbolAddress((void**)&yp, g_yp);
    cudaGetSymbolAddress((void**)&Pg, g_P);
    cudaGetSymbolAddress((void**)&hE, g_hE);
    cudaGetSymbolAddress((void**)&h0, g_h0);
    cudaGetSymbolAddress((void**)&wih, g_wih);
    cudaGetSymbolAddress((void**)&wil, g_wil);
    cudaGetSymbolAddress((void**)&woh, g_woh);
    cudaGetSymbolAddress((void**)&wol, g_wol);
    cudaGetSymbolAddress((void**)&w2h, g_w2h);
    cudaGetSymbolAddress((void**)&w2l, g_w2l);
    cudaGetSymbolAddress((void**)&wth, g_wth);
    cudaGetSymbolAddress((void**)&wtl, g_wtl);
    cudaGetSymbolAddress((void**)&wxh, g_wxh);
    cudaGetSymbolAddress((void**)&wxl, g_wxl);

    const int smemA = (2*CS*128 + CS*8) * sizeof(float);
    const int smemC = (3*CS*128 + 2*CS*8) * sizeof(float);
    const int smemG = (2*100*128 + 9*128) * sizeof(float);
    const int smemI = (128*132 + 2*64*132) * sizeof(float);
    const int smemX = (34*128 + 2*32*132 + 2*24*132 + 32*XDS) * sizeof(float);
    const int smemF = (64*132 + 2*128*132 + 64*132 + 64 + 64 + 256) * sizeof(float);
    static int attr_done = 0;
    if (!attr_done){
        cudaFuncSetAttribute(k_scanA, cudaFuncAttributeMaxDynamicSharedMemorySize, smemA);
        cudaFuncSetAttribute(k_scanC, cudaFuncAttributeMaxDynamicSharedMemorySize, smemC);
        cudaFuncSetAttribute(k_g1dw,  cudaFuncAttributeMaxDynamicSharedMemorySize, smemG);
        cudaFuncSetAttribute(k_inproj, cudaFuncAttributeMaxDynamicSharedMemorySize, smemI);
        cudaFuncSetAttribute(k_cxp,   cudaFuncAttributeMaxDynamicSharedMemorySize, smemX);
        cudaFuncSetAttribute(k_final, cudaFuncAttributeMaxDynamicSharedMemorySize, smemF);
        attr_done = 1;
    }

    k_prep<<<236, 256>>>(in_proj, out_proj, w2, wout, x_proj_w,
                         wih, wil, woh, wol, w2h, w2l, wth, wtl, wxh, wxl);
    k_g1dw<<<512, 256, smemG>>>(x, w1, dw, xs);
    k_inproj<<<NPIX/128, 256, smemI>>>(xs, wih, wil, u0, z);
    k_cxp<<<NPIX/32, 256, smemX>>>(u0, conv1d_w, conv1d_b, wxh, wxl, dt_proj_w, dt_proj_b, u, dl, Bm, Cm);
    k_scanA<<<BB*NC, 1024, smemA>>>(dl, u, Bm, A_log, Pg, hE);
    k_scanB<<<64, 128>>>(Pg, hE, h0);
    k_scanC<<<BB*NC, 1024, smemC>>>(dl, u, z, Bm, Cm, A_log, D_param, h0, yp);
    k_final<<<NPIX/64, 256, smemF>>>(yp, woh, wol, gamma, beta, x, w2h, w2l, wth, wtl, out);
}

// round 7
// speedup vs baseline: 7.2232x; 1.0523x over previous
#include <cuda_runtime.h>
#include <math.h>
#include <stdint.h>

// Problem constants
#define BB 8
#define HH 64
#define WW 64
#define CC 128
#define DD 128
#define LL 4096            // H*W
#define NPIX (BB*LL)       // 32768
#define NS 8               // D_STATE
#define RR 8               // DT_RANK

#define CS 64              // chunk size (steps)
#define NC (LL/CS)         // 64 chunks per batch

// Scratch (device globals; no allocations allowed)
__device__ float g_t1[NPIX*DD];     // grouped1x1 intermediate
__device__ float g_xs[NPIX*DD];
__device__ float g_u0[NPIX*DD];
__device__ float g_z [NPIX*DD];
__device__ float g_u [NPIX*DD];
__device__ float g_dl[NPIX*DD];
__device__ float g_Bm[NPIX*NS];
__device__ float g_Cm[NPIX*NS];
__device__ float g_P [BB*NC*1024];
__device__ float g_hE[BB*NC*1024];
__device__ float g_h0[BB*NC*1024];
// pre-split tf32 weights
__device__ float g_wih[256*128];
__device__ float g_wil[256*128];
__device__ float g_woh[128*128];
__device__ float g_wol[128*128];
__device__ float g_w2h[128*32];
__device__ float g_w2l[128*32];
__device__ float g_wth[128*32];
__device__ float g_wtl[128*32];
__device__ float g_wxh[24*128];
__device__ float g_wxl[24*128];

__device__ __forceinline__ float siluf(float v){ return v / (1.f + __expf(-v)); }

__device__ __forceinline__ uint32_t f2tf(float x){
    uint32_t r; asm("cvt.rna.tf32.f32 %0, %1;" : "=r"(r) : "f"(x)); return r;
}
__device__ __forceinline__ void mma8(float4& c, uint32_t a0, uint32_t a1, uint32_t a2, uint32_t a3,
                                     uint32_t b0, uint32_t b1){
    asm volatile("mma.sync.aligned.m16n8k8.row.col.f32.tf32.tf32.f32 "
                 "{%0,%1,%2,%3},{%4,%5,%6,%7},{%8,%9},{%0,%1,%2,%3};\n"
                 : "+f"(c.x), "+f"(c.y), "+f"(c.z), "+f"(c.w)
                 : "r"(a0), "r"(a1), "r"(a2), "r"(a3), "r"(b0), "r"(b1));
}

// ---------------------------------------------------------------- K0: weight split prep
__global__ void k_prep(const float* __restrict__ wi, const float* __restrict__ wo,
                       const float* __restrict__ w2, const float* __restrict__ wt,
                       const float* __restrict__ wx,
                       float* wih, float* wil, float* woh, float* wol,
                       float* w2h, float* w2l, float* wth, float* wtl,
                       float* wxh, float* wxl){
    int i = blockIdx.x * 256 + threadIdx.x;
    if (i >= 60416) return;
    const float* src; float* dh; float* dlo; int off;
    if (i < 32768){ src = wi; dh = wih; dlo = wil; off = i; }
    else if (i < 49152){ src = wo; dh = woh; dlo = wol; off = i - 32768; }
    else if (i < 53248){ src = w2; dh = w2h; dlo = w2l; off = i - 49152; }
    else if (i < 57344){ src = wt; dh = wth; dlo = wtl; off = i - 53248; }
    else { src = wx; dh = wxh; dlo = wxl; off = i - 57344; }
    float v = src[off];
    float h = __uint_as_float(f2tf(v));
    dh[off] = h; dlo[off] = v - h;
}

// ---------------------------------------------------------------- K1: grouped 1x1 (round-4 proven version)
__global__ void __launch_bounds__(256) k_g1(const float* __restrict__ x,
                                            const float* __restrict__ w,
                                            float* __restrict__ out){
    __shared__ float xt[32*128];
    int pix0 = blockIdx.x * 32;
    const float4* x4 = (const float4*)(x + (size_t)pix0*128);
    for (int i = threadIdx.x; i < 32*32; i += 256) ((float4*)xt)[i] = x4[i];
    __syncthreads();
    int t = threadIdx.x;
    int c = t & 127, half = t >> 7;
    int g = c >> 5;
    float4 wr[8];
#pragma unroll
    for (int i = 0; i < 8; i++) wr[i] = ((const float4*)(w + c*32))[i];
    const float* xb = xt + (half*16)*128 + g*32;
    float* ob = out + ((size_t)pix0 + half*16)*128 + c;
#pragma unroll
    for (int p = 0; p < 16; p++){
        const float* xr = xb + p*128;
        float a = 0.f;
#pragma unroll
        for (int i = 0; i < 8; i++){
            float4 xv = *(const float4*)(xr + i*4);
            a = fmaf(wr[i].x, xv.x, a); a = fmaf(wr[i].y, xv.y, a);
            a = fmaf(wr[i].z, xv.z, a); a = fmaf(wr[i].w, xv.w, a);
        }
        ob[(size_t)p*128] = a;
    }
}

// ---------------------------------------------------------------- K2: depthwise 3x3 + silu (round-4 proven version)
__global__ void k_dw(const float* __restrict__ t1, const float* __restrict__ dw,
                     float* __restrict__ out){
    int idx = blockIdx.x * 256 + threadIdx.x;     // NPIX*32 total
    int d4 = idx & 31; int pix = idx >> 5;
    int wc = pix & 63; int h = (pix >> 6) & 63; int b = pix >> 12;
    int d = d4 << 2;
    float4 acc = make_float4(0.f, 0.f, 0.f, 0.f);
#pragma unroll
    for (int kh = 0; kh < 3; kh++){
        int hh = h + kh - 1; if (hh < 0 || hh >= 64) continue;
#pragma unroll
        for (int kw = 0; kw < 3; kw++){
            int ww = wc + kw - 1; if (ww < 0 || ww >= 64) continue;
            float4 tv = *(const float4*)(t1 + (((b*64 + hh)*64 + ww) << 7) + d);
            float4 wv = *(const float4*)(dw + (kh*3 + kw)*128 + d);
            acc.x = fmaf(tv.x, wv.x, acc.x); acc.y = fmaf(tv.y, wv.y, acc.y);
            acc.z = fmaf(tv.z, wv.z, acc.z); acc.w = fmaf(tv.w, wv.w, acc.w);
        }
    }
    float4 r; r.x = siluf(acc.x); r.y = siluf(acc.y); r.z = siluf(acc.z); r.w = siluf(acc.w);
    *(float4*)(out + (size_t)pix*128 + d) = r;
}

// ---------------------------------------------------------------- K3: in_proj via tf32 mma (pre-split weights)
__global__ void __launch_bounds__(256, 1) k_inproj(const float* __restrict__ xs,
                       const float* __restrict__ wih, const float* __restrict__ wil,
                       float* __restrict__ ub, float* __restrict__ zb){
    extern __shared__ float sm[];
    float* xt  = sm;             // 128*132
    float* whs = sm + 128*132;   // 64*132
    float* wls = whs + 64*132;   // 64*132
    int tid = threadIdx.x;
    int pix0 = blockIdx.x * 128;
    {
        const float4* xs4 = (const float4*)(xs + (size_t)pix0*128);
        for (int i = tid; i < 128*32; i += 256){
            int p = i >> 5, q = i & 31;
            float4 v = xs4[i];
            v.x = __uint_as_float(f2tf(v.x)); v.y = __uint_as_float(f2tf(v.y));
            v.z = __uint_as_float(f2tf(v.z)); v.w = __uint_as_float(f2tf(v.w));
            *(float4*)(xt + p*132 + q*4) = v;
        }
    }
    int warp = tid >> 5, lane = tid & 31;
    int row_ = lane >> 2, col_ = lane & 3;
    int p0 = warp * 16;
    const float* xrA = xt + (p0 + row_)*132 + col_;
    const float* xrB = xrA + 8*132;
#pragma unroll 1
    for (int g = 0; g < 4; g++){
        __syncthreads();
        {
            const float4* h4 = (const float4*)(wih + g*64*128);
            const float4* l4 = (const float4*)(wil + g*64*128);
            for (int i = tid; i < 64*32; i += 256){
                int r = i >> 5, q = i & 31;
                *(float4*)(whs + r*132 + q*4) = h4[i];
                *(float4*)(wls + r*132 + q*4) = l4[i];
            }
        }
        __syncthreads();
        float4 acc[8];
#pragma unroll
        for (int t = 0; t < 8; t++) acc[t] = make_float4(0.f,0.f,0.f,0.f);
#pragma unroll 4
        for (int k = 0; k < 16; k++){
            int k8 = k*8;
            uint32_t a0 = __float_as_uint(xrA[k8]);
            uint32_t a1 = __float_as_uint(xrB[k8]);
            uint32_t a2 = __float_as_uint(xrA[k8 + 4]);
            uint32_t a3 = __float_as_uint(xrB[k8 + 4]);
#pragma unroll
            for (int t = 0; t < 8; t++){
                int lt = t*8;
                uint32_t bh0 = __float_as_uint(whs[(lt + row_)*132 + k8 + col_]);
                uint32_t bh1 = __float_as_uint(whs[(lt + row_)*132 + k8 + col_ + 4]);
                uint32_t bl0 = __float_as_uint(wls[(lt + row_)*132 + k8 + col_]);
                uint32_t bl1 = __float_as_uint(wls[(lt + row_)*132 + k8 + col_ + 4]);
                mma8(acc[t], a0, a1, a2, a3, bh0, bh1);
                mma8(acc[t], a0, a1, a2, a3, bl0, bl1);
            }
        }
        int pixA = pix0 + p0 + row_;
        int pixB = pixA + 8;
#pragma unroll
        for (int t = 0; t < 8; t++){
            int e0 = g*64 + t*8 + 2*col_;
            float* base = (g < 2) ? (ub + e0) : (zb + e0 - 128);
            *(float2*)(base + (size_t)pixA*128) = make_float2(acc[t].x, acc[t].y);
            *(float2*)(base + (size_t)pixB*128) = make_float2(acc[t].z, acc[t].w);
        }
    }
}

// ---------------------------------------------------------------- K4: fused conv1d + x_proj(mma) + dt_proj + softplus
#define XDS 26
__global__ void __launch_bounds__(256, 2) k_cxp(const float* __restrict__ u0,
                        const float* __restrict__ cw, const float* __restrict__ cb,
                        const float* __restrict__ wxh, const float* __restrict__ wxl,
                        const float* __restrict__ dtw, const float* __restrict__ dtb,
                        float* __restrict__ ug,
                        float* __restrict__ dl, float* __restrict__ Bb, float* __restrict__ Cb){
    extern __shared__ float sm[];
    float* u0s = sm;                 // 34*128
    float* uh  = u0s + 34*128;       // 32*132
    float* ul  = uh + 32*132;        // 32*132
    float* sxh = ul + 32*132;        // 24*132
    float* sxl = sxh + 24*132;       // 24*132
    float* xd  = sxl + 24*132;       // 32*XDS
    int pix0 = blockIdx.x * 32;
    int l0 = pix0 & (LL - 1);
    int t = threadIdx.x, warp = t >> 5, lane = t & 31;
    {
        const float4* u4 = (const float4*)(u0 + ((size_t)pix0 - 2)*128);
        for (int i = t; i < 34*32; i += 256){
            int p = i >> 5;
            float4 v = make_float4(0.f,0.f,0.f,0.f);
            if (!(l0 == 0 && p < 2)) v = u4[i];
            ((float4*)u0s)[i] = v;
        }
        const float4* h4 = (const float4*)wxh;
        const float4* l4 = (const float4*)wxl;
        for (int i = t; i < 24*32; i += 256){
            int r = i >> 5, q = i & 31;
            *(float4*)(sxh + r*132 + q*4) = h4[i];
            *(float4*)(sxl + r*132 + q*4) = l4[i];
        }
    }
    __syncthreads();
    {
        int d = t & 127, ph = t >> 7;
        float w0 = cw[d*3], w1c = cw[d*3 + 1], w2c = cw[d*3 + 2];
        float bias = cb[d];
#pragma unroll 4
        for (int p = ph*16; p < ph*16 + 16; p++){
            float a = fmaf(w2c, u0s[(p + 2)*128 + d],
                      fmaf(w1c, u0s[(p + 1)*128 + d],
                      fmaf(w0,  u0s[p*128 + d], bias)));
            a = siluf(a);
            ug[(size_t)(pix0 + p)*128 + d] = a;
            float hi = __uint_as_float(f2tf(a));
            uh[p*132 + d] = hi;
            ul[p*132 + d] = a - hi;
        }
    }
    __syncthreads();
    if (warp < 6){
        int m0 = (warp & 1) * 16;
        int n0 = (warp >> 1) * 8;
        int row_ = lane >> 2, col_ = lane & 3;
        const float* ahA = uh + (m0 + row_)*132 + col_;
        const float* ahB = ahA + 8*132;
        const float* alA = ul + (m0 + row_)*132 + col_;
        const float* alB = alA + 8*132;
        float4 acc = make_float4(0.f,0.f,0.f,0.f);
#pragma unroll 2
        for (int k = 0; k < 16; k++){
            int k8 = k*8;
            uint32_t h0 = __float_as_uint(ahA[k8]);
            uint32_t h1 = __float_as_uint(ahB[k8]);
            uint32_t h2 = __float_as_uint(ahA[k8 + 4]);
            uint32_t h3 = __float_as_uint(ahB[k8 + 4]);
            uint32_t l0_ = __float_as_uint(alA[k8]);
            uint32_t l1 = __float_as_uint(alB[k8]);
            uint32_t l2 = __float_as_uint(alA[k8 + 4]);
            uint32_t l3 = __float_as_uint(alB[k8 + 4]);
            uint32_t bh0 = __float_as_uint(sxh[(n0 + row_)*132 + k8 + col_]);
            uint32_t bh1 = __float_as_uint(sxh[(n0 + row_)*132 + k8 + col_ + 4]);
            uint32_t bl0 = __float_as_uint(sxl[(n0 + row_)*132 + k8 + col_]);
            uint32_t bl1 = __float_as_uint(sxl[(n0 + row_)*132 + k8 + col_ + 4]);
            mma8(acc, h0, h1, h2, h3, bh0, bh1);
            mma8(acc, h0, h1, h2, h3, bl0, bl1);
            mma8(acc, l0_, l1, l2, l3, bh0, bh1);
        }
        int pA = m0 + row_, pB = pA + 8;
        int cc = n0 + 2*col_;
        *(float2*)(xd + pA*XDS + cc) = make_float2(acc.x, acc.y);
        *(float2*)(xd + pB*XDS + cc) = make_float2(acc.z, acc.w);
    }
    __syncthreads();
    {
        int d = t & 127, ph = t >> 7;
        float4 wa = ((const float4*)(dtw + d*8))[0];
        float4 wb = ((const float4*)(dtw + d*8))[1];
        float bias = dtb[d];
#pragma unroll 4
        for (int p = ph*16; p < ph*16 + 16; p++){
            const float* xr = xd + p*XDS;
            float a = bias;
            a = fmaf(xr[0], wa.x, a); a = fmaf(xr[1], wa.y, a);
            a = fmaf(xr[2], wa.z, a); a = fmaf(xr[3], wa.w, a);
            a = fmaf(xr[4], wb.x, a); a = fmaf(xr[5], wb.y, a);
            a = fmaf(xr[6], wb.z, a); a = fmaf(xr[7], wb.w, a);
            float sp = (a > 20.f) ? a : log1pf(__expf(a));
            dl[(size_t)(pix0 + p)*128 + d] = sp;
        }
    }
    {
        int p = t >> 3, n = t & 7;
        Bb[(pix0 + p)*8 + n] = xd[p*XDS + 8 + n];
        Cb[(pix0 + p)*8 + n] = xd[p*XDS + 16 + n];
    }
}

// ---------------------------------------------------------------- K5: chunked scan, phase A
__global__ void k_scanA(const float* __restrict__ dl, const float* __restrict__ u,
                        const float* __restrict__ Bb, const float* __restrict__ A_log,
                        float* __restrict__ Pg, float* __restrict__ hEg){
    extern __shared__ float sm[];
    float* sdl = sm;            // CS*128
    float* su  = sm + CS*128;   // CS*128
    float* sB  = sm + 2*CS*128; // CS*8
    int b = blockIdx.x >> 6;
    int c = blockIdx.x & (NC - 1);
    int t = threadIdx.x;
    size_t base = ((size_t)b*LL + c*CS)*128;
    {
        const float4* dl4 = (const float4*)(dl + base);
        const float4* u4  = (const float4*)(u + base);
        for (int i = t; i < CS*32; i += 1024){
            ((float4*)sdl)[i] = dl4[i];
            ((float4*)su)[i]  = u4[i];
        }
    }
    int nb = (b*LL + c*CS)*8;
    if (t < CS*8) sB[t] = Bb[nb + t];
    __syncthreads();
    int d = t >> 3, n = t & 7;
    float Av = -__expf(A_log[d*8 + n]);
    float h = 0.f, P = 1.f;
#pragma unroll 8
    for (int l = 0; l < CS; l++){
        float de = sdl[l*128 + d];
        float uu = su[l*128 + d];
        float dA = __expf(de * Av);
        P *= dA;
        h = fmaf(dA, h, de * uu * sB[l*8 + n]);
    }
    int oidx = (b*NC + c)*1024 + t;
    Pg[oidx] = P;
    hEg[oidx] = h;
}

// ---------------------------------------------------------------- K6: chunk combine
__global__ void k_scanB(const float* __restrict__ Pg, const float* __restrict__ hEg,
                        float* __restrict__ h0g){
    int j = blockIdx.x * 128 + threadIdx.x;
    int b = j >> 10, dn = j & 1023;
    float h = 0.f;
#pragma unroll 8
    for (int c = 0; c < NC; c++){
        int idx = (b*NC + c)*1024 + dn;
        h0g[idx] = h;
        h = fmaf(Pg[idx], h, hEg[idx]);
    }
}

// ---------------------------------------------------------------- K7: MEGA2 = scanC + out_proj + LN + gate GEMMs
// 512 thr, one (b, chunk=64px) per block. smem 206KB with aliasing.
#define GWS 33
__global__ void __launch_bounds__(512, 1) k_mega2(
        const float* __restrict__ dl, const float* __restrict__ u,
        const float* __restrict__ z, const float* __restrict__ Bb,
        const float* __restrict__ Cb, const float* __restrict__ A_log,
        const float* __restrict__ Dp, const float* __restrict__ h0g,
        const float* __restrict__ woh, const float* __restrict__ wol,
        const float* __restrict__ gamma, const float* __restrict__ beta,
        const float* __restrict__ x,
        const float* __restrict__ w2h, const float* __restrict__ w2l,
        const float* __restrict__ wth, const float* __restrict__ wtl,
        float* __restrict__ out){
    extern __shared__ float sm[];
    float* r1 = sm;               // 17408 fl: sdl|su|sB|sC ; later wA(16896); later xt(8448)
    float* r2 = sm + 17408;       // 16896 fl: wB (wol); later gate weights 4x128*GWS
    float* r3 = r2 + 16896;       // 8448 fl: sy raw y -> yt (tf32) -> fs
    float* mt = r3 + 8448;        // 8448
    float* mus = mt + 8448;       // 64
    float* rss = mus + 64;        // 64
    float* gb  = rss + 64;        // 256
    float* sdl = r1;
    float* su  = r1 + 8192;
    float* sB  = r1 + 16384;
    float* sC  = r1 + 16896;
    float* wA  = r1;
    float* xt  = r1;
    float* s2h = r2;
    float* s2l = r2 + 128*GWS;
    float* sth = r2 + 2*128*GWS;
    float* stl = r2 + 3*128*GWS;
    int b = blockIdx.x >> 6;
    int c = blockIdx.x & (NC - 1);
    int t = threadIdx.x, warp = t >> 5, lane = t & 31;
    int row_ = lane >> 2, col_ = lane & 3;
    int pix0 = b*LL + c*CS;
    size_t base = (size_t)pix0*128;
    // phase 1: stage scan inputs + preload wB (wol) + gamma/beta
    {
        const float4* dl4 = (const float4*)(dl + base);
        const float4* u4  = (const float4*)(u + base);
        for (int i = t; i < CS*32; i += 512){
            ((float4*)sdl)[i] = dl4[i];
            ((float4*)su)[i]  = u4[i];
        }
        int nb = pix0*8;
        if (t < CS*8){ sB[t] = Bb[nb + t]; sC[t] = Cb[nb + t]; }
        const float4* l4 = (const float4*)wol;
        for (int i = t; i < 128*32; i += 512){
            int r = i >> 5, q = i & 31;
            *(float4*)(r2 + r*132 + q*4) = l4[i];
        }
        if (t < 128){ gb[t] = gamma[t]; gb[128 + t] = beta[t]; }
    }
    __syncthreads();
    // phase 2: scan (2 states per thread: d = t>>2, n = 2*(t&3), 2*(t&3)+1)
    {
        int d = t >> 2, np = (t & 3) * 2;
        float Av0 = -__expf(A_log[d*8 + np]);
        float Av1 = -__expf(A_log[d*8 + np + 1]);
        float2 h = *(const float2*)(h0g + (size_t)(b*NC + c)*1024 + d*8 + np);
#pragma unroll 4
        for (int l = 0; l < CS; l++){
            float de = sdl[l*128 + d];
            float uu = su[l*128 + d];
            float du = de * uu;
            float2 Bv = *(const float2*)(sB + l*8 + np);
            float2 Cv = *(const float2*)(sC + l*8 + np);
            h.x = fmaf(__expf(de * Av0), h.x, du * Bv.x);
            h.y = fmaf(__expf(de * Av1), h.y, du * Bv.y);
            float y = h.x * Cv.x + h.y * Cv.y;
            y += __shfl_xor_sync(0xffffffffu, y, 1);
            y += __shfl_xor_sync(0xffffffffu, y, 2);
            if ((t & 3) == 0) r3[l*132 + d] = y;
        }
    }
    __syncthreads();
    // phase 3: y + u*D, gate with silu(z), convert to tf32 in place
    {
        for (int i = t; i < CS*128; i += 512){
            int l = i >> 7, d = i & 127;
            float val = fmaf(su[l*128 + d], Dp[d], r3[l*132 + d]);
            val *= siluf(z[base + i]);
            r3[l*132 + d] = __uint_as_float(f2tf(val));
        }
    }
    __syncthreads();
    // phase 4: load wA (woh) over r1
    {
        const float4* h4 = (const float4*)woh;
        for (int i = t; i < 128*32; i += 512){
            int r = i >> 5, q = i & 31;
            *(float4*)(wA + r*132 + q*4) = h4[i];
        }
    }
    __syncthreads();
    // phase 5: out_proj GEMM (16 warps: 4 m-tiles x 4 n-quarters)
    {
        int p0 = (warp >> 2) * 16;
        int e00 = (warp & 3) * 32;
        const float* yrA = r3 + (p0 + row_)*132 + col_;
        const float* yrB = yrA + 8*132;
        float4 acc[4];
#pragma unroll
        for (int tt = 0; tt < 4; tt++) acc[tt] = make_float4(0.f,0.f,0.f,0.f);
#pragma unroll 4
        for (int k = 0; k < 16; k++){
            int k8 = k*8;
            uint32_t a0 = __float_as_uint(yrA[k8]);
            uint32_t a1 = __float_as_uint(yrB[k8]);
            uint32_t a2 = __float_as_uint(yrA[k8 + 4]);
            uint32_t a3 = __float_as_uint(yrB[k8 + 4]);
#pragma unroll
            for (int tt = 0; tt < 4; tt++){
                int e0 = e00 + tt*8;
                uint32_t bh0 = __float_as_uint(wA[(e0 + row_)*132 + k8 + col_]);
                uint32_t bh1 = __float_as_uint(wA[(e0 + row_)*132 + k8 + col_ + 4]);
                uint32_t bl0 = __float_as_uint(r2[(e0 + row_)*132 + k8 + col_]);
                uint32_t bl1 = __float_as_uint(r2[(e0 + row_)*132 + k8 + col_ + 4]);
                mma8(acc[tt], a0, a1, a2, a3, bh0, bh1);
                mma8(acc[tt], a0, a1, a2, a3, bl0, bl1);
            }
        }
        int pA = p0 + row_, pB = pA + 8;
#pragma unroll
        for (int tt = 0; tt < 4; tt++){
            int e = e00 + tt*8 + 2*col_;
            *(float2*)(mt + pA*132 + e) = make_float2(acc[tt].x, acc[tt].y);
            *(float2*)(mt + pB*132 + e) = make_float2(acc[tt].z, acc[tt].w);
        }
    }
    __syncthreads();   // wA/wB dead, mt valid
    // phase 6: load xt (tf32), gate weights; LN stats
    {
        const float4* x4 = (const float4*)(x + base);
        for (int i = t; i < 64*32; i += 512){
            int p = i >> 5, q = i & 31;
            float4 v = x4[i];
            v.x = __uint_as_float(f2tf(v.x)); v.y = __uint_as_float(f2tf(v.y));
            v.z = __uint_as_float(f2tf(v.z)); v.w = __uint_as_float(f2tf(v.w));
            *(float4*)(xt + p*132 + q*4) = v;
        }
        for (int i = t; i < 128*32; i += 512){
            int r = i >> 5, q = i & 31;
            s2h[r*GWS + q] = w2h[i];
            s2l[r*GWS + q] = w2l[i];
            sth[r*GWS + q] = wth[i];
            stl[r*GWS + q] = wtl[i];
        }
    }
    for (int p = warp*4; p < warp*4 + 4; p++){
        float4 v = *(const float4*)(mt + p*132 + lane*4);
        float s = v.x + v.y + v.z + v.w;
        s += __shfl_xor_sync(0xffffffffu, s, 16);
        s += __shfl_xor_sync(0xffffffffu, s, 8);
        s += __shfl_xor_sync(0xffffffffu, s, 4);
        s += __shfl_xor_sync(0xffffffffu, s, 2);
        s += __shfl_xor_sync(0xffffffffu, s, 1);
        float mu = s * (1.f/128.f);
        float dx = v.x - mu, dy = v.y - mu, dz = v.z - mu, dww = v.w - mu;
        float q = dx*dx + dy*dy + dz*dz + dww*dww;
        q += __shfl_xor_sync(0xffffffffu, q, 16);
        q += __shfl_xor_sync(0xffffffffu, q, 8);
        q += __shfl_xor_sync(0xffffffffu, q, 4);
        q += __shfl_xor_sync(0xffffffffu, q, 2);
        q += __shfl_xor_sync(0xffffffffu, q, 1);
        if (lane == 0){
            mus[p] = mu;
            rss[p] = rsqrtf(q * (1.f/128.f) + 1e-5f);
        }
    }
    __syncthreads();
    // phase 7: gate GEMM + LN combine -> fs (r3, tf32)
    int p0 = (warp >> 2) * 16;
    int cq = warp & 3;
    int pA = p0 + row_, pB = pA + 8;
    int kb = cq * 32;
#pragma unroll 1
    for (int nt = 0; nt < 4; nt++){
        int c0 = cq*32 + nt*8;
        float4 acc = make_float4(0.f,0.f,0.f,0.f);
#pragma unroll
        for (int k = 0; k < 4; k++){
            int kc = kb + k*8;
            const float* xrA = xt + pA*132 + kc + col_;
            uint32_t a0 = __float_as_uint(xrA[0]);
            uint32_t a1 = __float_as_uint(xrA[8*132]);
            uint32_t a2 = __float_as_uint(xrA[4]);
            uint32_t a3 = __float_as_uint(xrA[8*132 + 4]);
            int wi = (c0 + row_)*GWS + k*8 + col_;
            mma8(acc, a0, a1, a2, a3, __float_as_uint(s2h[wi]), __float_as_uint(s2h[wi + 4]));
            mma8(acc, a0, a1, a2, a3, __float_as_uint(s2l[wi]), __float_as_uint(s2l[wi + 4]));
        }
        int cc = c0 + 2*col_;
        float g0 = gb[cc], g1 = gb[cc + 1], b0 = gb[128 + cc], b1 = gb[128 + cc + 1];
        float vx = fmaf((mt[pA*132 + cc]     - mus[pA]) * rss[pA], g0, b0) * siluf(acc.x);
        float vy = fmaf((mt[pA*132 + cc + 1] - mus[pA]) * rss[pA], g1, b1) * siluf(acc.y);
        float vz = fmaf((mt[pB*132 + cc]     - mus[pB]) * rss[pB], g0, b0) * siluf(acc.z);
        float vw = fmaf((mt[pB*132 + cc + 1] - mus[pB]) * rss[pB], g1, b1) * siluf(acc.w);
        *(float2*)(r3 + pA*132 + cc) = make_float2(__uint_as_float(f2tf(vx)), __uint_as_float(f2tf(vy)));
        *(float2*)(r3 + pB*132 + cc) = make_float2(__uint_as_float(f2tf(vz)), __uint_as_float(f2tf(vw)));
    }
    __syncwarp();
    // phase 8: final grouped1x1 -> out
#pragma unroll 1
    for (int nt = 0; nt < 4; nt++){
        int c0 = cq*32 + nt*8;
        float4 acc = make_float4(0.f,0.f,0.f,0.f);
#pragma unroll
        for (int k = 0; k < 4; k++){
            int kc = kb + k*8;
            const float* frA = r3 + pA*132 + kc + col_;
            uint32_t a0 = __float_as_uint(frA[0]);
            uint32_t a1 = __float_as_uint(frA[8*132]);
            uint32_t a2 = __float_as_uint(frA[4]);
            uint32_t a3 = __float_as_uint(frA[8*132 + 4]);
            int wi = (c0 + row_)*GWS + k*8 + col_;
            mma8(acc, a0, a1, a2, a3, __float_as_uint(sth[wi]), __float_as_uint(sth[wi + 4]));
            mma8(acc, a0, a1, a2, a3, __float_as_uint(stl[wi]), __float_as_uint(stl[wi + 4]));
        }
        int cc = c0 + 2*col_;
        *(float2*)(out + (size_t)(pix0 + pA)*128 + cc) = make_float2(acc.x, acc.y);
        *(float2*)(out + (size_t)(pix0 + pB)*128 + cc) = make_float2(acc.z, acc.w);
    }
}

// ----------------------------------------------------------------
extern "C" void kernel_launch(void* const* d_in, const int* in_sizes, int n_in,
                              void* d_out, int out_size){
    const float* x        = (const float*)d_in[0];
    const float* w1       = (const float*)d_in[1];
    const float* dw       = (const float*)d_in[2];
    const float* in_proj  = (const float*)d_in[3];
    const float* conv1d_w = (const float*)d_in[4];
    const float* conv1d_b = (const float*)d_in[5];
    const float* x_proj_w = (const float*)d_in[6];
    const float* dt_proj_w= (const float*)d_in[7];
    const float* dt_proj_b= (const float*)d_in[8];
    const float* A_log    = (const float*)d_in[9];
    const float* D_param  = (const float*)d_in[10];
    const float* out_proj = (const float*)d_in[11];
    const float* gamma    = (const float*)d_in[12];
    const float* beta     = (const float*)d_in[13];
    const float* w2       = (const float*)d_in[14];
    const float* wout     = (const float*)d_in[15];
    float* out = (float*)d_out;

    float *t1, *xs, *u0, *z, *u, *dl, *Bm, *Cm, *Pg, *hE, *h0;
    float *wih, *wil, *woh, *wol, *w2h, *w2l, *wth, *wtl, *wxh, *wxl;
    cudaGetSymbolAddress((void**)&t1, g_t1);
    cudaGetSymbolAddress((void**)&xs, g_xs);
    cudaGetSymbolAddress((void**)&u0, g_u0);
    cudaGetSymbolAddress((void**)&z,  g_z);
    cudaGetSymbolAddress((void**)&u,  g_u);
    cudaGetSymbolAddress((void**)&dl, g_dl);
    cudaGetSymbolAddress((void**)&Bm, g_Bm);
    cudaGetSymbolAddress((void**)&Cm, g_Cm);
    cudaGetSymbolAddress((void**)&Pg, g_P);
    cudaGetSymbolAddress((void**)&hE, g_hE);
    cudaGetSymbolAddress((void**)&h0, g_h0);
    cudaGetSymbolAddress((void**)&wih, g_wih);
    cudaGetSymbolAddress((void**)&wil, g_wil);
    cudaGetSymbolAddress((void**)&woh, g_woh);
    cudaGetSymbolAddress((void**)&wol, g_wol);
    cudaGetSymbolAddress((void**)&w2h, g_w2h);
    cudaGetSymbolAddress((void**)&w2l, g_w2l);
    cudaGetSymbolAddress((void**)&wth, g_wth);
    cudaGetSymbolAddress((void**)&wtl, g_wtl);
    cudaGetSymbolAddress((void**)&wxh, g_wxh);
    cudaGetSymbolAddress((void**)&wxl, g_wxl);

    const int smemA = (2*CS*128 + CS*8) * sizeof(float);
    const int smemI = (128*132 + 2*64*132) * sizeof(float);
    const int smemX = (34*128 + 2*32*132 + 2*24*132 + 32*XDS) * sizeof(float);
    const int smemM = (17408 + 16896 + 8448 + 8448 + 64 + 64 + 256) * sizeof(float);
    static int attr_done = 0;
    if (!attr_done){
        cudaFuncSetAttribute(k_scanA, cudaFuncAttributeMaxDynamicSharedMemorySize, smemA);
        cudaFuncSetAttribute(k_inproj, cudaFuncAttributeMaxDynamicSharedMemorySize, smemI);
        cudaFuncSetAttribute(k_cxp,   cudaFuncAttributeMaxDynamicSharedMemorySize, smemX);
        cudaFuncSetAttribute(k_mega2, cudaFuncAttributeMaxDynamicSharedMemorySize, smemM);
        attr_done = 1;
    }

    k_prep<<<236, 256>>>(in_proj, out_proj, w2, wout, x_proj_w,
                         wih, wil, woh, wol, w2h, w2l, wth, wtl, wxh, wxl);
    k_g1<<<NPIX/32, 256>>>(x, w1, t1);
    k_dw<<<NPIX*32/256, 256>>>(t1, dw, xs);
    k_inproj<<<NPIX/128, 256, smemI>>>(xs, wih, wil, u0, z);
    k_cxp<<<NPIX/32, 256, smemX>>>(u0, conv1d_w, conv1d_b, wxh, wxl, dt_proj_w, dt_proj_b, u, dl, Bm, Cm);
    k_scanA<<<BB*NC, 1024, smemA>>>(dl, u, Bm, A_log, Pg, hE);
    k_scanB<<<64, 128>>>(Pg, hE, h0);
    k_mega2<<<BB*NC, 512, smemM>>>(dl, u, z, Bm, Cm, A_log, D_param, h0,
                                   woh, wol, gamma, beta, x, w2h, w2l, wth, wtl, out);
}

// round 8
// speedup vs baseline: 7.5031x; 1.0388x over previous
#include <cuda_runtime.h>
#include <math.h>
#include <stdint.h>

// Problem constants
#define BB 8
#define HH 64
#define WW 64
#define CC 128
#define DD 128
#define LL 4096            // H*W
#define NPIX (BB*LL)       // 32768
#define NS 8               // D_STATE
#define RR 8               // DT_RANK

#define CS 64              // chunk size (steps)
#define NC (LL/CS)         // 64 chunks per batch

// Scratch (device globals; no allocations allowed)
__device__ float g_t1[NPIX*DD];
__device__ float g_xs[NPIX*DD];
__device__ float g_u0[NPIX*DD];
__device__ float g_z [NPIX*DD];
__device__ float g_u [NPIX*DD];
__device__ float g_dl[NPIX*DD];
__device__ float g_Bm[NPIX*NS];
__device__ float g_Cm[NPIX*NS];
__device__ float g_P [BB*NC*1024];
__device__ float g_hE[BB*NC*1024];
__device__ float g_h0[BB*NC*1024];
// pre-split tf32 weights
__device__ float g_wih[256*128];
__device__ float g_wil[256*128];
__device__ float g_woh[128*128];
__device__ float g_wol[128*128];
__device__ float g_w2h[128*32];
__device__ float g_w2l[128*32];
__device__ float g_wth[128*32];
__device__ float g_wtl[128*32];
__device__ float g_wxh[24*128];
__device__ float g_wxl[24*128];

__device__ __forceinline__ float siluf(float v){ return v / (1.f + __expf(-v)); }

__device__ __forceinline__ uint32_t f2tf(float x){
    uint32_t r; asm("cvt.rna.tf32.f32 %0, %1;" : "=r"(r) : "f"(x)); return r;
}
__device__ __forceinline__ void mma8(float4& c, uint32_t a0, uint32_t a1, uint32_t a2, uint32_t a3,
                                     uint32_t b0, uint32_t b1){
    asm volatile("mma.sync.aligned.m16n8k8.row.col.f32.tf32.tf32.f32 "
                 "{%0,%1,%2,%3},{%4,%5,%6,%7},{%8,%9},{%0,%1,%2,%3};\n"
                 : "+f"(c.x), "+f"(c.y), "+f"(c.z), "+f"(c.w)
                 : "r"(a0), "r"(a1), "r"(a2), "r"(a3), "r"(b0), "r"(b1));
}

// ---------------------------------------------------------------- K0: weight split prep
__global__ void k_prep(const float* __restrict__ wi, const float* __restrict__ wo,
                       const float* __restrict__ w2, const float* __restrict__ wt,
                       const float* __restrict__ wx,
                       float* wih, float* wil, float* woh, float* wol,
                       float* w2h, float* w2l, float* wth, float* wtl,
                       float* wxh, float* wxl){
    int i = blockIdx.x * 256 + threadIdx.x;
    if (i >= 60416) return;
    const float* src; float* dh; float* dlo; int off;
    if (i < 32768){ src = wi; dh = wih; dlo = wil; off = i; }
    else if (i < 49152){ src = wo; dh = woh; dlo = wol; off = i - 32768; }
    else if (i < 53248){ src = w2; dh = w2h; dlo = w2l; off = i - 49152; }
    else if (i < 57344){ src = wt; dh = wth; dlo = wtl; off = i - 53248; }
    else { src = wx; dh = wxh; dlo = wxl; off = i - 57344; }
    float v = src[off];
    float h = __uint_as_float(f2tf(v));
    dh[off] = h; dlo[off] = v - h;
}

// ---------------------------------------------------------------- K1: grouped 1x1
__global__ void __launch_bounds__(256) k_g1(const float* __restrict__ x,
                                            const float* __restrict__ w,
                                            float* __restrict__ out){
    __shared__ float xt[32*128];
    int pix0 = blockIdx.x * 32;
    const float4* x4 = (const float4*)(x + (size_t)pix0*128);
    for (int i = threadIdx.x; i < 32*32; i += 256) ((float4*)xt)[i] = x4[i];
    __syncthreads();
    int t = threadIdx.x;
    int c = t & 127, half = t >> 7;
    int g = c >> 5;
    float4 wr[8];
#pragma unroll
    for (int i = 0; i < 8; i++) wr[i] = ((const float4*)(w + c*32))[i];
    const float* xb = xt + (half*16)*128 + g*32;
    float* ob = out + ((size_t)pix0 + half*16)*128 + c;
#pragma unroll
    for (int p = 0; p < 16; p++){
        const float* xr = xb + p*128;
        float a = 0.f;
#pragma unroll
        for (int i = 0; i < 8; i++){
            float4 xv = *(const float4*)(xr + i*4);
            a = fmaf(wr[i].x, xv.x, a); a = fmaf(wr[i].y, xv.y, a);
            a = fmaf(wr[i].z, xv.z, a); a = fmaf(wr[i].w, xv.w, a);
        }
        ob[(size_t)p*128] = a;
    }
}

// ---------------------------------------------------------------- K2: depthwise 3x3 + silu
__global__ void k_dw(const float* __restrict__ t1, const float* __restrict__ dw,
                     float* __restrict__ out){
    int idx = blockIdx.x * 256 + threadIdx.x;
    int d4 = idx & 31; int pix = idx >> 5;
    int wc = pix & 63; int h = (pix >> 6) & 63; int b = pix >> 12;
    int d = d4 << 2;
    float4 acc = make_float4(0.f, 0.f, 0.f, 0.f);
#pragma unroll
    for (int kh = 0; kh < 3; kh++){
        int hh = h + kh - 1; if (hh < 0 || hh >= 64) continue;
#pragma unroll
        for (int kw = 0; kw < 3; kw++){
            int ww = wc + kw - 1; if (ww < 0 || ww >= 64) continue;
            float4 tv = *(const float4*)(t1 + (((b*64 + hh)*64 + ww) << 7) + d);
            float4 wv = *(const float4*)(dw + (kh*3 + kw)*128 + d);
            acc.x = fmaf(tv.x, wv.x, acc.x); acc.y = fmaf(tv.y, wv.y, acc.y);
            acc.z = fmaf(tv.z, wv.z, acc.z); acc.w = fmaf(tv.w, wv.w, acc.w);
        }
    }
    float4 r; r.x = siluf(acc.x); r.y = siluf(acc.y); r.z = siluf(acc.z); r.w = siluf(acc.w);
    *(float4*)(out + (size_t)pix*128 + d) = r;
}

// ---------------------------------------------------------------- K3: in_proj via tf32 mma
// 512 thr (16 warps), 256 pixels/block, 128 blocks.
__global__ void __launch_bounds__(512, 1) k_inproj(const float* __restrict__ xs,
                       const float* __restrict__ wih, const float* __restrict__ wil,
                       float* __restrict__ ub, float* __restrict__ zb){
    extern __shared__ float sm[];
    float* xt  = sm;             // 256*132
    float* whs = sm + 256*132;   // 64*132
    float* wls = whs + 64*132;   // 64*132
    int tid = threadIdx.x;
    int pix0 = blockIdx.x * 256;
    {
        const float4* xs4 = (const float4*)(xs + (size_t)pix0*128);
        for (int i = tid; i < 256*32; i += 512){
            int p = i >> 5, q = i & 31;
            float4 v = xs4[i];
            v.x = __uint_as_float(f2tf(v.x)); v.y = __uint_as_float(f2tf(v.y));
            v.z = __uint_as_float(f2tf(v.z)); v.w = __uint_as_float(f2tf(v.w));
            *(float4*)(xt + p*132 + q*4) = v;
        }
    }
    int warp = tid >> 5, lane = tid & 31;
    int row_ = lane >> 2, col_ = lane & 3;
    int p0 = warp * 16;
    const float* xrA = xt + (p0 + row_)*132 + col_;
    const float* xrB = xrA + 8*132;
#pragma unroll 1
    for (int g = 0; g < 4; g++){
        __syncthreads();
        {
            const float4* h4 = (const float4*)(wih + g*64*128);
            const float4* l4 = (const float4*)(wil + g*64*128);
            for (int i = tid; i < 64*32; i += 512){
                int r = i >> 5, q = i & 31;
                *(float4*)(whs + r*132 + q*4) = h4[i];
                *(float4*)(wls + r*132 + q*4) = l4[i];
            }
        }
        __syncthreads();
        float4 acc[8];
#pragma unroll
        for (int t = 0; t < 8; t++) acc[t] = make_float4(0.f,0.f,0.f,0.f);
#pragma unroll 4
        for (int k = 0; k < 16; k++){
            int k8 = k*8;
            uint32_t a0 = __float_as_uint(xrA[k8]);
            uint32_t a1 = __float_as_uint(xrB[k8]);
            uint32_t a2 = __float_as_uint(xrA[k8 + 4]);
            uint32_t a3 = __float_as_uint(xrB[k8 + 4]);
#pragma unroll
            for (int t = 0; t < 8; t++){
                int lt = t*8;
                uint32_t bh0 = __float_as_uint(whs[(lt + row_)*132 + k8 + col_]);
                uint32_t bh1 = __float_as_uint(whs[(lt + row_)*132 + k8 + col_ + 4]);
                uint32_t bl0 = __float_as_uint(wls[(lt + row_)*132 + k8 + col_]);
                uint32_t bl1 = __float_as_uint(wls[(lt + row_)*132 + k8 + col_ + 4]);
                mma8(acc[t], a0, a1, a2, a3, bh0, bh1);
                mma8(acc[t], a0, a1, a2, a3, bl0, bl1);
            }
        }
        int pixA = pix0 + p0 + row_;
        int pixB = pixA + 8;
#pragma unroll
        for (int t = 0; t < 8; t++){
            int e0 = g*64 + t*8 + 2*col_;
            float* base = (g < 2) ? (ub + e0) : (zb + e0 - 128);
            *(float2*)(base + (size_t)pixA*128) = make_float2(acc[t].x, acc[t].y);
            *(float2*)(base + (size_t)pixB*128) = make_float2(acc[t].z, acc[t].w);
        }
    }
}

// ---------------------------------------------------------------- K4: fused conv1d + x_proj(mma) + dt_proj + scanA
// 512 thr, 64 pixels/block = one scan chunk; 512 blocks.
#define XDS 26
__global__ void __launch_bounds__(512, 1) k_cxp2(const float* __restrict__ u0,
                        const float* __restrict__ cw, const float* __restrict__ cb,
                        const float* __restrict__ wxh, const float* __restrict__ wxl,
                        const float* __restrict__ dtw, const float* __restrict__ dtb,
                        const float* __restrict__ A_log,
                        float* __restrict__ ug,
                        float* __restrict__ dl, float* __restrict__ Bb, float* __restrict__ Cb,
                        float* __restrict__ Pg, float* __restrict__ hEg){
    extern __shared__ float sm[];
    float* u0s = sm;                 // 66*128 = 8448 ; aliased by sdl (64*128) after conv/x_proj
    float* uh  = sm + 8448;          // 64*132
    float* ul  = uh + 8448;          // 64*132
    float* sxh = ul + 8448;          // 24*132
    float* sxl = sxh + 3168;         // 24*132
    float* xd  = sxl + 3168;         // 64*XDS
    float* sdl = u0s;
    int pix0 = blockIdx.x * 64;
    int b = blockIdx.x >> 6;
    int c = blockIdx.x & 63;
    int l0 = pix0 & (LL - 1);
    int t = threadIdx.x, warp = t >> 5, lane = t & 31;
    // stage u0 halo (66 rows) + x_proj weights
    {
        const float4* u4 = (const float4*)(u0 + ((size_t)pix0 - 2)*128);
        for (int i = t; i < 66*32; i += 512){
            int p = i >> 5;
            float4 v = make_float4(0.f,0.f,0.f,0.f);
            if (!(l0 == 0 && p < 2)) v = u4[i];
            ((float4*)u0s)[i] = v;
        }
        const float4* h4 = (const float4*)wxh;
        const float4* l4 = (const float4*)wxl;
        for (int i = t; i < 24*32; i += 512){
            int r = i >> 5, q = i & 31;
            *(float4*)(sxh + r*132 + q*4) = h4[i];
            *(float4*)(sxl + r*132 + q*4) = l4[i];
        }
    }
    __syncthreads();
    // conv1d + silu -> uh/ul (tf32 split) + ug (global fp32)
    {
        int d = t & 127, ph = t >> 7;   // ph in 0..3, 16 pixels each
        float w0 = cw[d*3], w1c = cw[d*3 + 1], w2c = cw[d*3 + 2];
        float bias = cb[d];
#pragma unroll 4
        for (int p = ph*16; p < ph*16 + 16; p++){
            float a = fmaf(w2c, u0s[(p + 2)*128 + d],
                      fmaf(w1c, u0s[(p + 1)*128 + d],
                      fmaf(w0,  u0s[p*128 + d], bias)));
            a = siluf(a);
            ug[(size_t)(pix0 + p)*128 + d] = a;
            float hi = __uint_as_float(f2tf(a));
            uh[p*132 + d] = hi;
            ul[p*132 + d] = a - hi;
        }
    }
    __syncthreads();
    // x_proj mma: 12 warp tiles (4 m-tiles of 16 x 3 n-tiles of 8)
    if (warp < 12){
        int m0 = (warp & 3) * 16;
        int n0 = (warp >> 2) * 8;
        int row_ = lane >> 2, col_ = lane & 3;
        const float* ahA = uh + (m0 + row_)*132 + col_;
        const float* ahB = ahA + 8*132;
        const float* alA = ul + (m0 + row_)*132 + col_;
        const float* alB = alA + 8*132;
        float4 acc = make_float4(0.f,0.f,0.f,0.f);
#pragma unroll 2
        for (int k = 0; k < 16; k++){
            int k8 = k*8;
            uint32_t h0 = __float_as_uint(ahA[k8]);
            uint32_t h1 = __float_as_uint(ahB[k8]);
            uint32_t h2 = __float_as_uint(ahA[k8 + 4]);
            uint32_t h3 = __float_as_uint(ahB[k8 + 4]);
            uint32_t l0_ = __float_as_uint(alA[k8]);
            uint32_t l1 = __float_as_uint(alB[k8]);
            uint32_t l2 = __float_as_uint(alA[k8 + 4]);
            uint32_t l3 = __float_as_uint(alB[k8 + 4]);
            uint32_t bh0 = __float_as_uint(sxh[(n0 + row_)*132 + k8 + col_]);
            uint32_t bh1 = __float_as_uint(sxh[(n0 + row_)*132 + k8 + col_ + 4]);
            uint32_t bl0 = __float_as_uint(sxl[(n0 + row_)*132 + k8 + col_]);
            uint32_t bl1 = __float_as_uint(sxl[(n0 + row_)*132 + k8 + col_ + 4]);
            mma8(acc, h0, h1, h2, h3, bh0, bh1);
            mma8(acc, h0, h1, h2, h3, bl0, bl1);
            mma8(acc, l0_, l1, l2, l3, bh0, bh1);
        }
        int pA = m0 + row_, pB = pA + 8;
        int cc = n0 + 2*col_;
        *(float2*)(xd + pA*XDS + cc) = make_float2(acc.x, acc.y);
        *(float2*)(xd + pB*XDS + cc) = make_float2(acc.z, acc.w);
    }
    __syncthreads();   // xd valid; u0s now dead -> sdl alias ok
    // dt_proj + softplus -> dl (global) + sdl (smem)
    {
        int d = t & 127, ph = t >> 7;
        float4 wa = ((const float4*)(dtw + d*8))[0];
        float4 wb = ((const float4*)(dtw + d*8))[1];
        float bias = dtb[d];
#pragma unroll 4
        for (int p = ph*16; p < ph*16 + 16; p++){
            const float* xr = xd + p*XDS;
            float a = bias;
            a = fmaf(xr[0], wa.x, a); a = fmaf(xr[1], wa.y, a);
            a = fmaf(xr[2], wa.z, a); a = fmaf(xr[3], wa.w, a);
            a = fmaf(xr[4], wb.x, a); a = fmaf(xr[5], wb.y, a);
            a = fmaf(xr[6], wb.z, a); a = fmaf(xr[7], wb.w, a);
            float sp = (a > 20.f) ? a : log1pf(__expf(a));
            dl[(size_t)(pix0 + p)*128 + d] = sp;
            sdl[p*128 + d] = sp;
        }
    }
    // B/C global write (512 threads = 64 pix x 8 n)
    {
        int p = t >> 3, n = t & 7;
        Bb[(pix0 + p)*8 + n] = xd[p*XDS + 8 + n];
        Cb[(pix0 + p)*8 + n] = xd[p*XDS + 16 + n];
    }
    __syncthreads();
    // scanA phase: 2 states/thread (d = t>>2, n = 2*(t&3)+{0,1})
    {
        int d = t >> 2, np = (t & 3) * 2;
        float Av0 = -__expf(A_log[d*8 + np]);
        float Av1 = -__expf(A_log[d*8 + np + 1]);
        float h0 = 0.f, h1 = 0.f, P0 = 1.f, P1 = 1.f;
#pragma unroll 4
        for (int l = 0; l < CS; l++){
            float de = sdl[l*128 + d];
            float uu = uh[l*132 + d] + ul[l*132 + d];
            float du = de * uu;
            float2 Bv = *(const float2*)(xd + l*XDS + 8 + np);
            float dA0 = __expf(de * Av0);
            float dA1 = __expf(de * Av1);
            P0 *= dA0; P1 *= dA1;
            h0 = fmaf(dA0, h0, du * Bv.x);
            h1 = fmaf(dA1, h1, du * Bv.y);
        }
        size_t oidx = (size_t)(b*NC + c)*1024 + d*8 + np;
        *(float2*)(Pg + oidx) = make_float2(P0, P1);
        *(float2*)(hEg + oidx) = make_float2(h0, h1);
    }
}

// ---------------------------------------------------------------- K5: chunk combine
__global__ void k_scanB(const float* __restrict__ Pg, const float* __restrict__ hEg,
                        float* __restrict__ h0g){
    int j = blockIdx.x * 128 + threadIdx.x;
    int b = j >> 10, dn = j & 1023;
    float h = 0.f;
#pragma unroll 8
    for (int c = 0; c < NC; c++){
        int idx = (b*NC + c)*1024 + dn;
        h0g[idx] = h;
        h = fmaf(Pg[idx], h, hEg[idx]);
    }
}

// ---------------------------------------------------------------- K6: MEGA2 = scanC + out_proj + LN + gate GEMMs
#define GWS 33
__global__ void __launch_bounds__(512, 1) k_mega2(
        const float* __restrict__ dl, const float* __restrict__ u,
        const float* __restrict__ z, const float* __restrict__ Bb,
        const float* __restrict__ Cb, const float* __restrict__ A_log,
        const float* __restrict__ Dp, const float* __restrict__ h0g,
        const float* __restrict__ woh, const float* __restrict__ wol,
        const float* __restrict__ gamma, const float* __restrict__ beta,
        const float* __restrict__ x,
        const float* __restrict__ w2h, const float* __restrict__ w2l,
        const float* __restrict__ wth, const float* __restrict__ wtl,
        float* __restrict__ out){
    extern __shared__ float sm[];
    float* r1 = sm;               // 17408
    float* r2 = sm + 17408;       // 16896
    float* r3 = r2 + 16896;       // 8448
    float* mt = r3 + 8448;        // 8448
    float* mus = mt + 8448;       // 64
    float* rss = mus + 64;        // 64
    float* gb  = rss + 64;        // 256
    float* sdl = r1;
    float* su  = r1 + 8192;
    float* sB  = r1 + 16384;
    float* sC  = r1 + 16896;
    float* wA  = r1;
    float* xt  = r1;
    float* s2h = r2;
    float* s2l = r2 + 128*GWS;
    float* sth = r2 + 2*128*GWS;
    float* stl = r2 + 3*128*GWS;
    int b = blockIdx.x >> 6;
    int c = blockIdx.x & (NC - 1);
    int t = threadIdx.x, warp = t >> 5, lane = t & 31;
    int row_ = lane >> 2, col_ = lane & 3;
    int pix0 = b*LL + c*CS;
    size_t base = (size_t)pix0*128;
    {
        const float4* dl4 = (const float4*)(dl + base);
        const float4* u4  = (const float4*)(u + base);
        for (int i = t; i < CS*32; i += 512){
            ((float4*)sdl)[i] = dl4[i];
            ((float4*)su)[i]  = u4[i];
        }
        int nb = pix0*8;
        if (t < CS*8){ sB[t] = Bb[nb + t]; sC[t] = Cb[nb + t]; }
        const float4* l4 = (const float4*)wol;
        for (int i = t; i < 128*32; i += 512){
            int r = i >> 5, q = i & 31;
            *(float4*)(r2 + r*132 + q*4) = l4[i];
        }
        if (t < 128){ gb[t] = gamma[t]; gb[128 + t] = beta[t]; }
    }
    __syncthreads();
    {
        int d = t >> 2, np = (t & 3) * 2;
        float Av0 = -__expf(A_log[d*8 + np]);
        float Av1 = -__expf(A_log[d*8 + np + 1]);
        float2 h = *(const float2*)(h0g + (size_t)(b*NC + c)*1024 + d*8 + np);
#pragma unroll 4
        for (int l = 0; l < CS; l++){
            float de = sdl[l*128 + d];
            float uu = su[l*128 + d];
            float du = de * uu;
            float2 Bv = *(const float2*)(sB + l*8 + np);
            float2 Cv = *(const float2*)(sC + l*8 + np);
            h.x = fmaf(__expf(de * Av0), h.x, du * Bv.x);
            h.y = fmaf(__expf(de * Av1), h.y, du * Bv.y);
            float y = h.x * Cv.x + h.y * Cv.y;
            y += __shfl_xor_sync(0xffffffffu, y, 1);
            y += __shfl_xor_sync(0xffffffffu, y, 2);
            if ((t & 3) == 0) r3[l*132 + d] = y;
        }
    }
    __syncthreads();
    {
        for (int i = t; i < CS*128; i += 512){
            int l = i >> 7, d = i & 127;
            float val = fmaf(su[l*128 + d], Dp[d], r3[l*132 + d]);
            val *= siluf(z[base + i]);
            r3[l*132 + d] = __uint_as_float(f2tf(val));
        }
    }
    __syncthreads();
    {
        const float4* h4 = (const float4*)woh;
        for (int i = t; i < 128*32; i += 512){
            int r = i >> 5, q = i & 31;
            *(float4*)(wA + r*132 + q*4) = h4[i];
        }
    }
    __syncthreads();
    {
        int p0 = (warp >> 2) * 16;
        int e00 = (warp & 3) * 32;
        const float* yrA = r3 + (p0 + row_)*132 + col_;
        const float* yrB = yrA + 8*132;
        float4 acc[4];
#pragma unroll
        for (int tt = 0; tt < 4; tt++) acc[tt] = make_float4(0.f,0.f,0.f,0.f);
#pragma unroll 4
        for (int k = 0; k < 16; k++){
            int k8 = k*8;
            uint32_t a0 = __float_as_uint(yrA[k8]);
            uint32_t a1 = __float_as_uint(yrB[k8]);
            uint32_t a2 = __float_as_uint(yrA[k8 + 4]);
            uint32_t a3 = __float_as_uint(yrB[k8 + 4]);
#pragma unroll
            for (int tt = 0; tt < 4; tt++){
                int e0 = e00 + tt*8;
                uint32_t bh0 = __float_as_uint(wA[(e0 + row_)*132 + k8 + col_]);
                uint32_t bh1 = __float_as_uint(wA[(e0 + row_)*132 + k8 + col_ + 4]);
                uint32_t bl0 = __float_as_uint(r2[(e0 + row_)*132 + k8 + col_]);
                uint32_t bl1 = __float_as_uint(r2[(e0 + row_)*132 + k8 + col_ + 4]);
                mma8(acc[tt], a0, a1, a2, a3, bh0, bh1);
                mma8(acc[tt], a0, a1, a2, a3, bl0, bl1);
            }
        }
        int pA = p0 + row_, pB = pA + 8;
#pragma unroll
        for (int tt = 0; tt < 4; tt++){
            int e = e00 + tt*8 + 2*col_;
            *(float2*)(mt + pA*132 + e) = make_float2(acc[tt].x, acc[tt].y);
            *(float2*)(mt + pB*132 + e) = make_float2(acc[tt].z, acc[tt].w);
        }
    }
    __syncthreads();
    {
        const float4* x4 = (const float4*)(x + base);
        for (int i = t; i < 64*32; i += 512){
            int p = i >> 5, q = i & 31;
            float4 v = x4[i];
            v.x = __uint_as_float(f2tf(v.x)); v.y = __uint_as_float(f2tf(v.y));
            v.z = __uint_as_float(f2tf(v.z)); v.w = __uint_as_float(f2tf(v.w));
            *(float4*)(xt + p*132 + q*4) = v;
        }
        for (int i = t; i < 128*32; i += 512){
            int r = i >> 5, q = i & 31;
            s2h[r*GWS + q] = w2h[i];
            s2l[r*GWS + q] = w2l[i];
            sth[r*GWS + q] = wth[i];
            stl[r*GWS + q] = wtl[i];
        }
    }
    for (int p = warp*4; p < warp*4 + 4; p++){
        float4 v = *(const float4*)(mt + p*132 + lane*4);
        float s = v.x + v.y + v.z + v.w;
        s += __shfl_xor_sync(0xffffffffu, s, 16);
        s += __shfl_xor_sync(0xffffffffu, s, 8);
        s += __shfl_xor_sync(0xffffffffu, s, 4);
        s += __shfl_xor_sync(0xffffffffu, s, 2);
        s += __shfl_xor_sync(0xffffffffu, s, 1);
        float mu = s * (1.f/128.f);
        float dx = v.x - mu, dy = v.y - mu, dz = v.z - mu, dww = v.w - mu;
        float q = dx*dx + dy*dy + dz*dz + dww*dww;
        q += __shfl_xor_sync(0xffffffffu, q, 16);
        q += __shfl_xor_sync(0xffffffffu, q, 8);
        q += __shfl_xor_sync(0xffffffffu, q, 4);
        q += __shfl_xor_sync(0xffffffffu, q, 2);
        q += __shfl_xor_sync(0xffffffffu, q, 1);
        if (lane == 0){
            mus[p] = mu;
            rss[p] = rsqrtf(q * (1.f/128.f) + 1e-5f);
        }
    }
    __syncthreads();
    int p0 = (warp >> 2) * 16;
    int cq = warp & 3;
    int pA = p0 + row_, pB = pA + 8;
    int kb = cq * 32;
#pragma unroll 1
    for (int nt = 0; nt < 4; nt++){
        int c0 = cq*32 + nt*8;
        float4 acc = make_float4(0.f,0.f,0.f,0.f);
#pragma unroll
        for (int k = 0; k < 4; k++){
            int kc = kb + k*8;
            const float* xrA = xt + pA*132 + kc + col_;
            uint32_t a0 = __float_as_uint(xrA[0]);
            uint32_t a1 = __float_as_uint(xrA[8*132]);
            uint32_t a2 = __float_as_uint(xrA[4]);
            uint32_t a3 = __float_as_uint(xrA[8*132 + 4]);
            int wi = (c0 + row_)*GWS + k*8 + col_;
            mma8(acc, a0, a1, a2, a3, __float_as_uint(s2h[wi]), __float_as_uint(s2h[wi + 4]));
            mma8(acc, a0, a1, a2, a3, __float_as_uint(s2l[wi]), __float_as_uint(s2l[wi + 4]));
        }
        int cc = c0 + 2*col_;
        float g0 = gb[cc], g1 = gb[cc + 1], b0 = gb[128 + cc], b1 = gb[128 + cc + 1];
        float vx = fmaf((mt[pA*132 + cc]     - mus[pA]) * rss[pA], g0, b0) * siluf(acc.x);
        float vy = fmaf((mt[pA*132 + cc + 1] - mus[pA]) * rss[pA], g1, b1) * siluf(acc.y);
        float vz = fmaf((mt[pB*132 + cc]     - mus[pB]) * rss[pB], g0, b0) * siluf(acc.z);
        float vw = fmaf((mt[pB*132 + cc + 1] - mus[pB]) * rss[pB], g1, b1) * siluf(acc.w);
        *(float2*)(r3 + pA*132 + cc) = make_float2(__uint_as_float(f2tf(vx)), __uint_as_float(f2tf(vy)));
        *(float2*)(r3 + pB*132 + cc) = make_float2(__uint_as_float(f2tf(vz)), __uint_as_float(f2tf(vw)));
    }
    __syncwarp();
#pragma unroll 1
    for (int nt = 0; nt < 4; nt++){
        int c0 = cq*32 + nt*8;
        float4 acc = make_float4(0.f,0.f,0.f,0.f);
#pragma unroll
        for (int k = 0; k < 4; k++){
            int kc = kb + k*8;
            const float* frA = r3 + pA*132 + kc + col_;
            uint32_t a0 = __float_as_uint(frA[0]);
            uint32_t a1 = __float_as_uint(frA[8*132]);
            uint32_t a2 = __float_as_uint(frA[4]);
            uint32_t a3 = __float_as_uint(frA[8*132 + 4]);
            int wi = (c0 + row_)*GWS + k*8 + col_;
            mma8(acc, a0, a1, a2, a3, __float_as_uint(sth[wi]), __float_as_uint(sth[wi + 4]));
            mma8(acc, a0, a1, a2, a3, __float_as_uint(stl[wi]), __float_as_uint(stl[wi + 4]));
        }
        int cc = c0 + 2*col_;
        *(float2*)(out + (size_t)(pix0 + pA)*128 + cc) = make_float2(acc.x, acc.y);
        *(float2*)(out + (size_t)(pix0 + pB)*128 + cc) = make_float2(acc.z, acc.w);
    }
}

// ----------------------------------------------------------------
extern "C" void kernel_launch(void* const* d_in, const int* in_sizes, int n_in,
                              void* d_out, int out_size){
    const float* x        = (const float*)d_in[0];
    const float* w1       = (const float*)d_in[1];
    const float* dw       = (const float*)d_in[2];
    const float* in_proj  = (const float*)d_in[3];
    const float* conv1d_w = (const float*)d_in[4];
    const float* conv1d_b = (const float*)d_in[5];
    const float* x_proj_w = (const float*)d_in[6];
    const float* dt_proj_w= (const float*)d_in[7];
    const float* dt_proj_b= (const float*)d_in[8];
    const float* A_log    = (const float*)d_in[9];
    const float* D_param  = (const float*)d_in[10];
    const float* out_proj = (const float*)d_in[11];
    const float* gamma    = (const float*)d_in[12];
    const float* beta     = (const float*)d_in[13];
    const float* w2       = (const float*)d_in[14];
    const float* wout     = (const float*)d_in[15];
    float* out = (float*)d_out;

    float *t1, *xs, *u0, *z, *u, *dl, *Bm, *Cm, *Pg, *hE, *h0;
    float *wih, *wil, *woh, *wol, *w2h, *w2l, *wth, *wtl, *wxh, *wxl;
    cudaGetSymbolAddress((void**)&t1, g_t1);
    cudaGetSymbolAddress((void**)&xs, g_xs);
    cudaGetSymbolAddress((void**)&u0, g_u0);
    cudaGetSymbolAddress((void**)&z,  g_z);
    cudaGetSymbolAddress((void**)&u,  g_u);
    cudaGetSymbolAddress((void**)&dl, g_dl);
    cudaGetSymbolAddress((void**)&Bm, g_Bm);
    cudaGetSymbolAddress((void**)&Cm, g_Cm);
    cudaGetSymbolAddress((void**)&Pg, g_P);
    cudaGetSymbolAddress((void**)&hE, g_hE);
    cudaGetSymbolAddress((void**)&h0, g_h0);
    cudaGetSymbolAddress((void**)&wih, g_wih);
    cudaGetSymbolAddress((void**)&wil, g_wil);
    cudaGetSymbolAddress((void**)&woh, g_woh);
    cudaGetSymbolAddress((void**)&wol, g_wol);
    cudaGetSymbolAddress((void**)&w2h, g_w2h);
    cudaGetSymbolAddress((void**)&w2l, g_w2l);
    cudaGetSymbolAddress((void**)&wth, g_wth);
    cudaGetSymbolAddress((void**)&wtl, g_wtl);
    cudaGetSymbolAddress((void**)&wxh, g_wxh);
    cudaGetSymbolAddress((void**)&wxl, g_wxl);

    const int smemI = (256*132 + 2*64*132) * sizeof(float);                    // 202.7 KB
    const int smemX = (66*128 + 2*64*132 + 2*24*132 + 64*XDS) * sizeof(float); // 133.4 KB
    const int smemM = (17408 + 16896 + 8448 + 8448 + 64 + 64 + 256) * sizeof(float);
    static int attr_done = 0;
    if (!attr_done){
        cudaFuncSetAttribute(k_inproj, cudaFuncAttributeMaxDynamicSharedMemorySize, smemI);
        cudaFuncSetAttribute(k_cxp2,  cudaFuncAttributeMaxDynamicSharedMemorySize, smemX);
        cudaFuncSetAttribute(k_mega2, cudaFuncAttributeMaxDynamicSharedMemorySize, smemM);
        attr_done = 1;
    }

    k_prep<<<236, 256>>>(in_proj, out_proj, w2, wout, x_proj_w,
                         wih, wil, woh, wol, w2h, w2l, wth, wtl, wxh, wxl);
    k_g1<<<NPIX/32, 256>>>(x, w1, t1);
    k_dw<<<NPIX*32/256, 256>>>(t1, dw, xs);
    k_inproj<<<NPIX/256, 512, smemI>>>(xs, wih, wil, u0, z);
    k_cxp2<<<NPIX/64, 512, smemX>>>(u0, conv1d_w, conv1d_b, wxh, wxl, dt_proj_w, dt_proj_b,
                                    A_log, u, dl, Bm, Cm, Pg, hE);
    k_scanB<<<64, 128>>>(Pg, hE, h0);
    k_mega2<<<BB*NC, 512, smemM>>>(dl, u, z, Bm, Cm, A_log, D_param, h0,
                                   woh, wol, gamma, beta, x, w2h, w2l, wth, wtl, out);
}

// round 10
// speedup vs baseline: 7.9295x; 1.0568x over previous
#include <cuda_runtime.h>
#include <math.h>
#include <stdint.h>

// Problem constants
#define BB 8
#define HH 64
#define WW 64
#define CC 128
#define DD 128
#define LL 4096            // H*W
#define NPIX (BB*LL)       // 32768
#define NS 8               // D_STATE
#define RR 8               // DT_RANK

#define CS 64              // chunk size (steps)
#define NC (LL/CS)         // 64 chunks per batch

// Scratch (device globals; no allocations allowed)
__device__ float g_t1[NPIX*DD];
__device__ float g_xs[NPIX*DD];
__device__ float g_u0[NPIX*DD];
__device__ float g_z [NPIX*DD];
__device__ float g_u [NPIX*DD];
__device__ float g_dl[NPIX*DD];
__device__ float g_Bm[NPIX*NS];
__device__ float g_Cm[NPIX*NS];
__device__ float g_P [BB*NC*1024];
__device__ float g_hE[BB*NC*1024];
__device__ float g_h0[BB*NC*1024];
// fragment-packed tf32 hi/lo weights: float4 {bh0, bh1, bl0, bl1} per (tile,k,lane)
__device__ float g_wip[65536];   // in_proj: 32 tiles x 16 k x 32 lanes
__device__ float g_wop[32768];   // out_proj: 16 tiles x 16 k x 32 lanes
__device__ float g_w2p[8192];    // w2 gate: 16 tiles x 4 k x 32 lanes
__device__ float g_wtp[8192];    // wout:    16 tiles x 4 k x 32 lanes
__device__ float g_wxp[6144];    // x_proj:  3 tiles x 16 k x 32 lanes

__device__ __forceinline__ float siluf(float v){ return v / (1.f + __expf(-v)); }

__device__ __forceinline__ uint32_t f2tf(float x){
    uint32_t r; asm("cvt.rna.tf32.f32 %0, %1;" : "=r"(r) : "f"(x)); return r;
}
__device__ __forceinline__ void mma8(float4& c, uint32_t a0, uint32_t a1, uint32_t a2, uint32_t a3,
                                     uint32_t b0, uint32_t b1){
    asm volatile("mma.sync.aligned.m16n8k8.row.col.f32.tf32.tf32.f32 "
                 "{%0,%1,%2,%3},{%4,%5,%6,%7},{%8,%9},{%0,%1,%2,%3};\n"
                 : "+f"(c.x), "+f"(c.y), "+f"(c.z), "+f"(c.w)
                 : "r"(a0), "r"(a1), "r"(a2), "r"(a3), "r"(b0), "r"(b1));
}
__device__ __forceinline__ float4 pack_hl(float v0, float v1){
    float h0 = __uint_as_float(f2tf(v0));
    float h1 = __uint_as_float(f2tf(v1));
    return make_float4(h0, h1, v0 - h0, v1 - h1);
}

// ---------------------------------------------------------------- K0: weight fragment-pack prep
__global__ void k_prep(const float* __restrict__ wi, const float* __restrict__ wo,
                       const float* __restrict__ w2, const float* __restrict__ wt,
                       const float* __restrict__ wx,
                       float* wip, float* wop, float* w2p, float* wtp, float* wxp){
    int i = blockIdx.x * 256 + threadIdx.x;
    if (i >= 30208) return;
    if (i < 16384){
        int lane = i & 31, k = (i >> 5) & 15, tile = i >> 9;
        int row = lane >> 2, col = lane & 3;
        int e = tile*8 + row, kc = k*8 + col;
        ((float4*)wip)[i] = pack_hl(wi[e*128 + kc], wi[e*128 + kc + 4]);
    } else if (i < 24576){
        int j = i - 16384;
        int lane = j & 31, k = (j >> 5) & 15, tile = j >> 9;
        int row = lane >> 2, col = lane & 3;
        int e = tile*8 + row, kc = k*8 + col;
        ((float4*)wop)[j] = pack_hl(wo[e*128 + kc], wo[e*128 + kc + 4]);
    } else if (i < 26624){
        int j = i - 24576;
        int lane = j & 31, k = (j >> 5) & 3, tile = j >> 7;
        int row = lane >> 2, col = lane & 3;
        int e = tile*8 + row;
        ((float4*)w2p)[j] = pack_hl(w2[e*32 + k*8 + col], w2[e*32 + k*8 + col + 4]);
    } else if (i < 28672){
        int j = i - 26624;
        int lane = j & 31, k = (j >> 5) & 3, tile = j >> 7;
        int row = lane >> 2, col = lane & 3;
        int e = tile*8 + row;
        ((float4*)wtp)[j] = pack_hl(wt[e*32 + k*8 + col], wt[e*32 + k*8 + col + 4]);
    } else {
        int j = i - 28672;
        int lane = j & 31, k = (j >> 5) & 15, tile = j >> 9;
        int row = lane >> 2, col = lane & 3;
        int e = tile*8 + row, kc = k*8 + col;
        ((float4*)wxp)[j] = pack_hl(wx[e*128 + kc], wx[e*128 + kc + 4]);
    }
}

// ---------------------------------------------------------------- K1: grouped 1x1
__global__ void __launch_bounds__(256) k_g1(const float* __restrict__ x,
                                            const float* __restrict__ w,
                                            float* __restrict__ out){
    __shared__ float xt[32*128];
    int pix0 = blockIdx.x * 32;
    const float4* x4 = (const float4*)(x + (size_t)pix0*128);
    for (int i = threadIdx.x; i < 32*32; i += 256) ((float4*)xt)[i] = x4[i];
    __syncthreads();
    int t = threadIdx.x;
    int c = t & 127, half = t >> 7;
    int g = c >> 5;
    float4 wr[8];
#pragma unroll
    for (int i = 0; i < 8; i++) wr[i] = ((const float4*)(w + c*32))[i];
    const float* xb = xt + (half*16)*128 + g*32;
    float* ob = out + ((size_t)pix0 + half*16)*128 + c;
#pragma unroll
    for (int p = 0; p < 16; p++){
        const float* xr = xb + p*128;
        float a = 0.f;
#pragma unroll
        for (int i = 0; i < 8; i++){
            float4 xv = *(const float4*)(xr + i*4);
            a = fmaf(wr[i].x, xv.x, a); a = fmaf(wr[i].y, xv.y, a);
            a = fmaf(wr[i].z, xv.z, a); a = fmaf(wr[i].w, xv.w, a);
        }
        ob[(size_t)p*128] = a;
    }
}

// ---------------------------------------------------------------- K2: depthwise 3x3 + silu
__global__ void k_dw(const float* __restrict__ t1, const float* __restrict__ dw,
                     float* __restrict__ out){
    int idx = blockIdx.x * 256 + threadIdx.x;
    int d4 = idx & 31; int pix = idx >> 5;
    int wc = pix & 63; int h = (pix >> 6) & 63; int b = pix >> 12;
    int d = d4 << 2;
    float4 acc = make_float4(0.f, 0.f, 0.f, 0.f);
#pragma unroll
    for (int kh = 0; kh < 3; kh++){
        int hh = h + kh - 1; if (hh < 0 || hh >= 64) continue;
#pragma unroll
        for (int kw = 0; kw < 3; kw++){
            int ww = wc + kw - 1; if (ww < 0 || ww >= 64) continue;
            float4 tv = *(const float4*)(t1 + (((b*64 + hh)*64 + ww) << 7) + d);
            float4 wv = *(const float4*)(dw + (kh*3 + kw)*128 + d);
            acc.x = fmaf(tv.x, wv.x, acc.x); acc.y = fmaf(tv.y, wv.y, acc.y);
            acc.z = fmaf(tv.z, wv.z, acc.z); acc.w = fmaf(tv.w, wv.w, acc.w);
        }
    }
    float4 r; r.x = siluf(acc.x); r.y = siluf(acc.y); r.z = siluf(acc.z); r.w = siluf(acc.w);
    *(float4*)(out + (size_t)pix*128 + d) = r;
}

// ---------------------------------------------------------------- K3: in_proj via tf32 mma (packed fragments)
__global__ void __launch_bounds__(512, 1) k_inproj(const float* __restrict__ xs,
                       const float* __restrict__ wip,
                       float* __restrict__ ub, float* __restrict__ zb){
    extern __shared__ float sm[];
    float* xt = sm;              // 256*132 = 33792
    float4* wp = (float4*)(sm + 256*132);   // 4096 float4 per group
    int tid = threadIdx.x;
    int pix0 = blockIdx.x * 256;
    {
        const float4* xs4 = (const float4*)(xs + (size_t)pix0*128);
        for (int i = tid; i < 256*32; i += 512){
            int p = i >> 5, q = i & 31;
            float4 v = xs4[i];
            v.x = __uint_as_float(f2tf(v.x)); v.y = __uint_as_float(f2tf(v.y));
            v.z = __uint_as_float(f2tf(v.z)); v.w = __uint_as_float(f2tf(v.w));
            *(float4*)(xt + p*132 + q*4) = v;
        }
    }
    int warp = tid >> 5, lane = tid & 31;
    int row_ = lane >> 2, col_ = lane & 3;
    int p0 = warp * 16;
    const float* xrA = xt + (p0 + row_)*132 + col_;
    const float* xrB = xrA + 8*132;
#pragma unroll 1
    for (int g = 0; g < 4; g++){
        __syncthreads();
        {
            const float4* src = (const float4*)wip + g*4096;
            for (int i = tid; i < 4096; i += 512) wp[i] = src[i];
        }
        __syncthreads();
        float4 acc[8];
#pragma unroll
        for (int t = 0; t < 8; t++) acc[t] = make_float4(0.f,0.f,0.f,0.f);
#pragma unroll 4
        for (int k = 0; k < 16; k++){
            int k8 = k*8;
            uint32_t a0 = __float_as_uint(xrA[k8]);
            uint32_t a1 = __float_as_uint(xrB[k8]);
            uint32_t a2 = __float_as_uint(xrA[k8 + 4]);
            uint32_t a3 = __float_as_uint(xrB[k8 + 4]);
#pragma unroll
            for (int t = 0; t < 8; t++){
                float4 bw = wp[(t*16 + k)*32 + lane];
                mma8(acc[t], a0, a1, a2, a3, __float_as_uint(bw.x), __float_as_uint(bw.y));
                mma8(acc[t], a0, a1, a2, a3, __float_as_uint(bw.z), __float_as_uint(bw.w));
            }
        }
        int pixA = pix0 + p0 + row_;
        int pixB = pixA + 8;
#pragma unroll
        for (int t = 0; t < 8; t++){
            int e0 = g*64 + t*8 + 2*col_;
            float* base = (g < 2) ? (ub + e0) : (zb + e0 - 128);
            *(float2*)(base + (size_t)pixA*128) = make_float2(acc[t].x, acc[t].y);
            *(float2*)(base + (size_t)pixB*128) = make_float2(acc[t].z, acc[t].w);
        }
    }
}

// ---------------------------------------------------------------- K4: fused conv1d + x_proj(mma) + dt_proj + scanA
#define XDS 26
__global__ void __launch_bounds__(512, 1) k_cxp2(const float* __restrict__ u0,
                        const float* __restrict__ cw, const float* __restrict__ cb,
                        const float* __restrict__ wxp,
                        const float* __restrict__ dtw, const float* __restrict__ dtb,
                        const float* __restrict__ A_log,
                        float* __restrict__ ug,
                        float* __restrict__ dl, float* __restrict__ Bb, float* __restrict__ Cb,
                        float* __restrict__ Pg, float* __restrict__ hEg){
    extern __shared__ float sm[];
    float* u0s = sm;                 // 66*128 = 8448 ; aliased by sdl after conv/x_proj
    float* uh  = sm + 8448;          // 64*132
    float* ul  = uh + 8448;          // 64*132
    float4* sxp = (float4*)(ul + 8448);  // 1536 float4
    float* xd  = ul + 8448 + 6144;   // 64*XDS
    float* sdl = u0s;
    int pix0 = blockIdx.x * 64;
    int b = blockIdx.x >> 6;
    int c = blockIdx.x & 63;
    int l0 = pix0 & (LL - 1);
    int t = threadIdx.x, warp = t >> 5, lane = t & 31;
    {
        const float4* u4 = (const float4*)(u0 + ((size_t)pix0 - 2)*128);
        for (int i = t; i < 66*32; i += 512){
            int p = i >> 5;
            float4 v = make_float4(0.f,0.f,0.f,0.f);
            if (!(l0 == 0 && p < 2)) v = u4[i];
            ((float4*)u0s)[i] = v;
        }
        const float4* src = (const float4*)wxp;
        for (int i = t; i < 1536; i += 512) sxp[i] = src[i];
    }
    __syncthreads();
    {
        int d = t & 127, ph = t >> 7;
        float w0 = cw[d*3], w1c = cw[d*3 + 1], w2c = cw[d*3 + 2];
        float bias = cb[d];
#pragma unroll 4
        for (int p = ph*16; p < ph*16 + 16; p++){
            float a = fmaf(w2c, u0s[(p + 2)*128 + d],
                      fmaf(w1c, u0s[(p + 1)*128 + d],
                      fmaf(w0,  u0s[p*128 + d], bias)));
            a = siluf(a);
            ug[(size_t)(pix0 + p)*128 + d] = a;
            float hi = __uint_as_float(f2tf(a));
            uh[p*132 + d] = hi;
            ul[p*132 + d] = a - hi;
        }
    }
    __syncthreads();
    if (warp < 12){
        int m0 = (warp & 3) * 16;
        int ntile = warp >> 2;
        int row_ = lane >> 2, col_ = lane & 3;
        const float* ahA = uh + (m0 + row_)*132 + col_;
        const float* ahB = ahA + 8*132;
        const float* alA = ul + (m0 + row_)*132 + col_;
        const float* alB = alA + 8*132;
        float4 acc = make_float4(0.f,0.f,0.f,0.f);
#pragma unroll 2
        for (int k = 0; k < 16; k++){
            int k8 = k*8;
            uint32_t h0 = __float_as_uint(ahA[k8]);
            uint32_t h1 = __float_as_uint(ahB[k8]);
            uint32_t h2 = __float_as_uint(ahA[k8 + 4]);
            uint32_t h3 = __float_as_uint(ahB[k8 + 4]);
            uint32_t l0_ = __float_as_uint(alA[k8]);
            uint32_t l1 = __float_as_uint(alB[k8]);
            uint32_t l2 = __float_as_uint(alA[k8 + 4]);
            uint32_t l3 = __float_as_uint(alB[k8 + 4]);
            float4 bw = sxp[(ntile*16 + k)*32 + lane];
            uint32_t bh0 = __float_as_uint(bw.x), bh1 = __float_as_uint(bw.y);
            uint32_t bl0 = __float_as_uint(bw.z), bl1 = __float_as_uint(bw.w);
            mma8(acc, h0, h1, h2, h3, bh0, bh1);
            mma8(acc, h0, h1, h2, h3, bl0, bl1);
            mma8(acc, l0_, l1, l2, l3, bh0, bh1);
        }
        int pA = m0 + row_, pB = pA + 8;
        int cc = ntile*8 + 2*col_;
        *(float2*)(xd + pA*XDS + cc) = make_float2(acc.x, acc.y);
        *(float2*)(xd + pB*XDS + cc) = make_float2(acc.z, acc.w);
    }
    __syncthreads();
    {
        int d = t & 127, ph = t >> 7;
        float4 wa = ((const float4*)(dtw + d*8))[0];
        float4 wb = ((const float4*)(dtw + d*8))[1];
        float bias = dtb[d];
#pragma unroll 4
        for (int p = ph*16; p < ph*16 + 16; p++){
            const float* xr = xd + p*XDS;
            float a = bias;
            a = fmaf(xr[0], wa.x, a); a = fmaf(xr[1], wa.y, a);
            a = fmaf(xr[2], wa.z, a); a = fmaf(xr[3], wa.w, a);
            a = fmaf(xr[4], wb.x, a); a = fmaf(xr[5], wb.y, a);
            a = fmaf(xr[6], wb.z, a); a = fmaf(xr[7], wb.w, a);
            float sp = (a > 20.f) ? a : log1pf(__expf(a));
            dl[(size_t)(pix0 + p)*128 + d] = sp;
            sdl[p*128 + d] = sp;
        }
    }
    {
        int p = t >> 3, n = t & 7;
        Bb[(pix0 + p)*8 + n] = xd[p*XDS + 8 + n];
        Cb[(pix0 + p)*8 + n] = xd[p*XDS + 16 + n];
    }
    __syncthreads();
    {
        int d = t >> 2, np = (t & 3) * 2;
        float Av0 = -__expf(A_log[d*8 + np]);
        float Av1 = -__expf(A_log[d*8 + np + 1]);
        float h0 = 0.f, h1 = 0.f, P0 = 1.f, P1 = 1.f;
#pragma unroll 4
        for (int l = 0; l < CS; l++){
            float de = sdl[l*128 + d];
            float uu = uh[l*132 + d] + ul[l*132 + d];
            float du = de * uu;
            float2 Bv = *(const float2*)(xd + l*XDS + 8 + np);
            float dA0 = __expf(de * Av0);
            float dA1 = __expf(de * Av1);
            P0 *= dA0; P1 *= dA1;
            h0 = fmaf(dA0, h0, du * Bv.x);
            h1 = fmaf(dA1, h1, du * Bv.y);
        }
        size_t oidx = (size_t)(b*NC + c)*1024 + d*8 + np;
        *(float2*)(Pg + oidx) = make_float2(P0, P1);
        *(float2*)(hEg + oidx) = make_float2(h0, h1);
    }
}

// ---------------------------------------------------------------- K5: chunk combine
__global__ void k_scanB(const float* __restrict__ Pg, const float* __restrict__ hEg,
                        float* __restrict__ h0g){
    int j = blockIdx.x * 128 + threadIdx.x;
    int b = j >> 10, dn = j & 1023;
    float h = 0.f;
#pragma unroll 8
    for (int c = 0; c < NC; c++){
        int idx = (b*NC + c)*1024 + dn;
        h0g[idx] = h;
        h = fmaf(Pg[idx], h, hEg[idx]);
    }
}

// ---------------------------------------------------------------- K6: MEGA2 = scanC + out_proj + LN + gate GEMMs
__global__ void __launch_bounds__(512, 1) k_mega2(
        const float* __restrict__ dl, const float* __restrict__ u,
        const float* __restrict__ z, const float* __restrict__ Bb,
        const float* __restrict__ Cb, const float* __restrict__ A_log,
        const float* __restrict__ Dp, const float* __restrict__ h0g,
        const float* __restrict__ wop,
        const float* __restrict__ gamma, const float* __restrict__ beta,
        const float* __restrict__ x,
        const float* __restrict__ w2p, const float* __restrict__ wtp,
        float* __restrict__ out){
    extern __shared__ float sm[];
    float* r1 = sm;               // 17408
    float* r2 = sm + 17408;       // 16896
    float* r3 = r2 + 16896;       // 8448
    float* mt = r3 + 8448;        // 8448
    float* mus = mt + 8448;       // 64
    float* rss = mus + 64;        // 64
    float* gb  = rss + 64;        // 256
    float* sdl = r1;
    float* su  = r1 + 8192;
    float* sB  = r1 + 16384;
    float* sC  = r1 + 16896;
    float* xt  = r1;
    int b = blockIdx.x >> 6;
    int c = blockIdx.x & (NC - 1);
    int t = threadIdx.x, warp = t >> 5, lane = t & 31;
    int row_ = lane >> 2, col_ = lane & 3;
    int pix0 = b*LL + c*CS;
    size_t base = (size_t)pix0*128;
    // phase 1
    {
        const float4* dl4 = (const float4*)(dl + base);
        const float4* u4  = (const float4*)(u + base);
        for (int i = t; i < CS*32; i += 512){
            ((float4*)sdl)[i] = dl4[i];
            ((float4*)su)[i]  = u4[i];
        }
        int nb = pix0*8;
        if (t < CS*8){ sB[t] = Bb[nb + t]; sC[t] = Cb[nb + t]; }
        const float4* src = (const float4*)wop;
        for (int i = t; i < 4096; i += 512) ((float4*)r2)[i] = src[i];
        if (t < 128){ gb[t] = gamma[t]; gb[128 + t] = beta[t]; }
    }
    __syncthreads();
    // phase 2: scan
    {
        int d = t >> 2, np = (t & 3) * 2;
        float Av0 = -__expf(A_log[d*8 + np]);
        float Av1 = -__expf(A_log[d*8 + np + 1]);
        float2 h = *(const float2*)(h0g + (size_t)(b*NC + c)*1024 + d*8 + np);
#pragma unroll 4
        for (int l = 0; l < CS; l++){
            float de = sdl[l*128 + d];
            float uu = su[l*128 + d];
            float du = de * uu;
            float2 Bv = *(const float2*)(sB + l*8 + np);
            float2 Cv = *(const float2*)(sC + l*8 + np);
            h.x = fmaf(__expf(de * Av0), h.x, du * Bv.x);
            h.y = fmaf(__expf(de * Av1), h.y, du * Bv.y);
            float y = h.x * Cv.x + h.y * Cv.y;
            y += __shfl_xor_sync(0xffffffffu, y, 1);
            y += __shfl_xor_sync(0xffffffffu, y, 2);
            if ((t & 3) == 0) r3[l*132 + d] = y;
        }
    }
    __syncthreads();
    // phase 3
    {
        for (int i = t; i < CS*128; i += 512){
            int l = i >> 7, d = i & 127;
            float val = fmaf(su[l*128 + d], Dp[d], r3[l*132 + d]);
            val *= siluf(z[base + i]);
            r3[l*132 + d] = __uint_as_float(f2tf(val));
        }
    }
    __syncthreads();
    // phase 4: wop tiles 8..15 into r1 (su dead)
    {
        const float4* src = (const float4*)wop + 4096;
        for (int i = t; i < 4096; i += 512) ((float4*)r1)[i] = src[i];
    }
    __syncthreads();
    // phase 5: out_proj GEMM
    {
        int p0 = (warp >> 2) * 16;
        int nq = warp & 3;
        const float* yrA = r3 + (p0 + row_)*132 + col_;
        const float* yrB = yrA + 8*132;
        float4 acc[4];
#pragma unroll
        for (int tt = 0; tt < 4; tt++) acc[tt] = make_float4(0.f,0.f,0.f,0.f);
#pragma unroll 4
        for (int k = 0; k < 16; k++){
            int k8 = k*8;
            uint32_t a0 = __float_as_uint(yrA[k8]);
            uint32_t a1 = __float_as_uint(yrB[k8]);
            uint32_t a2 = __float_as_uint(yrA[k8 + 4]);
            uint32_t a3 = __float_as_uint(yrB[k8 + 4]);
#pragma unroll
            for (int tt = 0; tt < 4; tt++){
                int tile = nq*4 + tt;
                const float4* wb4 = (tile < 8) ? ((const float4*)r2 + tile*512)
                                               : ((const float4*)r1 + (tile - 8)*512);
                float4 bw = wb4[k*32 + lane];
                mma8(acc[tt], a0, a1, a2, a3, __float_as_uint(bw.x), __float_as_uint(bw.y));
                mma8(acc[tt], a0, a1, a2, a3, __float_as_uint(bw.z), __float_as_uint(bw.w));
            }
        }
        int pA = p0 + row_, pB = pA + 8;
#pragma unroll
        for (int tt = 0; tt < 4; tt++){
            int e = nq*32 + tt*8 + 2*col_;
            *(float2*)(mt + pA*132 + e) = make_float2(acc[tt].x, acc[tt].y);
            *(float2*)(mt + pB*132 + e) = make_float2(acc[tt].z, acc[tt].w);
        }
    }
    __syncthreads();
    // phase 6: xt (tf32) into r1, gate packed into r2; LN stats
    {
        const float4* x4 = (const float4*)(x + base);
        for (int i = t; i < 64*32; i += 512){
            int p = i >> 5, q = i & 31;
            float4 v = x4[i];
            v.x = __uint_as_float(f2tf(v.x)); v.y = __uint_as_float(f2tf(v.y));
            v.z = __uint_as_float(f2tf(v.z)); v.w = __uint_as_float(f2tf(v.w));
            *(float4*)(xt + p*132 + q*4) = v;
        }
        const float4* s2 = (const float4*)w2p;
        const float4* st = (const float4*)wtp;
        for (int i = t; i < 2048; i += 512){
            ((float4*)r2)[i] = s2[i];
            ((float4*)r2)[2048 + i] = st[i];
        }
    }
    for (int p = warp*4; p < warp*4 + 4; p++){
        float4 v = *(const float4*)(mt + p*132 + lane*4);
        float s = v.x + v.y + v.z + v.w;
        s += __shfl_xor_sync(0xffffffffu, s, 16);
        s += __shfl_xor_sync(0xffffffffu, s, 8);
        s += __shfl_xor_sync(0xffffffffu, s, 4);
        s += __shfl_xor_sync(0xffffffffu, s, 2);
        s += __shfl_xor_sync(0xffffffffu, s, 1);
        float mu = s * (1.f/128.f);
        float dx = v.x - mu, dy = v.y - mu, dz = v.z - mu, dww = v.w - mu;
        float q = dx*dx + dy*dy + dz*dz + dww*dww;
        q += __shfl_xor_sync(0xffffffffu, q, 16);
        q += __shfl_xor_sync(0xffffffffu, q, 8);
        q += __shfl_xor_sync(0xffffffffu, q, 4);
        q += __shfl_xor_sync(0xffffffffu, q, 2);
        q += __shfl_xor_sync(0xffffffffu, q, 1);
        if (lane == 0){
            mus[p] = mu;
            rss[p] = rsqrtf(q * (1.f/128.f) + 1e-5f);
        }
    }
    __syncthreads();
    int p0 = (warp >> 2) * 16;
    int cq = warp & 3;
    int pA = p0 + row_, pB = pA + 8;
    // phase 7: gate GEMM + LN combine -> fs (r3, tf32)
#pragma unroll 1
    for (int nt = 0; nt < 4; nt++){
        int c0 = cq*32 + nt*8;
        int kb = (c0 >> 5) << 5;
        int tile = cq*4 + nt;
        float4 acc = make_float4(0.f,0.f,0.f,0.f);
#pragma unroll
        for (int k = 0; k < 4; k++){
            int kc = kb + k*8;
            const float* xrA = xt + pA*132 + kc + col_;
            uint32_t a0 = __float_as_uint(xrA[0]);
            uint32_t a1 = __float_as_uint(xrA[8*132]);
            uint32_t a2 = __float_as_uint(xrA[4]);
            uint32_t a3 = __float_as_uint(xrA[8*132 + 4]);
            float4 bw = ((const float4*)r2)[(tile*4 + k)*32 + lane];
            mma8(acc, a0, a1, a2, a3, __float_as_uint(bw.x), __float_as_uint(bw.y));
            mma8(acc, a0, a1, a2, a3, __float_as_uint(bw.z), __float_as_uint(bw.w));
        }
        int cc = c0 + 2*col_;
        float g0 = gb[cc], g1 = gb[cc + 1], b0 = gb[128 + cc], b1 = gb[128 + cc + 1];
        float vx = fmaf((mt[pA*132 + cc]     - mus[pA]) * rss[pA], g0, b0) * siluf(acc.x);
        float vy = fmaf((mt[pA*132 + cc + 1] - mus[pA]) * rss[pA], g1, b1) * siluf(acc.y);
        float vz = fmaf((mt[pB*132 + cc]     - mus[pB]) * rss[pB], g0, b0) * siluf(acc.z);
        float vw = fmaf((mt[pB*132 + cc + 1] - mus[pB]) * rss[pB], g1, b1) * siluf(acc.w);
        *(float2*)(r3 + pA*132 + cc) = make_float2(__uint_as_float(f2tf(vx)), __uint_as_float(f2tf(vy)));
        *(float2*)(r3 + pB*132 + cc) = make_float2(__uint_as_float(f2tf(vz)), __uint_as_float(f2tf(vw)));
    }
    __syncwarp();
    // phase 8: final grouped1x1 -> out  (wtp fragments live at float4 offset 2048 in r2)
#pragma unroll 1
    for (int nt = 0; nt < 4; nt++){
        int c0 = cq*32 + nt*8;
        int kb = (c0 >> 5) << 5;
        int tile = cq*4 + nt;
        float4 acc = make_float4(0.f,0.f,0.f,0.f);
#pragma unroll
        for (int k = 0; k < 4; k++){
            int kc = kb + k*8;
            const float* frA = r3 + pA*132 + kc + col_;
            uint32_t a0 = __float_as_uint(frA[0]);
            uint32_t a1 = __float_as_uint(frA[8*132]);
            uint32_t a2 = __float_as_uint(frA[4]);
            uint32_t a3 = __float_as_uint(frA[8*132 + 4]);
            float4 bw = ((const float4*)r2)[2048 + (tile*4 + k)*32 + lane];
            mma8(acc, a0, a1, a2, a3, __float_as_uint(bw.x), __float_as_uint(bw.y));
            mma8(acc, a0, a1, a2, a3, __float_as_uint(bw.z), __float_as_uint(bw.w));
        }
        int cc = c0 + 2*col_;
        *(float2*)(out + (size_t)(pix0 + pA)*128 + cc) = make_float2(acc.x, acc.y);
        *(float2*)(out + (size_t)(pix0 + pB)*128 + cc) = make_float2(acc.z, acc.w);
    }
}

// ----------------------------------------------------------------
extern "C" void kernel_launch(void* const* d_in, const int* in_sizes, int n_in,
                              void* d_out, int out_size){
    const float* x        = (const float*)d_in[0];
    const float* w1       = (const float*)d_in[1];
    const float* dw       = (const float*)d_in[2];
    const float* in_proj  = (const float*)d_in[3];
    const float* conv1d_w = (const float*)d_in[4];
    const float* conv1d_b = (const float*)d_in[5];
    const float* x_proj_w = (const float*)d_in[6];
    const float* dt_proj_w= (const float*)d_in[7];
    const float* dt_proj_b= (const float*)d_in[8];
    const float* A_log    = (const float*)d_in[9];
    const float* D_param  = (const float*)d_in[10];
    const float* out_proj = (const float*)d_in[11];
    const float* gamma    = (const float*)d_in[12];
    const float* beta     = (const float*)d_in[13];
    const float* w2       = (const float*)d_in[14];
    const float* wout     = (const float*)d_in[15];
    float* out = (float*)d_out;

    float *t1, *xs, *u0, *z, *u, *dl, *Bm, *Cm, *Pg, *hE, *h0;
    float *wip, *wop, *w2p, *wtp, *wxp;
    cudaGetSymbolAddress((void**)&t1, g_t1);
    cudaGetSymbolAddress((void**)&xs, g_xs);
    cudaGetSymbolAddress((void**)&u0, g_u0);
    cudaGetSymbolAddress((void**)&z,  g_z);
    cudaGetSymbolAddress((void**)&u,  g_u);
    cudaGetSymbolAddress((void**)&dl, g_dl);
    cudaGetSymbolAddress((void**)&Bm, g_Bm);
    cudaGetSymbolAddress((void**)&Cm, g_Cm);
    cudaGetSymbolAddress((void**)&Pg, g_P);
    cudaGetSymbolAddress((void**)&hE, g_hE);
    cudaGetSymbolAddress((void**)&h0, g_h0);
    cudaGetSymbolAddress((void**)&wip, g_wip);
    cudaGetSymbolAddress((void**)&wop, g_wop);
    cudaGetSymbolAddress((void**)&w2p, g_w2p);
    cudaGetSymbolAddress((void**)&wtp, g_wtp);
    cudaGetSymbolAddress((void**)&wxp, g_wxp);

    const int smemI = (256*132 + 16384) * sizeof(float);
    const int smemX = (8448*3 + 6144 + 64*XDS) * sizeof(float);
    const int smemM = (17408 + 16896 + 8448 + 8448 + 64 + 64 + 256) * sizeof(float);
    static int attr_done = 0;
    if (!attr_done){
        cudaFuncSetAttribute(k_inproj, cudaFuncAttributeMaxDynamicSharedMemorySize, smemI);
        cudaFuncSetAttribute(k_cxp2,  cudaFuncAttributeMaxDynamicSharedMemorySize, smemX);
        cudaFuncSetAttribute(k_mega2, cudaFuncAttributeMaxDynamicSharedMemorySize, smemM);
        attr_done = 1;
    }

    k_prep<<<118, 256>>>(in_proj, out_proj, w2, wout, x_proj_w, wip, wop, w2p, wtp, wxp);
    k_g1<<<NPIX/32, 256>>>(x, w1, t1);
    k_dw<<<NPIX*32/256, 256>>>(t1, dw, xs);
    k_inproj<<<NPIX/256, 512, smemI>>>(xs, wip, u0, z);
    k_cxp2<<<NPIX/64, 512, smemX>>>(u0, conv1d_w, conv1d_b, wxp, dt_proj_w, dt_proj_b,
                                    A_log, u, dl, Bm, Cm, Pg, hE);
    k_scanB<<<64, 128>>>(Pg, hE, h0);
    k_mega2<<<BB*NC, 512, smemM>>>(dl, u, z, Bm, Cm, A_log, D_param, h0,
                                   wop, gamma, beta, x, w2p, wtp, out);
}

// round 11
// speedup vs baseline: 8.8771x; 1.1195x over previous
#include <cuda_runtime.h>
#include <math.h>
#include <stdint.h>

// Problem constants
#define BB 8
#define HH 64
#define WW 64
#define CC 128
#define DD 128
#define LL 4096            // H*W
#define NPIX (BB*LL)       // 32768
#define NS 8               // D_STATE
#define RR 8               // DT_RANK

#define CS 64              // chunk size (steps)
#define NC (LL/CS)         // 64 chunks per batch

// Scratch (device globals; no allocations allowed)
__device__ float g_t1[NPIX*DD];
__device__ float g_xs[NPIX*DD];
__device__ float g_u0[NPIX*DD];
__device__ float g_z [NPIX*DD];
__device__ float g_u [NPIX*DD];
__device__ float g_dl[NPIX*DD];
__device__ float g_Bm[NPIX*NS];
__device__ float g_Cm[NPIX*NS];
__device__ float g_P [BB*NC*1024];
__device__ float g_hE[BB*NC*1024];
__device__ float g_h0[BB*NC*1024];
// fragment-packed tf32 hi/lo weights: float4 {bh0, bh1, bl0, bl1} per (tile,k,lane)
__device__ float g_wip[65536];   // in_proj: 32 tiles x 16 k x 32 lanes
__device__ float g_wop[32768];   // out_proj: 16 tiles x 16 k x 32 lanes
__device__ float g_w2p[8192];    // w2 gate: 16 tiles x 4 k x 32 lanes
__device__ float g_wtp[8192];    // wout:    16 tiles x 4 k x 32 lanes
__device__ float g_wxp[6144];    // x_proj:  3 tiles x 16 k x 32 lanes

__device__ __forceinline__ float siluf(float v){ return v / (1.f + __expf(-v)); }

__device__ __forceinline__ uint32_t f2tf(float x){
    uint32_t r; asm("cvt.rna.tf32.f32 %0, %1;" : "=r"(r) : "f"(x)); return r;
}
__device__ __forceinline__ void mma8(float4& c, uint32_t a0, uint32_t a1, uint32_t a2, uint32_t a3,
                                     uint32_t b0, uint32_t b1){
    asm volatile("mma.sync.aligned.m16n8k8.row.col.f32.tf32.tf32.f32 "
                 "{%0,%1,%2,%3},{%4,%5,%6,%7},{%8,%9},{%0,%1,%2,%3};\n"
                 : "+f"(c.x), "+f"(c.y), "+f"(c.z), "+f"(c.w)
                 : "r"(a0), "r"(a1), "r"(a2), "r"(a3), "r"(b0), "r"(b1));
}
__device__ __forceinline__ float4 pack_hl(float v0, float v1){
    float h0 = __uint_as_float(f2tf(v0));
    float h1 = __uint_as_float(f2tf(v1));
    return make_float4(h0, h1, v0 - h0, v1 - h1);
}

// ---------------------------------------------------------------- K0: weight fragment-pack prep
__global__ void k_prep(const float* __restrict__ wi, const float* __restrict__ wo,
                       const float* __restrict__ w2, const float* __restrict__ wt,
                       const float* __restrict__ wx,
                       float* wip, float* wop, float* w2p, float* wtp, float* wxp){
    int i = blockIdx.x * 256 + threadIdx.x;
    if (i >= 30208) return;
    if (i < 16384){
        int lane = i & 31, k = (i >> 5) & 15, tile = i >> 9;
        int row = lane >> 2, col = lane & 3;
        int e = tile*8 + row, kc = k*8 + col;
        ((float4*)wip)[i] = pack_hl(wi[e*128 + kc], wi[e*128 + kc + 4]);
    } else if (i < 24576){
        int j = i - 16384;
        int lane = j & 31, k = (j >> 5) & 15, tile = j >> 9;
        int row = lane >> 2, col = lane & 3;
        int e = tile*8 + row, kc = k*8 + col;
        ((float4*)wop)[j] = pack_hl(wo[e*128 + kc], wo[e*128 + kc + 4]);
    } else if (i < 26624){
        int j = i - 24576;
        int lane = j & 31, k = (j >> 5) & 3, tile = j >> 7;
        int row = lane >> 2, col = lane & 3;
        int e = tile*8 + row;
        ((float4*)w2p)[j] = pack_hl(w2[e*32 + k*8 + col], w2[e*32 + k*8 + col + 4]);
    } else if (i < 28672){
        int j = i - 26624;
        int lane = j & 31, k = (j >> 5) & 3, tile = j >> 7;
        int row = lane >> 2, col = lane & 3;
        int e = tile*8 + row;
        ((float4*)wtp)[j] = pack_hl(wt[e*32 + k*8 + col], wt[e*32 + k*8 + col + 4]);
    } else {
        int j = i - 28672;
        int lane = j & 31, k = (j >> 5) & 15, tile = j >> 9;
        int row = lane >> 2, col = lane & 3;
        int e = tile*8 + row, kc = k*8 + col;
        ((float4*)wxp)[j] = pack_hl(wx[e*128 + kc], wx[e*128 + kc + 4]);
    }
}

// ---------------------------------------------------------------- K1: grouped 1x1
__global__ void __launch_bounds__(256) k_g1(const float* __restrict__ x,
                                            const float* __restrict__ w,
                                            float* __restrict__ out){
    __shared__ float xt[32*128];
    int pix0 = blockIdx.x * 32;
    const float4* x4 = (const float4*)(x + (size_t)pix0*128);
    for (int i = threadIdx.x; i < 32*32; i += 256) ((float4*)xt)[i] = x4[i];
    __syncthreads();
    int t = threadIdx.x;
    int c = t & 127, half = t >> 7;
    int g = c >> 5;
    float4 wr[8];
#pragma unroll
    for (int i = 0; i < 8; i++) wr[i] = ((const float4*)(w + c*32))[i];
    const float* xb = xt + (half*16)*128 + g*32;
    float* ob = out + ((size_t)pix0 + half*16)*128 + c;
#pragma unroll
    for (int p = 0; p < 16; p++){
        const float* xr = xb + p*128;
        float a = 0.f;
#pragma unroll
        for (int i = 0; i < 8; i++){
            float4 xv = *(const float4*)(xr + i*4);
            a = fmaf(wr[i].x, xv.x, a); a = fmaf(wr[i].y, xv.y, a);
            a = fmaf(wr[i].z, xv.z, a); a = fmaf(wr[i].w, xv.w, a);
        }
        ob[(size_t)p*128] = a;
    }
}

// ---------------------------------------------------------------- K2: depthwise 3x3 + silu
__global__ void k_dw(const float* __restrict__ t1, const float* __restrict__ dw,
                     float* __restrict__ out){
    int idx = blockIdx.x * 256 + threadIdx.x;
    int d4 = idx & 31; int pix = idx >> 5;
    int wc = pix & 63; int h = (pix >> 6) & 63; int b = pix >> 12;
    int d = d4 << 2;
    float4 acc = make_float4(0.f, 0.f, 0.f, 0.f);
#pragma unroll
    for (int kh = 0; kh < 3; kh++){
        int hh = h + kh - 1; if (hh < 0 || hh >= 64) continue;
#pragma unroll
        for (int kw = 0; kw < 3; kw++){
            int ww = wc + kw - 1; if (ww < 0 || ww >= 64) continue;
            float4 tv = *(const float4*)(t1 + (((b*64 + hh)*64 + ww) << 7) + d);
            float4 wv = *(const float4*)(dw + (kh*3 + kw)*128 + d);
            acc.x = fmaf(tv.x, wv.x, acc.x); acc.y = fmaf(tv.y, wv.y, acc.y);
            acc.z = fmaf(tv.z, wv.z, acc.z); acc.w = fmaf(tv.w, wv.w, acc.w);
        }
    }
    float4 r; r.x = siluf(acc.x); r.y = siluf(acc.y); r.z = siluf(acc.z); r.w = siluf(acc.w);
    *(float4*)(out + (size_t)pix*128 + d) = r;
}

// ---------------------------------------------------------------- K3: in_proj via tf32 mma
// 512 thr, 128 pixels/block, 256 blocks, 2 blocks/SM. Weights direct-LDG (L1/L2 hot).
__global__ void __launch_bounds__(512, 2) k_inproj(const float* __restrict__ xs,
                       const float* __restrict__ wip,
                       float* __restrict__ ub, float* __restrict__ zb){
    extern __shared__ float sm[];
    float* xt = sm;              // 128*132 = 16896 fl
    int tid = threadIdx.x;
    int pix0 = blockIdx.x * 128;
    {
        const float4* xs4 = (const float4*)(xs + (size_t)pix0*128);
        for (int i = tid; i < 128*32; i += 512){
            int p = i >> 5, q = i & 31;
            float4 v = xs4[i];
            v.x = __uint_as_float(f2tf(v.x)); v.y = __uint_as_float(f2tf(v.y));
            v.z = __uint_as_float(f2tf(v.z)); v.w = __uint_as_float(f2tf(v.w));
            *(float4*)(xt + p*132 + q*4) = v;
        }
    }
    __syncthreads();
    int warp = tid >> 5, lane = tid & 31;
    int row_ = lane >> 2, col_ = lane & 3;
    int mt_ = warp >> 1, nh = warp & 1;
    int p0 = mt_ * 16;
    const float* xrA = xt + (p0 + row_)*132 + col_;
    const float* xrB = xrA + 8*132;
    const float4* wip4 = (const float4*)wip;
#pragma unroll 1
    for (int g = 0; g < 4; g++){
        float4 acc[4];
#pragma unroll
        for (int tt = 0; tt < 4; tt++) acc[tt] = make_float4(0.f,0.f,0.f,0.f);
#pragma unroll 4
        for (int k = 0; k < 16; k++){
            int k8 = k*8;
            uint32_t a0 = __float_as_uint(xrA[k8]);
            uint32_t a1 = __float_as_uint(xrB[k8]);
            uint32_t a2 = __float_as_uint(xrA[k8 + 4]);
            uint32_t a3 = __float_as_uint(xrB[k8 + 4]);
#pragma unroll
            for (int tt = 0; tt < 4; tt++){
                int tile = g*8 + nh*4 + tt;
                float4 bw = __ldg(wip4 + tile*512 + k*32 + lane);
                mma8(acc[tt], a0, a1, a2, a3, __float_as_uint(bw.x), __float_as_uint(bw.y));
                mma8(acc[tt], a0, a1, a2, a3, __float_as_uint(bw.z), __float_as_uint(bw.w));
            }
        }
        int pixA = pix0 + p0 + row_;
        int pixB = pixA + 8;
#pragma unroll
        for (int tt = 0; tt < 4; tt++){
            int e0 = g*64 + (nh*4 + tt)*8 + 2*col_;
            float* base = (g < 2) ? (ub + e0) : (zb + e0 - 128);
            *(float2*)(base + (size_t)pixA*128) = make_float2(acc[tt].x, acc[tt].y);
            *(float2*)(base + (size_t)pixB*128) = make_float2(acc[tt].z, acc[tt].w);
        }
    }
}

// ---------------------------------------------------------------- K4: fused conv1d + x_proj(mma) + dt_proj + scanA
// 512 thr, 64 pixels/block = one scan chunk; 512 blocks; 2 blocks/SM (74.2 KB).
#define XDS 26
__global__ void __launch_bounds__(512, 2) k_cxp2(const float* __restrict__ u0,
                        const float* __restrict__ cw, const float* __restrict__ cb,
                        const float* __restrict__ wxp,
                        const float* __restrict__ dtw, const float* __restrict__ dtb,
                        const float* __restrict__ A_log,
                        float* __restrict__ ug,
                        float* __restrict__ dl, float* __restrict__ Bb, float* __restrict__ Cb,
                        float* __restrict__ Pg, float* __restrict__ hEg){
    extern __shared__ float sm[];
    float* u0s = sm;                 // 66*128 = 8448 ; aliased by sdl (64*128) after conv
    float* su  = sm + 8448;          // 64*132 = 8448 (fp32 conv output)
    float* xd  = sm + 16896;         // 64*XDS = 1664
    float* sdl = u0s;
    int pix0 = blockIdx.x * 64;
    int b = blockIdx.x >> 6;
    int c = blockIdx.x & 63;
    int l0 = pix0 & (LL - 1);
    int t = threadIdx.x, warp = t >> 5, lane = t & 31;
    {
        const float4* u4 = (const float4*)(u0 + ((size_t)pix0 - 2)*128);
        for (int i = t; i < 66*32; i += 512){
            int p = i >> 5;
            float4 v = make_float4(0.f,0.f,0.f,0.f);
            if (!(l0 == 0 && p < 2)) v = u4[i];
            ((float4*)u0s)[i] = v;
        }
    }
    __syncthreads();
    // conv1d + silu -> su (fp32 smem) + ug (global)
    {
        int d = t & 127, ph = t >> 7;
        float w0 = cw[d*3], w1c = cw[d*3 + 1], w2c = cw[d*3 + 2];
        float bias = cb[d];
#pragma unroll 4
        for (int p = ph*16; p < ph*16 + 16; p++){
            float a = fmaf(w2c, u0s[(p + 2)*128 + d],
                      fmaf(w1c, u0s[(p + 1)*128 + d],
                      fmaf(w0,  u0s[p*128 + d], bias)));
            a = siluf(a);
            ug[(size_t)(pix0 + p)*128 + d] = a;
            su[p*132 + d] = a;
        }
    }
    __syncthreads();
    // x_proj mma: on-the-fly tf32 split of A; B fragments direct-LDG
    if (warp < 12){
        int m0 = (warp & 3) * 16;
        int ntile = warp >> 2;
        int row_ = lane >> 2, col_ = lane & 3;
        const float* aA = su + (m0 + row_)*132 + col_;
        const float* aB = aA + 8*132;
        const float4* wxp4 = (const float4*)wxp;
        float4 acc = make_float4(0.f,0.f,0.f,0.f);
#pragma unroll 2
        for (int k = 0; k < 16; k++){
            int k8 = k*8;
            float f0 = aA[k8], f1 = aB[k8], f2 = aA[k8 + 4], f3 = aB[k8 + 4];
            uint32_t h0 = f2tf(f0), h1 = f2tf(f1), h2 = f2tf(f2), h3 = f2tf(f3);
            uint32_t l0_ = __float_as_uint(f0 - __uint_as_float(h0));
            uint32_t l1  = __float_as_uint(f1 - __uint_as_float(h1));
            uint32_t l2  = __float_as_uint(f2 - __uint_as_float(h2));
            uint32_t l3  = __float_as_uint(f3 - __uint_as_float(h3));
            float4 bw = __ldg(wxp4 + (ntile*16 + k)*32 + lane);
            uint32_t bh0 = __float_as_uint(bw.x), bh1 = __float_as_uint(bw.y);
            uint32_t bl0 = __float_as_uint(bw.z), bl1 = __float_as_uint(bw.w);
            mma8(acc, h0, h1, h2, h3, bh0, bh1);
            mma8(acc, h0, h1, h2, h3, bl0, bl1);
            mma8(acc, l0_, l1, l2, l3, bh0, bh1);
        }
        int pA = m0 + row_, pB = pA + 8;
        int cc = ntile*8 + 2*col_;
        *(float2*)(xd + pA*XDS + cc) = make_float2(acc.x, acc.y);
        *(float2*)(xd + pB*XDS + cc) = make_float2(acc.z, acc.w);
    }
    __syncthreads();   // xd valid; u0s dead -> sdl alias ok
    // dt_proj + softplus -> dl (global) + sdl (smem)
    {
        int d = t & 127, ph = t >> 7;
        float4 wa = ((const float4*)(dtw + d*8))[0];
        float4 wb = ((const float4*)(dtw + d*8))[1];
        float bias = dtb[d];
#pragma unroll 4
        for (int p = ph*16; p < ph*16 + 16; p++){
            const float* xr = xd + p*XDS;
            float a = bias;
            a = fmaf(xr[0], wa.x, a); a = fmaf(xr[1], wa.y, a);
            a = fmaf(xr[2], wa.z, a); a = fmaf(xr[3], wa.w, a);
            a = fmaf(xr[4], wb.x, a); a = fmaf(xr[5], wb.y, a);
            a = fmaf(xr[6], wb.z, a); a = fmaf(xr[7], wb.w, a);
            float sp = (a > 20.f) ? a : log1pf(__expf(a));
            dl[(size_t)(pix0 + p)*128 + d] = sp;
            sdl[p*128 + d] = sp;
        }
    }
    {
        int p = t >> 3, n = t & 7;
        Bb[(pix0 + p)*8 + n] = xd[p*XDS + 8 + n];
        Cb[(pix0 + p)*8 + n] = xd[p*XDS + 16 + n];
    }
    __syncthreads();
    // scanA phase: 2 states/thread
    {
        int d = t >> 2, np = (t & 3) * 2;
        float Av0 = -__expf(A_log[d*8 + np]);
        float Av1 = -__expf(A_log[d*8 + np + 1]);
        float h0 = 0.f, h1 = 0.f, P0 = 1.f, P1 = 1.f;
#pragma unroll 4
        for (int l = 0; l < CS; l++){
            float de = sdl[l*128 + d];
            float uu = su[l*132 + d];
            float du = de * uu;
            float2 Bv = *(const float2*)(xd + l*XDS + 8 + np);
            float dA0 = __expf(de * Av0);
            float dA1 = __expf(de * Av1);
            P0 *= dA0; P1 *= dA1;
            h0 = fmaf(dA0, h0, du * Bv.x);
            h1 = fmaf(dA1, h1, du * Bv.y);
        }
        size_t oidx = (size_t)(b*NC + c)*1024 + d*8 + np;
        *(float2*)(Pg + oidx) = make_float2(P0, P1);
        *(float2*)(hEg + oidx) = make_float2(h0, h1);
    }
}

// ---------------------------------------------------------------- K5: chunk combine
__global__ void k_scanB(const float* __restrict__ Pg, const float* __restrict__ hEg,
                        float* __restrict__ h0g){
    int j = blockIdx.x * 128 + threadIdx.x;
    int b = j >> 10, dn = j & 1023;
    float h = 0.f;
#pragma unroll 8
    for (int c = 0; c < NC; c++){
        int idx = (b*NC + c)*1024 + dn;
        h0g[idx] = h;
        h = fmaf(Pg[idx], h, hEg[idx]);
    }
}

// ---------------------------------------------------------------- K6: MEGA2 = scanC + out_proj + LN + gate GEMMs
// Weights direct-LDG; smem 138.8 KB.
__global__ void __launch_bounds__(512, 1) k_mega2(
        const float* __restrict__ dl, const float* __restrict__ u,
        const float* __restrict__ z, const float* __restrict__ Bb,
        const float* __restrict__ Cb, const float* __restrict__ A_log,
        const float* __restrict__ Dp, const float* __restrict__ h0g,
        const float* __restrict__ wop,
        const float* __restrict__ gamma, const float* __restrict__ beta,
        const float* __restrict__ x,
        const float* __restrict__ w2p, const float* __restrict__ wtp,
        float* __restrict__ out){
    extern __shared__ float sm[];
    float* r1 = sm;               // 17408: sdl|su|sB|sC ; later xt (8448)
    float* r3 = sm + 17408;       // 8448: y -> fs
    float* mt = r3 + 8448;        // 8448
    float* mus = mt + 8448;       // 64
    float* rss = mus + 64;        // 64
    float* gb  = rss + 64;        // 256
    float* sdl = r1;
    float* su  = r1 + 8192;
    float* sB  = r1 + 16384;
    float* sC  = r1 + 16896;
    float* xt  = r1;
    const float4* wop4 = (const float4*)wop;
    const float4* w2p4 = (const float4*)w2p;
    const float4* wtp4 = (const float4*)wtp;
    int b = blockIdx.x >> 6;
    int c = blockIdx.x & (NC - 1);
    int t = threadIdx.x, warp = t >> 5, lane = t & 31;
    int row_ = lane >> 2, col_ = lane & 3;
    int pix0 = b*LL + c*CS;
    size_t base = (size_t)pix0*128;
    // phase 1: stage scan inputs + gamma/beta
    {
        const float4* dl4 = (const float4*)(dl + base);
        const float4* u4  = (const float4*)(u + base);
        for (int i = t; i < CS*32; i += 512){
            ((float4*)sdl)[i] = dl4[i];
            ((float4*)su)[i]  = u4[i];
        }
        int nb = pix0*8;
        if (t < CS*8){ sB[t] = Bb[nb + t]; sC[t] = Cb[nb + t]; }
        if (t < 128){ gb[t] = gamma[t]; gb[128 + t] = beta[t]; }
    }
    __syncthreads();
    // phase 2: scan
    {
        int d = t >> 2, np = (t & 3) * 2;
        float Av0 = -__expf(A_log[d*8 + np]);
        float Av1 = -__expf(A_log[d*8 + np + 1]);
        float2 h = *(const float2*)(h0g + (size_t)(b*NC + c)*1024 + d*8 + np);
#pragma unroll 4
        for (int l = 0; l < CS; l++){
            float de = sdl[l*128 + d];
            float uu = su[l*128 + d];
            float du = de * uu;
            float2 Bv = *(const float2*)(sB + l*8 + np);
            float2 Cv = *(const float2*)(sC + l*8 + np);
            h.x = fmaf(__expf(de * Av0), h.x, du * Bv.x);
            h.y = fmaf(__expf(de * Av1), h.y, du * Bv.y);
            float y = h.x * Cv.x + h.y * Cv.y;
            y += __shfl_xor_sync(0xffffffffu, y, 1);
            y += __shfl_xor_sync(0xffffffffu, y, 2);
            if ((t & 3) == 0) r3[l*132 + d] = y;
        }
    }
    __syncthreads();
    // phase 3: y + u*D, gate silu(z), tf32
    {
        for (int i = t; i < CS*128; i += 512){
            int l = i >> 7, d = i & 127;
            float val = fmaf(su[l*128 + d], Dp[d], r3[l*132 + d]);
            val *= siluf(z[base + i]);
            r3[l*132 + d] = __uint_as_float(f2tf(val));
        }
    }
    __syncthreads();
    // phase 5: out_proj GEMM (16 warps: 4 m-tiles x 4 n-quarters; B direct-LDG)
    {
        int p0 = (warp >> 2) * 16;
        int nq = warp & 3;
        const float* yrA = r3 + (p0 + row_)*132 + col_;
        const float* yrB = yrA + 8*132;
        float4 acc[4];
#pragma unroll
        for (int tt = 0; tt < 4; tt++) acc[tt] = make_float4(0.f,0.f,0.f,0.f);
#pragma unroll 4
        for (int k = 0; k < 16; k++){
            int k8 = k*8;
            uint32_t a0 = __float_as_uint(yrA[k8]);
            uint32_t a1 = __float_as_uint(yrB[k8]);
            uint32_t a2 = __float_as_uint(yrA[k8 + 4]);
            uint32_t a3 = __float_as_uint(yrB[k8 + 4]);
#pragma unroll
            for (int tt = 0; tt < 4; tt++){
                int tile = nq*4 + tt;
                float4 bw = __ldg(wop4 + tile*512 + k*32 + lane);
                mma8(acc[tt], a0, a1, a2, a3, __float_as_uint(bw.x), __float_as_uint(bw.y));
                mma8(acc[tt], a0, a1, a2, a3, __float_as_uint(bw.z), __float_as_uint(bw.w));
            }
        }
        int pA = p0 + row_, pB = pA + 8;
#pragma unroll
        for (int tt = 0; tt < 4; tt++){
            int e = nq*32 + tt*8 + 2*col_;
            *(float2*)(mt + pA*132 + e) = make_float2(acc[tt].x, acc[tt].y);
            *(float2*)(mt + pB*132 + e) = make_float2(acc[tt].z, acc[tt].w);
        }
    }
    __syncthreads();   // r1 scan data dead, mt valid
    // phase 6: xt (tf32) into r1; LN stats
    {
        const float4* x4 = (const float4*)(x + base);
        for (int i = t; i < 64*32; i += 512){
            int p = i >> 5, q = i & 31;
            float4 v = x4[i];
            v.x = __uint_as_float(f2tf(v.x)); v.y = __uint_as_float(f2tf(v.y));
            v.z = __uint_as_float(f2tf(v.z)); v.w = __uint_as_float(f2tf(v.w));
            *(float4*)(xt + p*132 + q*4) = v;
        }
    }
    for (int p = warp*4; p < warp*4 + 4; p++){
        float4 v = *(const float4*)(mt + p*132 + lane*4);
        float s = v.x + v.y + v.z + v.w;
        s += __shfl_xor_sync(0xffffffffu, s, 16);
        s += __shfl_xor_sync(0xffffffffu, s, 8);
        s += __shfl_xor_sync(0xffffffffu, s, 4);
        s += __shfl_xor_sync(0xffffffffu, s, 2);
        s += __shfl_xor_sync(0xffffffffu, s, 1);
        float mu = s * (1.f/128.f);
        float dx = v.x - mu, dy = v.y - mu, dz = v.z - mu, dww = v.w - mu;
        float q = dx*dx + dy*dy + dz*dz + dww*dww;
        q += __shfl_xor_sync(0xffffffffu, q, 16);
        q += __shfl_xor_sync(0xffffffffu, q, 8);
        q += __shfl_xor_sync(0xffffffffu, q, 4);
        q += __shfl_xor_sync(0xffffffffu, q, 2);
        q += __shfl_xor_sync(0xffffffffu, q, 1);
        if (lane == 0){
            mus[p] = mu;
            rss[p] = rsqrtf(q * (1.f/128.f) + 1e-5f);
        }
    }
    __syncthreads();
    int p0 = (warp >> 2) * 16;
    int cq = warp & 3;
    int pA = p0 + row_, pB = pA + 8;
    // phase 7: gate GEMM + LN combine -> fs (r3, tf32)
#pragma unroll 1
    for (int nt = 0; nt < 4; nt++){
        int c0 = cq*32 + nt*8;
        int kb = (c0 >> 5) << 5;
        int tile = cq*4 + nt;
        float4 acc = make_float4(0.f,0.f,0.f,0.f);
#pragma unroll
        for (int k = 0; k < 4; k++){
            int kc = kb + k*8;
            const float* xrA = xt + pA*132 + kc + col_;
            uint32_t a0 = __float_as_uint(xrA[0]);
            uint32_t a1 = __float_as_uint(xrA[8*132]);
            uint32_t a2 = __float_as_uint(xrA[4]);
            uint32_t a3 = __float_as_uint(xrA[8*132 + 4]);
            float4 bw = __ldg(w2p4 + (tile*4 + k)*32 + lane);
            mma8(acc, a0, a1, a2, a3, __float_as_uint(bw.x), __float_as_uint(bw.y));
            mma8(acc, a0, a1, a2, a3, __float_as_uint(bw.z), __float_as_uint(bw.w));
        }
        int cc = c0 + 2*col_;
        float g0 = gb[cc], g1 = gb[cc + 1], b0 = gb[128 + cc], b1 = gb[128 + cc + 1];
        float vx = fmaf((mt[pA*132 + cc]     - mus[pA]) * rss[pA], g0, b0) * siluf(acc.x);
        float vy = fmaf((mt[pA*132 + cc + 1] - mus[pA]) * rss[pA], g1, b1) * siluf(acc.y);
        float vz = fmaf((mt[pB*132 + cc]     - mus[pB]) * rss[pB], g0, b0) * siluf(acc.z);
        float vw = fmaf((mt[pB*132 + cc + 1] - mus[pB]) * rss[pB], g1, b1) * siluf(acc.w);
        *(float2*)(r3 + pA*132 + cc) = make_float2(__uint_as_float(f2tf(vx)), __uint_as_float(f2tf(vy)));
        *(float2*)(r3 + pB*132 + cc) = make_float2(__uint_as_float(f2tf(vz)), __uint_as_float(f2tf(vw)));
    }
    __syncwarp();
    // phase 8: final grouped1x1 -> out
#pragma unroll 1
    for (int nt = 0; nt < 4; nt++){
        int c0 = cq*32 + nt*8;
        int kb = (c0 >> 5) << 5;
        int tile = cq*4 + nt;
        float4 acc = make_float4(0.f,0.f,0.f,0.f);
#pragma unroll
        for (int k = 0; k < 4; k++){
            int kc = kb + k*8;
            const float* frA = r3 + pA*132 + kc + col_;
            uint32_t a0 = __float_as_uint(frA[0]);
            uint32_t a1 = __float_as_uint(frA[8*132]);
            uint32_t a2 = __float_as_uint(frA[4]);
            uint32_t a3 = __float_as_uint(frA[8*132 + 4]);
            float4 bw = __ldg(wtp4 + (tile*4 + k)*32 + lane);
            mma8(acc, a0, a1, a2, a3, __float_as_uint(bw.x), __float_as_uint(bw.y));
            mma8(acc, a0, a1, a2, a3, __float_as_uint(bw.z), __float_as_uint(bw.w));
        }
        int cc = c0 + 2*col_;
        *(float2*)(out + (size_t)(pix0 + pA)*128 + cc) = make_float2(acc.x, acc.y);
        *(float2*)(out + (size_t)(pix0 + pB)*128 + cc) = make_float2(acc.z, acc.w);
    }
}

// ----------------------------------------------------------------
extern "C" void kernel_launch(void* const* d_in, const int* in_sizes, int n_in,
                              void* d_out, int out_size){
    const float* x        = (const float*)d_in[0];
    const float* w1       = (const float*)d_in[1];
    const float* dw       = (const float*)d_in[2];
    const float* in_proj  = (const float*)d_in[3];
    const float* conv1d_w = (const float*)d_in[4];
    const float* conv1d_b = (const float*)d_in[5];
    const float* x_proj_w = (const float*)d_in[6];
    const float* dt_proj_w= (const float*)d_in[7];
    const float* dt_proj_b= (const float*)d_in[8];
    const float* A_log    = (const float*)d_in[9];
    const float* D_param  = (const float*)d_in[10];
    const float* out_proj = (const float*)d_in[11];
    const float* gamma    = (const float*)d_in[12];
    const float* beta     = (const float*)d_in[13];
    const float* w2       = (const float*)d_in[14];
    const float* wout     = (const float*)d_in[15];
    float* out = (float*)d_out;

    float *t1, *xs, *u0, *z, *u, *dl, *Bm, *Cm, *Pg, *hE, *h0;
    float *wip, *wop, *w2p, *wtp, *wxp;
    cudaGetSymbolAddress((void**)&t1, g_t1);
    cudaGetSymbolAddress((void**)&xs, g_xs);
    cudaGetSymbolAddress((void**)&u0, g_u0);
    cudaGetSymbolAddress((void**)&z,  g_z);
    cudaGetSymbolAddress((void**)&u,  g_u);
    cudaGetSymbolAddress((void**)&dl, g_dl);
    cudaGetSymbolAddress((void**)&Bm, g_Bm);
    cudaGetSymbolAddress((void**)&Cm, g_Cm);
    cudaGetSymbolAddress((void**)&Pg, g_P);
    cudaGetSymbolAddress((void**)&hE, g_hE);
    cudaGetSymbolAddress((void**)&h0, g_h0);
    cudaGetSymbolAddress((void**)&wip, g_wip);
    cudaGetSymbolAddress((void**)&wop, g_wop);
    cudaGetSymbolAddress((void**)&w2p, g_w2p);
    cudaGetSymbolAddress((void**)&wtp, g_wtp);
    cudaGetSymbolAddress((void**)&wxp, g_wxp);

    const int smemI = (128*132) * sizeof(float);                     // 67.6 KB
    const int smemX = (8448 + 8448 + 64*XDS) * sizeof(float);        // 74.2 KB
    const int smemM = (17408 + 8448 + 8448 + 64 + 64 + 256) * sizeof(float); // 138.8 KB
    static int attr_done = 0;
    if (!attr_done){
        cudaFuncSetAttribute(k_inproj, cudaFuncAttributeMaxDynamicSharedMemorySize, smemI);
        cudaFuncSetAttribute(k_cxp2,  cudaFuncAttributeMaxDynamicSharedMemorySize, smemX);
        cudaFuncSetAttribute(k_mega2, cudaFuncAttributeMaxDynamicSharedMemorySize, smemM);
        attr_done = 1;
    }

    k_prep<<<118, 256>>>(in_proj, out_proj, w2, wout, x_proj_w, wip, wop, w2p, wtp, wxp);
    k_g1<<<NPIX/32, 256>>>(x, w1, t1);
    k_dw<<<NPIX*32/256, 256>>>(t1, dw, xs);
    k_inproj<<<NPIX/128, 512, smemI>>>(xs, wip, u0, z);
    k_cxp2<<<NPIX/64, 512, smemX>>>(u0, conv1d_w, conv1d_b, wxp, dt_proj_w, dt_proj_b,
                                    A_log, u, dl, Bm, Cm, Pg, hE);
    k_scanB<<<64, 128>>>(Pg, hE, h0);
    k_mega2<<<BB*NC, 512, smemM>>>(dl, u, z, Bm, Cm, A_log, D_param, h0,
                                   wop, gamma, beta, x, w2p, wtp, out);
}

// round 12
// speedup vs baseline: 9.1309x; 1.0286x over previous
#include <cuda_runtime.h>
#include <math.h>
#include <stdint.h>

// Problem constants
#define BB 8
#define HH 64
#define WW 64
#define CC 128
#define DD 128
#define LL 4096            // H*W
#define NPIX (BB*LL)       // 32768
#define NS 8               // D_STATE
#define RR 8               // DT_RANK

#define CS 64              // chunk size (steps)
#define NC (LL/CS)         // 64 chunks per batch

// Scratch (device globals; no allocations allowed)
__device__ float g_t1[NPIX*DD];
__device__ float g_xs[NPIX*DD];
__device__ float g_u0[NPIX*DD];
__device__ float g_z [NPIX*DD];
__device__ float g_u [NPIX*DD];
__device__ float g_dl[NPIX*DD];
__device__ float g_Bm[NPIX*NS];
__device__ float g_Cm[NPIX*NS];
__device__ float g_P [BB*NC*1024];
__device__ float g_hE[BB*NC*1024];
__device__ float g_h0[BB*NC*1024];
// fragment-packed tf32 hi/lo weights: float4 {bh0, bh1, bl0, bl1} per (tile,k,lane)
__device__ float g_wip[65536];   // in_proj: 32 tiles x 16 k x 32 lanes
__device__ float g_wop[32768];   // out_proj: 16 tiles x 16 k x 32 lanes
__device__ float g_w2p[8192];    // w2 gate: 16 tiles x 4 k x 32 lanes
__device__ float g_wtp[8192];    // wout:    16 tiles x 4 k x 32 lanes
__device__ float g_wxp[6144];    // x_proj:  3 tiles x 16 k x 32 lanes

__device__ __forceinline__ float siluf(float v){ return v / (1.f + __expf(-v)); }

__device__ __forceinline__ uint32_t f2tf(float x){
    uint32_t r; asm("cvt.rna.tf32.f32 %0, %1;" : "=r"(r) : "f"(x)); return r;
}
__device__ __forceinline__ void mma8(float4& c, uint32_t a0, uint32_t a1, uint32_t a2, uint32_t a3,
                                     uint32_t b0, uint32_t b1){
    asm volatile("mma.sync.aligned.m16n8k8.row.col.f32.tf32.tf32.f32 "
                 "{%0,%1,%2,%3},{%4,%5,%6,%7},{%8,%9},{%0,%1,%2,%3};\n"
                 : "+f"(c.x), "+f"(c.y), "+f"(c.z), "+f"(c.w)
                 : "r"(a0), "r"(a1), "r"(a2), "r"(a3), "r"(b0), "r"(b1));
}
__device__ __forceinline__ float4 pack_hl(float v0, float v1){
    float h0 = __uint_as_float(f2tf(v0));
    float h1 = __uint_as_float(f2tf(v1));
    return make_float4(h0, h1, v0 - h0, v1 - h1);
}

// ---------------------------------------------------------------- K0: weight fragment-pack prep
__global__ void k_prep(const float* __restrict__ wi, const float* __restrict__ wo,
                       const float* __restrict__ w2, const float* __restrict__ wt,
                       const float* __restrict__ wx,
                       float* wip, float* wop, float* w2p, float* wtp, float* wxp){
    int i = blockIdx.x * 256 + threadIdx.x;
    if (i >= 30208) return;
    if (i < 16384){
        int lane = i & 31, k = (i >> 5) & 15, tile = i >> 9;
        int row = lane >> 2, col = lane & 3;
        int e = tile*8 + row, kc = k*8 + col;
        ((float4*)wip)[i] = pack_hl(wi[e*128 + kc], wi[e*128 + kc + 4]);
    } else if (i < 24576){
        int j = i - 16384;
        int lane = j & 31, k = (j >> 5) & 15, tile = j >> 9;
        int row = lane >> 2, col = lane & 3;
        int e = tile*8 + row, kc = k*8 + col;
        ((float4*)wop)[j] = pack_hl(wo[e*128 + kc], wo[e*128 + kc + 4]);
    } else if (i < 26624){
        int j = i - 24576;
        int lane = j & 31, k = (j >> 5) & 3, tile = j >> 7;
        int row = lane >> 2, col = lane & 3;
        int e = tile*8 + row;
        ((float4*)w2p)[j] = pack_hl(w2[e*32 + k*8 + col], w2[e*32 + k*8 + col + 4]);
    } else if (i < 28672){
        int j = i - 26624;
        int lane = j & 31, k = (j >> 5) & 3, tile = j >> 7;
        int row = lane >> 2, col = lane & 3;
        int e = tile*8 + row;
        ((float4*)wtp)[j] = pack_hl(wt[e*32 + k*8 + col], wt[e*32 + k*8 + col + 4]);
    } else {
        int j = i - 28672;
        int lane = j & 31, k = (j >> 5) & 15, tile = j >> 9;
        int row = lane >> 2, col = lane & 3;
        int e = tile*8 + row, kc = k*8 + col;
        ((float4*)wxp)[j] = pack_hl(wx[e*128 + kc], wx[e*128 + kc + 4]);
    }
}

// ---------------------------------------------------------------- K1: grouped 1x1
__global__ void __launch_bounds__(256) k_g1(const float* __restrict__ x,
                                            const float* __restrict__ w,
                                            float* __restrict__ out){
    __shared__ float xt[32*128];
    int pix0 = blockIdx.x * 32;
    const float4* x4 = (const float4*)(x + (size_t)pix0*128);
    for (int i = threadIdx.x; i < 32*32; i += 256) ((float4*)xt)[i] = x4[i];
    __syncthreads();
    int t = threadIdx.x;
    int c = t & 127, half = t >> 7;
    int g = c >> 5;
    float4 wr[8];
#pragma unroll
    for (int i = 0; i < 8; i++) wr[i] = ((const float4*)(w + c*32))[i];
    const float* xb = xt + (half*16)*128 + g*32;
    float* ob = out + ((size_t)pix0 + half*16)*128 + c;
#pragma unroll
    for (int p = 0; p < 16; p++){
        const float* xr = xb + p*128;
        float a = 0.f;
#pragma unroll
        for (int i = 0; i < 8; i++){
            float4 xv = *(const float4*)(xr + i*4);
            a = fmaf(wr[i].x, xv.x, a); a = fmaf(wr[i].y, xv.y, a);
            a = fmaf(wr[i].z, xv.z, a); a = fmaf(wr[i].w, xv.w, a);
        }
        ob[(size_t)p*128] = a;
    }
}

// ---------------------------------------------------------------- K2: depthwise 3x3 + silu
__global__ void k_dw(const float* __restrict__ t1, const float* __restrict__ dw,
                     float* __restrict__ out){
    int idx = blockIdx.x * 256 + threadIdx.x;
    int d4 = idx & 31; int pix = idx >> 5;
    int wc = pix & 63; int h = (pix >> 6) & 63; int b = pix >> 12;
    int d = d4 << 2;
    float4 acc = make_float4(0.f, 0.f, 0.f, 0.f);
#pragma unroll
    for (int kh = 0; kh < 3; kh++){
        int hh = h + kh - 1; if (hh < 0 || hh >= 64) continue;
#pragma unroll
        for (int kw = 0; kw < 3; kw++){
            int ww = wc + kw - 1; if (ww < 0 || ww >= 64) continue;
            float4 tv = *(const float4*)(t1 + (((b*64 + hh)*64 + ww) << 7) + d);
            float4 wv = *(const float4*)(dw + (kh*3 + kw)*128 + d);
            acc.x = fmaf(tv.x, wv.x, acc.x); acc.y = fmaf(tv.y, wv.y, acc.y);
            acc.z = fmaf(tv.z, wv.z, acc.z); acc.w = fmaf(tv.w, wv.w, acc.w);
        }
    }
    float4 r; r.x = siluf(acc.x); r.y = siluf(acc.y); r.z = siluf(acc.z); r.w = siluf(acc.w);
    *(float4*)(out + (size_t)pix*128 + d) = r;
}

// ---------------------------------------------------------------- K3: in_proj via tf32 mma (2 m-tiles per warp)
// 512 thr, 128 pixels/block, 256 blocks. warp = (mp 0..3: 32 px, nq 0..3: 2 tiles/g)
__global__ void __launch_bounds__(512, 2) k_inproj(const float* __restrict__ xs,
                       const float* __restrict__ wip,
                       float* __restrict__ ub, float* __restrict__ zb){
    extern __shared__ float sm[];
    float* xt = sm;              // 128*132
    int tid = threadIdx.x;
    int pix0 = blockIdx.x * 128;
    {
        const float4* xs4 = (const float4*)(xs + (size_t)pix0*128);
        for (int i = tid; i < 128*32; i += 512){
            int p = i >> 5, q = i & 31;
            float4 v = xs4[i];
            v.x = __uint_as_float(f2tf(v.x)); v.y = __uint_as_float(f2tf(v.y));
            v.z = __uint_as_float(f2tf(v.z)); v.w = __uint_as_float(f2tf(v.w));
            *(float4*)(xt + p*132 + q*4) = v;
        }
    }
    __syncthreads();
    int warp = tid >> 5, lane = tid & 31;
    int row_ = lane >> 2, col_ = lane & 3;
    int mp = warp >> 2, nq = warp & 3;
    int m0 = mp * 32;
    const float* xA0 = xt + (m0 + row_)*132 + col_;
    const float* xB0 = xA0 + 8*132;
    const float* xA1 = xA0 + 16*132;
    const float* xB1 = xA1 + 8*132;
    const float4* wip4 = (const float4*)wip;
#pragma unroll 1
    for (int g = 0; g < 4; g++){
        float4 acc[2][2];
#pragma unroll
        for (int mm = 0; mm < 2; mm++)
#pragma unroll
            for (int tt = 0; tt < 2; tt++) acc[mm][tt] = make_float4(0.f,0.f,0.f,0.f);
#pragma unroll 4
        for (int k = 0; k < 16; k++){
            int k8 = k*8;
            uint32_t a0 = __float_as_uint(xA0[k8]);
            uint32_t a1 = __float_as_uint(xB0[k8]);
            uint32_t a2 = __float_as_uint(xA0[k8 + 4]);
            uint32_t a3 = __float_as_uint(xB0[k8 + 4]);
            uint32_t c0 = __float_as_uint(xA1[k8]);
            uint32_t c1 = __float_as_uint(xB1[k8]);
            uint32_t c2 = __float_as_uint(xA1[k8 + 4]);
            uint32_t c3 = __float_as_uint(xB1[k8 + 4]);
#pragma unroll
            for (int tt = 0; tt < 2; tt++){
                int tile = g*8 + nq*2 + tt;
                float4 bw = __ldg(wip4 + tile*512 + k*32 + lane);
                uint32_t bh0 = __float_as_uint(bw.x), bh1 = __float_as_uint(bw.y);
                uint32_t bl0 = __float_as_uint(bw.z), bl1 = __float_as_uint(bw.w);
                mma8(acc[0][tt], a0, a1, a2, a3, bh0, bh1);
                mma8(acc[0][tt], a0, a1, a2, a3, bl0, bl1);
                mma8(acc[1][tt], c0, c1, c2, c3, bh0, bh1);
                mma8(acc[1][tt], c0, c1, c2, c3, bl0, bl1);
            }
        }
#pragma unroll
        for (int mm = 0; mm < 2; mm++){
            int pixA = pix0 + m0 + mm*16 + row_;
            int pixB = pixA + 8;
#pragma unroll
            for (int tt = 0; tt < 2; tt++){
                int e0 = g*64 + (nq*2 + tt)*8 + 2*col_;
                float* basep = (g < 2) ? (ub + e0) : (zb + e0 - 128);
                *(float2*)(basep + (size_t)pixA*128) = make_float2(acc[mm][tt].x, acc[mm][tt].y);
                *(float2*)(basep + (size_t)pixB*128) = make_float2(acc[mm][tt].z, acc[mm][tt].w);
            }
        }
    }
}

// ---------------------------------------------------------------- K4: fused conv1d + x_proj(mma) + dt_proj + scanA
#define XDS 26
__global__ void __launch_bounds__(512, 2) k_cxp2(const float* __restrict__ u0,
                        const float* __restrict__ cw, const float* __restrict__ cb,
                        const float* __restrict__ wxp,
                        const float* __restrict__ dtw, const float* __restrict__ dtb,
                        const float* __restrict__ A_log,
                        float* __restrict__ ug,
                        float* __restrict__ dl, float* __restrict__ Bb, float* __restrict__ Cb,
                        float* __restrict__ Pg, float* __restrict__ hEg){
    extern __shared__ float sm[];
    float* u0s = sm;                 // 66*128 = 8448 ; aliased by sdl after conv
    float* su  = sm + 8448;          // 64*132
    float* xd  = sm + 16896;         // 64*XDS
    float* sdl = u0s;
    int pix0 = blockIdx.x * 64;
    int b = blockIdx.x >> 6;
    int c = blockIdx.x & 63;
    int l0 = pix0 & (LL - 1);
    int t = threadIdx.x, warp = t >> 5, lane = t & 31;
    {
        const float4* u4 = (const float4*)(u0 + ((size_t)pix0 - 2)*128);
        for (int i = t; i < 66*32; i += 512){
            int p = i >> 5;
            float4 v = make_float4(0.f,0.f,0.f,0.f);
            if (!(l0 == 0 && p < 2)) v = u4[i];
            ((float4*)u0s)[i] = v;
        }
    }
    __syncthreads();
    {
        int d = t & 127, ph = t >> 7;
        float w0 = cw[d*3], w1c = cw[d*3 + 1], w2c = cw[d*3 + 2];
        float bias = cb[d];
#pragma unroll 4
        for (int p = ph*16; p < ph*16 + 16; p++){
            float a = fmaf(w2c, u0s[(p + 2)*128 + d],
                      fmaf(w1c, u0s[(p + 1)*128 + d],
                      fmaf(w0,  u0s[p*128 + d], bias)));
            a = siluf(a);
            ug[(size_t)(pix0 + p)*128 + d] = a;
            su[p*132 + d] = a;
        }
    }
    __syncthreads();
    if (warp < 12){
        int m0 = (warp & 3) * 16;
        int ntile = warp >> 2;
        int row_ = lane >> 2, col_ = lane & 3;
        const float* aA = su + (m0 + row_)*132 + col_;
        const float* aB = aA + 8*132;
        const float4* wxp4 = (const float4*)wxp;
        float4 acc = make_float4(0.f,0.f,0.f,0.f);
#pragma unroll 2
        for (int k = 0; k < 16; k++){
            int k8 = k*8;
            float f0 = aA[k8], f1 = aB[k8], f2 = aA[k8 + 4], f3 = aB[k8 + 4];
            uint32_t h0 = f2tf(f0), h1 = f2tf(f1), h2 = f2tf(f2), h3 = f2tf(f3);
            uint32_t l0_ = __float_as_uint(f0 - __uint_as_float(h0));
            uint32_t l1  = __float_as_uint(f1 - __uint_as_float(h1));
            uint32_t l2  = __float_as_uint(f2 - __uint_as_float(h2));
            uint32_t l3  = __float_as_uint(f3 - __uint_as_float(h3));
            float4 bw = __ldg(wxp4 + (ntile*16 + k)*32 + lane);
            uint32_t bh0 = __float_as_uint(bw.x), bh1 = __float_as_uint(bw.y);
            uint32_t bl0 = __float_as_uint(bw.z), bl1 = __float_as_uint(bw.w);
            mma8(acc, h0, h1, h2, h3, bh0, bh1);
            mma8(acc, h0, h1, h2, h3, bl0, bl1);
            mma8(acc, l0_, l1, l2, l3, bh0, bh1);
        }
        int pA = m0 + row_, pB = pA + 8;
        int cc = ntile*8 + 2*col_;
        *(float2*)(xd + pA*XDS + cc) = make_float2(acc.x, acc.y);
        *(float2*)(xd + pB*XDS + cc) = make_float2(acc.z, acc.w);
    }
    __syncthreads();
    {
        int d = t & 127, ph = t >> 7;
        float4 wa = ((const float4*)(dtw + d*8))[0];
        float4 wb = ((const float4*)(dtw + d*8))[1];
        float bias = dtb[d];
#pragma unroll 4
        for (int p = ph*16; p < ph*16 + 16; p++){
            const float* xr = xd + p*XDS;
            float a = bias;
            a = fmaf(xr[0], wa.x, a); a = fmaf(xr[1], wa.y, a);
            a = fmaf(xr[2], wa.z, a); a = fmaf(xr[3], wa.w, a);
            a = fmaf(xr[4], wb.x, a); a = fmaf(xr[5], wb.y, a);
            a = fmaf(xr[6], wb.z, a); a = fmaf(xr[7], wb.w, a);
            float sp = (a > 20.f) ? a : log1pf(__expf(a));
            dl[(size_t)(pix0 + p)*128 + d] = sp;
            sdl[p*128 + d] = sp;
        }
    }
    {
        int p = t >> 3, n = t & 7;
        Bb[(pix0 + p)*8 + n] = xd[p*XDS + 8 + n];
        Cb[(pix0 + p)*8 + n] = xd[p*XDS + 16 + n];
    }
    __syncthreads();
    {
        int d = t >> 2, np = (t & 3) * 2;
        float Av0 = -__expf(A_log[d*8 + np]);
        float Av1 = -__expf(A_log[d*8 + np + 1]);
        float h0 = 0.f, h1 = 0.f, P0 = 1.f, P1 = 1.f;
#pragma unroll 4
        for (int l = 0; l < CS; l++){
            float de = sdl[l*128 + d];
            float uu = su[l*132 + d];
            float du = de * uu;
            float2 Bv = *(const float2*)(xd + l*XDS + 8 + np);
            float dA0 = __expf(de * Av0);
            float dA1 = __expf(de * Av1);
            P0 *= dA0; P1 *= dA1;
            h0 = fmaf(dA0, h0, du * Bv.x);
            h1 = fmaf(dA1, h1, du * Bv.y);
        }
        size_t oidx = (size_t)(b*NC + c)*1024 + d*8 + np;
        *(float2*)(Pg + oidx) = make_float2(P0, P1);
        *(float2*)(hEg + oidx) = make_float2(h0, h1);
    }
}

// ---------------------------------------------------------------- K5: chunk combine
__global__ void k_scanB(const float* __restrict__ Pg, const float* __restrict__ hEg,
                        float* __restrict__ h0g){
    int j = blockIdx.x * 128 + threadIdx.x;
    int b = j >> 10, dn = j & 1023;
    float h = 0.f;
#pragma unroll 8
    for (int c = 0; c < NC; c++){
        int idx = (b*NC + c)*1024 + dn;
        h0g[idx] = h;
        h = fmaf(Pg[idx], h, hEg[idx]);
    }
}

// ---------------------------------------------------------------- K6: MEGA2 = scanC + out_proj + LN + gate GEMMs
__global__ void __launch_bounds__(512, 1) k_mega2(
        const float* __restrict__ dl, const float* __restrict__ u,
        const float* __restrict__ z, const float* __restrict__ Bb,
        const float* __restrict__ Cb, const float* __restrict__ A_log,
        const float* __restrict__ Dp, const float* __restrict__ h0g,
        const float* __restrict__ wop,
        const float* __restrict__ gamma, const float* __restrict__ beta,
        const float* __restrict__ x,
        const float* __restrict__ w2p, const float* __restrict__ wtp,
        float* __restrict__ out){
    extern __shared__ float sm[];
    float* r1 = sm;               // 17408: sdl|su|sB|sC ; later xt (8448)
    float* r3 = sm + 17408;       // 8448: y -> fs
    float* mt = r3 + 8448;        // 8448
    float* mus = mt + 8448;       // 64
    float* rss = mus + 64;        // 64
    float* gb  = rss + 64;        // 256
    float* sdl = r1;
    float* su  = r1 + 8192;
    float* sB  = r1 + 16384;
    float* sC  = r1 + 16896;
    float* xt  = r1;
    const float4* wop4 = (const float4*)wop;
    const float4* w2p4 = (const float4*)w2p;
    const float4* wtp4 = (const float4*)wtp;
    int b = blockIdx.x >> 6;
    int c = blockIdx.x & (NC - 1);
    int t = threadIdx.x, warp = t >> 5, lane = t & 31;
    int row_ = lane >> 2, col_ = lane & 3;
    int pix0 = b*LL + c*CS;
    size_t base = (size_t)pix0*128;
    // phase 1
    {
        const float4* dl4 = (const float4*)(dl + base);
        const float4* u4  = (const float4*)(u + base);
        for (int i = t; i < CS*32; i += 512){
            ((float4*)sdl)[i] = dl4[i];
            ((float4*)su)[i]  = u4[i];
        }
        int nb = pix0*8;
        if (t < CS*8){ sB[t] = Bb[nb + t]; sC[t] = Cb[nb + t]; }
        if (t < 128){ gb[t] = gamma[t]; gb[128 + t] = beta[t]; }
    }
    __syncthreads();
    // phase 2: scan
    {
        int d = t >> 2, np = (t & 3) * 2;
        float Av0 = -__expf(A_log[d*8 + np]);
        float Av1 = -__expf(A_log[d*8 + np + 1]);
        float2 h = *(const float2*)(h0g + (size_t)(b*NC + c)*1024 + d*8 + np);
#pragma unroll 4
        for (int l = 0; l < CS; l++){
            float de = sdl[l*128 + d];
            float uu = su[l*128 + d];
            float du = de * uu;
            float2 Bv = *(const float2*)(sB + l*8 + np);
            float2 Cv = *(const float2*)(sC + l*8 + np);
            h.x = fmaf(__expf(de * Av0), h.x, du * Bv.x);
            h.y = fmaf(__expf(de * Av1), h.y, du * Bv.y);
            float y = h.x * Cv.x + h.y * Cv.y;
            y += __shfl_xor_sync(0xffffffffu, y, 1);
            y += __shfl_xor_sync(0xffffffffu, y, 2);
            if ((t & 3) == 0) r3[l*132 + d] = y;
        }
    }
    __syncthreads();
    // phase 3
    {
        for (int i = t; i < CS*128; i += 512){
            int l = i >> 7, d = i & 127;
            float val = fmaf(su[l*128 + d], Dp[d], r3[l*132 + d]);
            val *= siluf(z[base + i]);
            r3[l*132 + d] = __uint_as_float(f2tf(val));
        }
    }
    __syncthreads();
    // phase 5: out_proj GEMM (warp = (mp 0..1: 2 m-tiles, tp 0..7: 2 tiles); B direct-LDG)
    {
        int mp = warp >> 3, tp = warp & 7;
        int m0 = mp * 32;
        const float* yA0 = r3 + (m0 + row_)*132 + col_;
        const float* yB0 = yA0 + 8*132;
        const float* yA1 = yA0 + 16*132;
        const float* yB1 = yA1 + 8*132;
        float4 acc[2][2];
#pragma unroll
        for (int mm = 0; mm < 2; mm++)
#pragma unroll
            for (int tt = 0; tt < 2; tt++) acc[mm][tt] = make_float4(0.f,0.f,0.f,0.f);
#pragma unroll 4
        for (int k = 0; k < 16; k++){
            int k8 = k*8;
            uint32_t a0 = __float_as_uint(yA0[k8]);
            uint32_t a1 = __float_as_uint(yB0[k8]);
            uint32_t a2 = __float_as_uint(yA0[k8 + 4]);
            uint32_t a3 = __float_as_uint(yB0[k8 + 4]);
            uint32_t c0 = __float_as_uint(yA1[k8]);
            uint32_t c1 = __float_as_uint(yB1[k8]);
            uint32_t c2 = __float_as_uint(yA1[k8 + 4]);
            uint32_t c3 = __float_as_uint(yB1[k8 + 4]);
#pragma unroll
            for (int tt = 0; tt < 2; tt++){
                int tile = tp*2 + tt;
                float4 bw = __ldg(wop4 + tile*512 + k*32 + lane);
                uint32_t bh0 = __float_as_uint(bw.x), bh1 = __float_as_uint(bw.y);
                uint32_t bl0 = __float_as_uint(bw.z), bl1 = __float_as_uint(bw.w);
                mma8(acc[0][tt], a0, a1, a2, a3, bh0, bh1);
                mma8(acc[0][tt], a0, a1, a2, a3, bl0, bl1);
                mma8(acc[1][tt], c0, c1, c2, c3, bh0, bh1);
                mma8(acc[1][tt], c0, c1, c2, c3, bl0, bl1);
            }
        }
#pragma unroll
        for (int mm = 0; mm < 2; mm++){
            int pA = m0 + mm*16 + row_, pB = pA + 8;
#pragma unroll
            for (int tt = 0; tt < 2; tt++){
                int e = (tp*2 + tt)*8 + 2*col_;
                *(float2*)(mt + pA*132 + e) = make_float2(acc[mm][tt].x, acc[mm][tt].y);
                *(float2*)(mt + pB*132 + e) = make_float2(acc[mm][tt].z, acc[mm][tt].w);
            }
        }
    }
    __syncthreads();
    // phase 6: xt (tf32) into r1; LN stats
    {
        const float4* x4 = (const float4*)(x + base);
        for (int i = t; i < 64*32; i += 512){
            int p = i >> 5, q = i & 31;
            float4 v = x4[i];
            v.x = __uint_as_float(f2tf(v.x)); v.y = __uint_as_float(f2tf(v.y));
            v.z = __uint_as_float(f2tf(v.z)); v.w = __uint_as_float(f2tf(v.w));
            *(float4*)(xt + p*132 + q*4) = v;
        }
    }
    for (int p = warp*4; p < warp*4 + 4; p++){
        float4 v = *(const float4*)(mt + p*132 + lane*4);
        float s = v.x + v.y + v.z + v.w;
        s += __shfl_xor_sync(0xffffffffu, s, 16);
        s += __shfl_xor_sync(0xffffffffu, s, 8);
        s += __shfl_xor_sync(0xffffffffu, s, 4);
        s += __shfl_xor_sync(0xffffffffu, s, 2);
        s += __shfl_xor_sync(0xffffffffu, s, 1);
        float mu = s * (1.f/128.f);
        float dx = v.x - mu, dy = v.y - mu, dz = v.z - mu, dww = v.w - mu;
        float q = dx*dx + dy*dy + dz*dz + dww*dww;
        q += __shfl_xor_sync(0xffffffffu, q, 16);
        q += __shfl_xor_sync(0xffffffffu, q, 8);
        q += __shfl_xor_sync(0xffffffffu, q, 4);
        q += __shfl_xor_sync(0xffffffffu, q, 2);
        q += __shfl_xor_sync(0xffffffffu, q, 1);
        if (lane == 0){
            mus[p] = mu;
            rss[p] = rsqrtf(q * (1.f/128.f) + 1e-5f);
        }
    }
    __syncthreads();
    int p0 = (warp >> 2) * 16;
    int cq = warp & 3;
    int pA = p0 + row_, pB = pA + 8;
    // phase 7: gate GEMM + LN combine -> fs (r3, tf32)
#pragma unroll 1
    for (int nt = 0; nt < 4; nt++){
        int c0 = cq*32 + nt*8;
        int kb = (c0 >> 5) << 5;
        int tile = cq*4 + nt;
        float4 acc = make_float4(0.f,0.f,0.f,0.f);
#pragma unroll
        for (int k = 0; k < 4; k++){
            int kc = kb + k*8;
            const float* xrA = xt + pA*132 + kc + col_;
            uint32_t a0 = __float_as_uint(xrA[0]);
            uint32_t a1 = __float_as_uint(xrA[8*132]);
            uint32_t a2 = __float_as_uint(xrA[4]);
            uint32_t a3 = __float_as_uint(xrA[8*132 + 4]);
            float4 bw = __ldg(w2p4 + (tile*4 + k)*32 + lane);
            mma8(acc, a0, a1, a2, a3, __float_as_uint(bw.x), __float_as_uint(bw.y));
            mma8(acc, a0, a1, a2, a3, __float_as_uint(bw.z), __float_as_uint(bw.w));
        }
        int cc = c0 + 2*col_;
        float g0 = gb[cc], g1 = gb[cc + 1], b0 = gb[128 + cc], b1 = gb[128 + cc + 1];
        float vx = fmaf((mt[pA*132 + cc]     - mus[pA]) * rss[pA], g0, b0) * siluf(acc.x);
        float vy = fmaf((mt[pA*132 + cc + 1] - mus[pA]) * rss[pA], g1, b1) * siluf(acc.y);
        float vz = fmaf((mt[pB*132 + cc]     - mus[pB]) * rss[pB], g0, b0) * siluf(acc.z);
        float vw = fmaf((mt[pB*132 + cc + 1] - mus[pB]) * rss[pB], g1, b1) * siluf(acc.w);
        *(float2*)(r3 + pA*132 + cc) = make_float2(__uint_as_float(f2tf(vx)), __uint_as_float(f2tf(vy)));
        *(float2*)(r3 + pB*132 + cc) = make_float2(__uint_as_float(f2tf(vz)), __uint_as_float(f2tf(vw)));
    }
    __syncwarp();
    // phase 8: final grouped1x1 -> out
#pragma unroll 1
    for (int nt = 0; nt < 4; nt++){
        int c0 = cq*32 + nt*8;
        int kb = (c0 >> 5) << 5;
        int tile = cq*4 + nt;
        float4 acc = make_float4(0.f,0.f,0.f,0.f);
#pragma unroll
        for (int k = 0; k < 4; k++){
            int kc = kb + k*8;
            const float* frA = r3 + pA*132 + kc + col_;
            uint32_t a0 = __float_as_uint(frA[0]);
            uint32_t a1 = __float_as_uint(frA[8*132]);
            uint32_t a2 = __float_as_uint(frA[4]);
            uint32_t a3 = __float_as_uint(frA[8*132 + 4]);
            float4 bw = __ldg(wtp4 + (tile*4 + k)*32 + lane);
            mma8(acc, a0, a1, a2, a3, __float_as_uint(bw.x), __float_as_uint(bw.y));
            mma8(acc, a0, a1, a2, a3, __float_as_uint(bw.z), __float_as_uint(bw.w));
        }
        int cc = c0 + 2*col_;
        *(float2*)(out + (size_t)(pix0 + pA)*128 + cc) = make_float2(acc.x, acc.y);
        *(float2*)(out + (size_t)(pix0 + pB)*128 + cc) = make_float2(acc.z, acc.w);
    }
}

// ----------------------------------------------------------------
extern "C" void kernel_launch(void* const* d_in, const int* in_sizes, int n_in,
                              void* d_out, int out_size){
    const float* x        = (const float*)d_in[0];
    const float* w1       = (const float*)d_in[1];
    const float* dw       = (const float*)d_in[2];
    const float* in_proj  = (const float*)d_in[3];
    const float* conv1d_w = (const float*)d_in[4];
    const float* conv1d_b = (const float*)d_in[5];
    const float* x_proj_w = (const float*)d_in[6];
    const float* dt_proj_w= (const float*)d_in[7];
    const float* dt_proj_b= (const float*)d_in[8];
    const float* A_log    = (const float*)d_in[9];
    const float* D_param  = (const float*)d_in[10];
    const float* out_proj = (const float*)d_in[11];
    const float* gamma    = (const float*)d_in[12];
    const float* beta     = (const float*)d_in[13];
    const float* w2       = (const float*)d_in[14];
    const float* wout     = (const float*)d_in[15];
    float* out = (float*)d_out;

    float *t1, *xs, *u0, *z, *u, *dl, *Bm, *Cm, *Pg, *hE, *h0;
    float *wip, *wop, *w2p, *wtp, *wxp;
    cudaGetSymbolAddress((void**)&t1, g_t1);
    cudaGetSymbolAddress((void**)&xs, g_xs);
    cudaGetSymbolAddress((void**)&u0, g_u0);
    cudaGetSymbolAddress((void**)&z,  g_z);
    cudaGetSymbolAddress((void**)&u,  g_u);
    cudaGetSymbolAddress((void**)&dl, g_dl);
    cudaGetSymbolAddress((void**)&Bm, g_Bm);
    cudaGetSymbolAddress((void**)&Cm, g_Cm);
    cudaGetSymbolAddress((void**)&Pg, g_P);
    cudaGetSymbolAddress((void**)&hE, g_hE);
    cudaGetSymbolAddress((void**)&h0, g_h0);
    cudaGetSymbolAddress((void**)&wip, g_wip);
    cudaGetSymbolAddress((void**)&wop, g_wop);
    cudaGetSymbolAddress((void**)&w2p, g_w2p);
    cudaGetSymbolAddress((void**)&wtp, g_wtp);
    cudaGetSymbolAddress((void**)&wxp, g_wxp);

    const int smemI = (128*132) * sizeof(float);
    const int smemX = (8448 + 8448 + 64*XDS) * sizeof(float);
    const int smemM = (17408 + 8448 + 8448 + 64 + 64 + 256) * sizeof(float);
    static int attr_done = 0;
    if (!attr_done){
        cudaFuncSetAttribute(k_inproj, cudaFuncAttributeMaxDynamicSharedMemorySize, smemI);
        cudaFuncSetAttribute(k_cxp2,  cudaFuncAttributeMaxDynamicSharedMemorySize, smemX);
        cudaFuncSetAttribute(k_mega2, cudaFuncAttributeMaxDynamicSharedMemorySize, smemM);
        attr_done = 1;
    }

    k_prep<<<118, 256>>>(in_proj, out_proj, w2, wout, x_proj_w, wip, wop, w2p, wtp, wxp);
    k_g1<<<NPIX/32, 256>>>(x, w1, t1);
    k_dw<<<NPIX*32/256, 256>>>(t1, dw, xs);
    k_inproj<<<NPIX/128, 512, smemI>>>(xs, wip, u0, z);
    k_cxp2<<<NPIX/64, 512, smemX>>>(u0, conv1d_w, conv1d_b, wxp, dt_proj_w, dt_proj_b,
                                    A_log, u, dl, Bm, Cm, Pg, hE);
    k_scanB<<<64, 128>>>(Pg, hE, h0);
    k_mega2<<<BB*NC, 512, smemM>>>(dl, u, z, Bm, Cm, A_log, D_param, h0,
                                   wop, gamma, beta, x, w2p, wtp, out);
}

// round 13
// speedup vs baseline: 9.2758x; 1.0159x over previous
#include <cuda_runtime.h>
#include <math.h>
#include <stdint.h>

// Problem constants
#define BB 8
#define HH 64
#define WW 64
#define CC 128
#define DD 128
#define LL 4096            // H*W
#define NPIX (BB*LL)       // 32768
#define NS 8               // D_STATE
#define RR 8               // DT_RANK

#define CS 64              // chunk size (steps)
#define NC (LL/CS)         // 64 chunks per batch

// Scratch (device globals; no allocations allowed)
__device__ float g_t1[NPIX*DD];
__device__ float g_xs[NPIX*DD];
__device__ float g_u0[NPIX*DD];
__device__ float g_z [NPIX*DD];
__device__ float g_u [NPIX*DD];
__device__ float g_dl[NPIX*DD];
__device__ float g_Bm[NPIX*NS];
__device__ float g_Cm[NPIX*NS];
__device__ float g_P [BB*NC*1024];
__device__ float g_hE[BB*NC*1024];
__device__ float g_h0[BB*NC*1024];
// fragment-packed tf32 hi/lo weights: float4 {bh0, bh1, bl0, bl1} per (tile,k,lane)
__device__ float g_wip[65536];   // in_proj: 32 tiles x 16 k x 32 lanes
__device__ float g_wop[32768];   // out_proj: 16 tiles x 16 k x 32 lanes
__device__ float g_w2p[8192];    // w2 gate: 16 tiles x 4 k x 32 lanes
__device__ float g_wtp[8192];    // wout:    16 tiles x 4 k x 32 lanes
__device__ float g_wxp[6144];    // x_proj:  3 tiles x 16 k x 32 lanes

__device__ __forceinline__ float siluf(float v){ return v / (1.f + __expf(-v)); }

__device__ __forceinline__ uint32_t f2tf(float x){
    uint32_t r; asm("cvt.rna.tf32.f32 %0, %1;" : "=r"(r) : "f"(x)); return r;
}
__device__ __forceinline__ void mma8(float4& c, uint32_t a0, uint32_t a1, uint32_t a2, uint32_t a3,
                                     uint32_t b0, uint32_t b1){
    asm volatile("mma.sync.aligned.m16n8k8.row.col.f32.tf32.tf32.f32 "
                 "{%0,%1,%2,%3},{%4,%5,%6,%7},{%8,%9},{%0,%1,%2,%3};\n"
                 : "+f"(c.x), "+f"(c.y), "+f"(c.z), "+f"(c.w)
                 : "r"(a0), "r"(a1), "r"(a2), "r"(a3), "r"(b0), "r"(b1));
}
__device__ __forceinline__ void ldsm4(uint32_t& r0, uint32_t& r1, uint32_t& r2, uint32_t& r3,
                                      uint32_t addr){
    asm volatile("ldmatrix.sync.aligned.m8n8.x4.shared.b16 {%0,%1,%2,%3}, [%4];"
                 : "=r"(r0), "=r"(r1), "=r"(r2), "=r"(r3) : "r"(addr));
}
__device__ __forceinline__ float4 pack_hl(float v0, float v1){
    float h0 = __uint_as_float(f2tf(v0));
    float h1 = __uint_as_float(f2tf(v1));
    return make_float4(h0, h1, v0 - h0, v1 - h1);
}

// ---------------------------------------------------------------- K0: weight fragment-pack prep
__global__ void k_prep(const float* __restrict__ wi, const float* __restrict__ wo,
                       const float* __restrict__ w2, const float* __restrict__ wt,
                       const float* __restrict__ wx,
                       float* wip, float* wop, float* w2p, float* wtp, float* wxp){
    int i = blockIdx.x * 256 + threadIdx.x;
    if (i >= 30208) return;
    if (i < 16384){
        int lane = i & 31, k = (i >> 5) & 15, tile = i >> 9;
        int row = lane >> 2, col = lane & 3;
        int e = tile*8 + row, kc = k*8 + col;
        ((float4*)wip)[i] = pack_hl(wi[e*128 + kc], wi[e*128 + kc + 4]);
    } else if (i < 24576){
        int j = i - 16384;
        int lane = j & 31, k = (j >> 5) & 15, tile = j >> 9;
        int row = lane >> 2, col = lane & 3;
        int e = tile*8 + row, kc = k*8 + col;
        ((float4*)wop)[j] = pack_hl(wo[e*128 + kc], wo[e*128 + kc + 4]);
    } else if (i < 26624){
        int j = i - 24576;
        int lane = j & 31, k = (j >> 5) & 3, tile = j >> 7;
        int row = lane >> 2, col = lane & 3;
        int e = tile*8 + row;
        ((float4*)w2p)[j] = pack_hl(w2[e*32 + k*8 + col], w2[e*32 + k*8 + col + 4]);
    } else if (i < 28672){
        int j = i - 26624;
        int lane = j & 31, k = (j >> 5) & 3, tile = j >> 7;
        int row = lane >> 2, col = lane & 3;
        int e = tile*8 + row;
        ((float4*)wtp)[j] = pack_hl(wt[e*32 + k*8 + col], wt[e*32 + k*8 + col + 4]);
    } else {
        int j = i - 28672;
        int lane = j & 31, k = (j >> 5) & 15, tile = j >> 9;
        int row = lane >> 2, col = lane & 3;
        int e = tile*8 + row, kc = k*8 + col;
        ((float4*)wxp)[j] = pack_hl(wx[e*128 + kc], wx[e*128 + kc + 4]);
    }
}

// ---------------------------------------------------------------- K1: grouped 1x1
__global__ void __launch_bounds__(256) k_g1(const float* __restrict__ x,
                                            const float* __restrict__ w,
                                            float* __restrict__ out){
    __shared__ float xt[32*128];
    int pix0 = blockIdx.x * 32;
    const float4* x4 = (const float4*)(x + (size_t)pix0*128);
    for (int i = threadIdx.x; i < 32*32; i += 256) ((float4*)xt)[i] = x4[i];
    __syncthreads();
    int t = threadIdx.x;
    int c = t & 127, half = t >> 7;
    int g = c >> 5;
    float4 wr[8];
#pragma unroll
    for (int i = 0; i < 8; i++) wr[i] = ((const float4*)(w + c*32))[i];
    const float* xb = xt + (half*16)*128 + g*32;
    float* ob = out + ((size_t)pix0 + half*16)*128 + c;
#pragma unroll
    for (int p = 0; p < 16; p++){
        const float* xr = xb + p*128;
        float a = 0.f;
#pragma unroll
        for (int i = 0; i < 8; i++){
            float4 xv = *(const float4*)(xr + i*4);
            a = fmaf(wr[i].x, xv.x, a); a = fmaf(wr[i].y, xv.y, a);
            a = fmaf(wr[i].z, xv.z, a); a = fmaf(wr[i].w, xv.w, a);
        }
        ob[(size_t)p*128] = a;
    }
}

// ---------------------------------------------------------------- K2: depthwise 3x3 + silu
__global__ void k_dw(const float* __restrict__ t1, const float* __restrict__ dw,
                     float* __restrict__ out){
    int idx = blockIdx.x * 256 + threadIdx.x;
    int d4 = idx & 31; int pix = idx >> 5;
    int wc = pix & 63; int h = (pix >> 6) & 63; int b = pix >> 12;
    int d = d4 << 2;
    float4 acc = make_float4(0.f, 0.f, 0.f, 0.f);
#pragma unroll
    for (int kh = 0; kh < 3; kh++){
        int hh = h + kh - 1; if (hh < 0 || hh >= 64) continue;
#pragma unroll
        for (int kw = 0; kw < 3; kw++){
            int ww = wc + kw - 1; if (ww < 0 || ww >= 64) continue;
            float4 tv = *(const float4*)(t1 + (((b*64 + hh)*64 + ww) << 7) + d);
            float4 wv = *(const float4*)(dw + (kh*3 + kw)*128 + d);
            acc.x = fmaf(tv.x, wv.x, acc.x); acc.y = fmaf(tv.y, wv.y, acc.y);
            acc.z = fmaf(tv.z, wv.z, acc.z); acc.w = fmaf(tv.w, wv.w, acc.w);
        }
    }
    float4 r; r.x = siluf(acc.x); r.y = siluf(acc.y); r.z = siluf(acc.z); r.w = siluf(acc.w);
    *(float4*)(out + (size_t)pix*128 + d) = r;
}

// ---------------------------------------------------------------- K3: in_proj via tf32 mma (ldmatrix A)
// 512 thr, 128 pixels/block, 256 blocks. warp = (mp 0..3: 32 px, nq 0..3: 2 tiles/g)
__global__ void __launch_bounds__(512, 2) k_inproj(const float* __restrict__ xs,
                       const float* __restrict__ wip,
                       float* __restrict__ ub, float* __restrict__ zb){
    extern __shared__ float sm[];
    float* xt = sm;              // 128*132
    int tid = threadIdx.x;
    int pix0 = blockIdx.x * 128;
    {
        const float4* xs4 = (const float4*)(xs + (size_t)pix0*128);
        for (int i = tid; i < 128*32; i += 512){
            int p = i >> 5, q = i & 31;
            float4 v = xs4[i];
            v.x = __uint_as_float(f2tf(v.x)); v.y = __uint_as_float(f2tf(v.y));
            v.z = __uint_as_float(f2tf(v.z)); v.w = __uint_as_float(f2tf(v.w));
            *(float4*)(xt + p*132 + q*4) = v;
        }
    }
    __syncthreads();
    int warp = tid >> 5, lane = tid & 31;
    int row_ = lane >> 2, col_ = lane & 3;
    int mp = warp >> 2, nq = warp & 3;
    int m0 = mp * 32;
    int lr = lane & 15, lc = (lane >> 4) << 2;
    uint32_t xtb = (uint32_t)__cvta_generic_to_shared(xt);
    uint32_t aad0 = xtb + (((m0 + lr)*132 + lc) << 2);
    uint32_t aad1 = aad0 + (16*132 << 2);
    const float4* wip4 = (const float4*)wip;
#pragma unroll 1
    for (int g = 0; g < 4; g++){
        float4 acc[2][2];
#pragma unroll
        for (int mm = 0; mm < 2; mm++)
#pragma unroll
            for (int tt = 0; tt < 2; tt++) acc[mm][tt] = make_float4(0.f,0.f,0.f,0.f);
#pragma unroll 4
        for (int k = 0; k < 16; k++){
            uint32_t a0, a1, a2, a3, c0, c1, c2, c3;
            ldsm4(a0, a1, a2, a3, aad0 + k*32);
            ldsm4(c0, c1, c2, c3, aad1 + k*32);
#pragma unroll
            for (int tt = 0; tt < 2; tt++){
                int tile = g*8 + nq*2 + tt;
                float4 bw = __ldg(wip4 + tile*512 + k*32 + lane);
                uint32_t bh0 = __float_as_uint(bw.x), bh1 = __float_as_uint(bw.y);
                uint32_t bl0 = __float_as_uint(bw.z), bl1 = __float_as_uint(bw.w);
                mma8(acc[0][tt], a0, a1, a2, a3, bh0, bh1);
                mma8(acc[0][tt], a0, a1, a2, a3, bl0, bl1);
                mma8(acc[1][tt], c0, c1, c2, c3, bh0, bh1);
                mma8(acc[1][tt], c0, c1, c2, c3, bl0, bl1);
            }
        }
#pragma unroll
        for (int mm = 0; mm < 2; mm++){
            int pixA = pix0 + m0 + mm*16 + row_;
            int pixB = pixA + 8;
#pragma unroll
            for (int tt = 0; tt < 2; tt++){
                int e0 = g*64 + (nq*2 + tt)*8 + 2*col_;
                float* basep = (g < 2) ? (ub + e0) : (zb + e0 - 128);
                *(float2*)(basep + (size_t)pixA*128) = make_float2(acc[mm][tt].x, acc[mm][tt].y);
                *(float2*)(basep + (size_t)pixB*128) = make_float2(acc[mm][tt].z, acc[mm][tt].w);
            }
        }
    }
}

// ---------------------------------------------------------------- K4: fused conv1d + x_proj(mma) + dt_proj + scanA
#define XDS 26
__global__ void __launch_bounds__(512, 2) k_cxp2(const float* __restrict__ u0,
                        const float* __restrict__ cw, const float* __restrict__ cb,
                        const float* __restrict__ wxp,
                        const float* __restrict__ dtw, const float* __restrict__ dtb,
                        const float* __restrict__ A_log,
                        float* __restrict__ ug,
                        float* __restrict__ dl, float* __restrict__ Bb, float* __restrict__ Cb,
                        float* __restrict__ Pg, float* __restrict__ hEg){
    extern __shared__ float sm[];
    float* u0s = sm;                 // 66*128 = 8448 ; aliased by sdl after conv
    float* su  = sm + 8448;          // 64*132
    float* xd  = sm + 16896;         // 64*XDS
    float* sdl = u0s;
    int pix0 = blockIdx.x * 64;
    int b = blockIdx.x >> 6;
    int c = blockIdx.x & 63;
    int l0 = pix0 & (LL - 1);
    int t = threadIdx.x, warp = t >> 5, lane = t & 31;
    {
        const float4* u4 = (const float4*)(u0 + ((size_t)pix0 - 2)*128);
        for (int i = t; i < 66*32; i += 512){
            int p = i >> 5;
            float4 v = make_float4(0.f,0.f,0.f,0.f);
            if (!(l0 == 0 && p < 2)) v = u4[i];
            ((float4*)u0s)[i] = v;
        }
    }
    __syncthreads();
    {
        int d = t & 127, ph = t >> 7;
        float w0 = cw[d*3], w1c = cw[d*3 + 1], w2c = cw[d*3 + 2];
        float bias = cb[d];
#pragma unroll 4
        for (int p = ph*16; p < ph*16 + 16; p++){
            float a = fmaf(w2c, u0s[(p + 2)*128 + d],
                      fmaf(w1c, u0s[(p + 1)*128 + d],
                      fmaf(w0,  u0s[p*128 + d], bias)));
            a = siluf(a);
            ug[(size_t)(pix0 + p)*128 + d] = a;
            su[p*132 + d] = a;
        }
    }
    __syncthreads();
    if (warp < 12){
        int m0 = (warp & 3) * 16;
        int ntile = warp >> 2;
        int row_ = lane >> 2, col_ = lane & 3;
        int lr = lane & 15, lc = (lane >> 4) << 2;
        uint32_t sub = (uint32_t)__cvta_generic_to_shared(su);
        uint32_t aad = sub + (((m0 + lr)*132 + lc) << 2);
        const float4* wxp4 = (const float4*)wxp;
        float4 acc = make_float4(0.f,0.f,0.f,0.f);
#pragma unroll 2
        for (int k = 0; k < 16; k++){
            uint32_t u0_, u1_, u2_, u3_;
            ldsm4(u0_, u1_, u2_, u3_, aad + k*32);
            float f0 = __uint_as_float(u0_), f1 = __uint_as_float(u1_);
            float f2 = __uint_as_float(u2_), f3 = __uint_as_float(u3_);
            uint32_t h0 = f2tf(f0), h1 = f2tf(f1), h2 = f2tf(f2), h3 = f2tf(f3);
            uint32_t l0_ = __float_as_uint(f0 - __uint_as_float(h0));
            uint32_t l1  = __float_as_uint(f1 - __uint_as_float(h1));
            uint32_t l2  = __float_as_uint(f2 - __uint_as_float(h2));
            uint32_t l3  = __float_as_uint(f3 - __uint_as_float(h3));
            float4 bw = __ldg(wxp4 + (ntile*16 + k)*32 + lane);
            uint32_t bh0 = __float_as_uint(bw.x), bh1 = __float_as_uint(bw.y);
            uint32_t bl0 = __float_as_uint(bw.z), bl1 = __float_as_uint(bw.w);
            mma8(acc, h0, h1, h2, h3, bh0, bh1);
            mma8(acc, h0, h1, h2, h3, bl0, bl1);
            mma8(acc, l0_, l1, l2, l3, bh0, bh1);
        }
        int pA = m0 + row_, pB = pA + 8;
        int cc = ntile*8 + 2*col_;
        *(float2*)(xd + pA*XDS + cc) = make_float2(acc.x, acc.y);
        *(float2*)(xd + pB*XDS + cc) = make_float2(acc.z, acc.w);
    }
    __syncthreads();
    {
        int d = t & 127, ph = t >> 7;
        float4 wa = ((const float4*)(dtw + d*8))[0];
        float4 wb = ((const float4*)(dtw + d*8))[1];
        float bias = dtb[d];
#pragma unroll 4
        for (int p = ph*16; p < ph*16 + 16; p++){
            const float* xr = xd + p*XDS;
            float a = bias;
            a = fmaf(xr[0], wa.x, a); a = fmaf(xr[1], wa.y, a);
            a = fmaf(xr[2], wa.z, a); a = fmaf(xr[3], wa.w, a);
            a = fmaf(xr[4], wb.x, a); a = fmaf(xr[5], wb.y, a);
            a = fmaf(xr[6], wb.z, a); a = fmaf(xr[7], wb.w, a);
            float sp = (a > 20.f) ? a : log1pf(__expf(a));
            dl[(size_t)(pix0 + p)*128 + d] = sp;
            sdl[p*128 + d] = sp;
        }
    }
    {
        int p = t >> 3, n = t & 7;
        Bb[(pix0 + p)*8 + n] = xd[p*XDS + 8 + n];
        Cb[(pix0 + p)*8 + n] = xd[p*XDS + 16 + n];
    }
    __syncthreads();
    {
        int d = t >> 2, np = (t & 3) * 2;
        float Av0 = -__expf(A_log[d*8 + np]);
        float Av1 = -__expf(A_log[d*8 + np + 1]);
        float h0 = 0.f, h1 = 0.f, P0 = 1.f, P1 = 1.f;
#pragma unroll 4
        for (int l = 0; l < CS; l++){
            float de = sdl[l*128 + d];
            float uu = su[l*132 + d];
            float du = de * uu;
            float2 Bv = *(const float2*)(xd + l*XDS + 8 + np);
            float dA0 = __expf(de * Av0);
            float dA1 = __expf(de * Av1);
            P0 *= dA0; P1 *= dA1;
            h0 = fmaf(dA0, h0, du * Bv.x);
            h1 = fmaf(dA1, h1, du * Bv.y);
        }
        size_t oidx = (size_t)(b*NC + c)*1024 + d*8 + np;
        *(float2*)(Pg + oidx) = make_float2(P0, P1);
        *(float2*)(hEg + oidx) = make_float2(h0, h1);
    }
}

// ---------------------------------------------------------------- K5: chunk combine
__global__ void k_scanB(const float* __restrict__ Pg, const float* __restrict__ hEg,
                        float* __restrict__ h0g){
    int j = blockIdx.x * 128 + threadIdx.x;
    int b = j >> 10, dn = j & 1023;
    float h = 0.f;
#pragma unroll 8
    for (int c = 0; c < NC; c++){
        int idx = (b*NC + c)*1024 + dn;
        h0g[idx] = h;
        h = fmaf(Pg[idx], h, hEg[idx]);
    }
}

// ---------------------------------------------------------------- K6: MEGA2 = scanC + out_proj + LN + gate GEMMs
__global__ void __launch_bounds__(512, 1) k_mega2(
        const float* __restrict__ dl, const float* __restrict__ u,
        const float* __restrict__ z, const float* __restrict__ Bb,
        const float* __restrict__ Cb, const float* __restrict__ A_log,
        const float* __restrict__ Dp, const float* __restrict__ h0g,
        const float* __restrict__ wop,
        const float* __restrict__ gamma, const float* __restrict__ beta,
        const float* __restrict__ x,
        const float* __restrict__ w2p, const float* __restrict__ wtp,
        float* __restrict__ out){
    extern __shared__ float sm[];
    float* r1 = sm;               // 17408: sdl|su|sB|sC ; later xt (8448)
    float* r3 = sm + 17408;       // 8448: y -> fs
    float* mt = r3 + 8448;        // 8448
    float* mus = mt + 8448;       // 64
    float* rss = mus + 64;        // 64
    float* gb  = rss + 64;        // 256
    float* sdl = r1;
    float* su  = r1 + 8192;
    float* sB  = r1 + 16384;
    float* sC  = r1 + 16896;
    float* xt  = r1;
    const float4* wop4 = (const float4*)wop;
    const float4* w2p4 = (const float4*)w2p;
    const float4* wtp4 = (const float4*)wtp;
    int b = blockIdx.x >> 6;
    int c = blockIdx.x & (NC - 1);
    int t = threadIdx.x, warp = t >> 5, lane = t & 31;
    int row_ = lane >> 2, col_ = lane & 3;
    int lr = lane & 15, lc = (lane >> 4) << 2;
    int pix0 = b*LL + c*CS;
    size_t base = (size_t)pix0*128;
    // phase 1
    {
        const float4* dl4 = (const float4*)(dl + base);
        const float4* u4  = (const float4*)(u + base);
        for (int i = t; i < CS*32; i += 512){
            ((float4*)sdl)[i] = dl4[i];
            ((float4*)su)[i]  = u4[i];
        }
        int nb = pix0*8;
        if (t < CS*8){ sB[t] = Bb[nb + t]; sC[t] = Cb[nb + t]; }
        if (t < 128){ gb[t] = gamma[t]; gb[128 + t] = beta[t]; }
    }
    __syncthreads();
    // phase 2: scan
    {
        int d = t >> 2, np = (t & 3) * 2;
        float Av0 = -__expf(A_log[d*8 + np]);
        float Av1 = -__expf(A_log[d*8 + np + 1]);
        float2 h = *(const float2*)(h0g + (size_t)(b*NC + c)*1024 + d*8 + np);
#pragma unroll 4
        for (int l = 0; l < CS; l++){
            float de = sdl[l*128 + d];
            float uu = su[l*128 + d];
            float du = de * uu;
            float2 Bv = *(const float2*)(sB + l*8 + np);
            float2 Cv = *(const float2*)(sC + l*8 + np);
            h.x = fmaf(__expf(de * Av0), h.x, du * Bv.x);
            h.y = fmaf(__expf(de * Av1), h.y, du * Bv.y);
            float y = h.x * Cv.x + h.y * Cv.y;
            y += __shfl_xor_sync(0xffffffffu, y, 1);
            y += __shfl_xor_sync(0xffffffffu, y, 2);
            if ((t & 3) == 0) r3[l*132 + d] = y;
        }
    }
    __syncthreads();
    // phase 3
    {
        for (int i = t; i < CS*128; i += 512){
            int l = i >> 7, d = i & 127;
            float val = fmaf(su[l*128 + d], Dp[d], r3[l*132 + d]);
            val *= siluf(z[base + i]);
            r3[l*132 + d] = __uint_as_float(f2tf(val));
        }
    }
    __syncthreads();
    // phase 5: out_proj GEMM (warp = (mp 0..1: 2 m-tiles, tp 0..7: 2 tiles); ldmatrix A)
    {
        int mp = warp >> 3, tp = warp & 7;
        int m0 = mp * 32;
        uint32_t r3b = (uint32_t)__cvta_generic_to_shared(r3);
        uint32_t yad0 = r3b + (((m0 + lr)*132 + lc) << 2);
        uint32_t yad1 = yad0 + (16*132 << 2);
        float4 acc[2][2];
#pragma unroll
        for (int mm = 0; mm < 2; mm++)
#pragma unroll
            for (int tt = 0; tt < 2; tt++) acc[mm][tt] = make_float4(0.f,0.f,0.f,0.f);
#pragma unroll 4
        for (int k = 0; k < 16; k++){
            uint32_t a0, a1, a2, a3, c0, c1, c2, c3;
            ldsm4(a0, a1, a2, a3, yad0 + k*32);
            ldsm4(c0, c1, c2, c3, yad1 + k*32);
#pragma unroll
            for (int tt = 0; tt < 2; tt++){
                int tile = tp*2 + tt;
                float4 bw = __ldg(wop4 + tile*512 + k*32 + lane);
                uint32_t bh0 = __float_as_uint(bw.x), bh1 = __float_as_uint(bw.y);
                uint32_t bl0 = __float_as_uint(bw.z), bl1 = __float_as_uint(bw.w);
                mma8(acc[0][tt], a0, a1, a2, a3, bh0, bh1);
                mma8(acc[0][tt], a0, a1, a2, a3, bl0, bl1);
                mma8(acc[1][tt], c0, c1, c2, c3, bh0, bh1);
                mma8(acc[1][tt], c0, c1, c2, c3, bl0, bl1);
            }
        }
#pragma unroll
        for (int mm = 0; mm < 2; mm++){
            int pA = m0 + mm*16 + row_, pB = pA + 8;
#pragma unroll
            for (int tt = 0; tt < 2; tt++){
                int e = (tp*2 + tt)*8 + 2*col_;
                *(float2*)(mt + pA*132 + e) = make_float2(acc[mm][tt].x, acc[mm][tt].y);
                *(float2*)(mt + pB*132 + e) = make_float2(acc[mm][tt].z, acc[mm][tt].w);
            }
        }
    }
    __syncthreads();
    // phase 6: xt (tf32) into r1; LN stats
    {
        const float4* x4 = (const float4*)(x + base);
        for (int i = t; i < 64*32; i += 512){
            int p = i >> 5, q = i & 31;
            float4 v = x4[i];
            v.x = __uint_as_float(f2tf(v.x)); v.y = __uint_as_float(f2tf(v.y));
            v.z = __uint_as_float(f2tf(v.z)); v.w = __uint_as_float(f2tf(v.w));
            *(float4*)(xt + p*132 + q*4) = v;
        }
    }
    for (int p = warp*4; p < warp*4 + 4; p++){
        float4 v = *(const float4*)(mt + p*132 + lane*4);
        float s = v.x + v.y + v.z + v.w;
        s += __shfl_xor_sync(0xffffffffu, s, 16);
        s += __shfl_xor_sync(0xffffffffu, s, 8);
        s += __shfl_xor_sync(0xffffffffu, s, 4);
        s += __shfl_xor_sync(0xffffffffu, s, 2);
        s += __shfl_xor_sync(0xffffffffu, s, 1);
        float mu = s * (1.f/128.f);
        float dx = v.x - mu, dy = v.y - mu, dz = v.z - mu, dww = v.w - mu;
        float q = dx*dx + dy*dy + dz*dz + dww*dww;
        q += __shfl_xor_sync(0xffffffffu, q, 16);
        q += __shfl_xor_sync(0xffffffffu, q, 8);
        q += __shfl_xor_sync(0xffffffffu, q, 4);
        q += __shfl_xor_sync(0xffffffffu, q, 2);
        q += __shfl_xor_sync(0xffffffffu, q, 1);
        if (lane == 0){
            mus[p] = mu;
            rss[p] = rsqrtf(q * (1.f/128.f) + 1e-5f);
        }
    }
    __syncthreads();
    int p0 = (warp >> 2) * 16;
    int cq = warp & 3;
    int pA = p0 + row_, pB = pA + 8;
    // phase 7: gate GEMM + LN combine -> fs (r3, tf32); A fragments hoisted via ldmatrix
    {
        uint32_t xtb = (uint32_t)__cvta_generic_to_shared(xt);
        uint32_t xad = xtb + (((p0 + lr)*132 + lc + cq*32) << 2);
        uint32_t af[4][4];
#pragma unroll
        for (int k = 0; k < 4; k++) ldsm4(af[k][0], af[k][1], af[k][2], af[k][3], xad + k*32);
#pragma unroll 1
        for (int nt = 0; nt < 4; nt++){
            int c0 = cq*32 + nt*8;
            int tile = cq*4 + nt;
            float4 acc = make_float4(0.f,0.f,0.f,0.f);
#pragma unroll
            for (int k = 0; k < 4; k++){
                float4 bw = __ldg(w2p4 + (tile*4 + k)*32 + lane);
                mma8(acc, af[k][0], af[k][1], af[k][2], af[k][3],
                     __float_as_uint(bw.x), __float_as_uint(bw.y));
                mma8(acc, af[k][0], af[k][1], af[k][2], af[k][3],
                     __float_as_uint(bw.z), __float_as_uint(bw.w));
            }
            int cc = c0 + 2*col_;
            float g0 = gb[cc], g1 = gb[cc + 1], b0 = gb[128 + cc], b1 = gb[128 + cc + 1];
            float vx = fmaf((mt[pA*132 + cc]     - mus[pA]) * rss[pA], g0, b0) * siluf(acc.x);
            float vy = fmaf((mt[pA*132 + cc + 1] - mus[pA]) * rss[pA], g1, b1) * siluf(acc.y);
            float vz = fmaf((mt[pB*132 + cc]     - mus[pB]) * rss[pB], g0, b0) * siluf(acc.z);
            float vw = fmaf((mt[pB*132 + cc + 1] - mus[pB]) * rss[pB], g1, b1) * siluf(acc.w);
            *(float2*)(r3 + pA*132 + cc) = make_float2(__uint_as_float(f2tf(vx)), __uint_as_float(f2tf(vy)));
            *(float2*)(r3 + pB*132 + cc) = make_float2(__uint_as_float(f2tf(vz)), __uint_as_float(f2tf(vw)));
        }
    }
    __syncwarp();
    // phase 8: final grouped1x1 -> out; A fragments hoisted via ldmatrix
    {
        uint32_t r3b = (uint32_t)__cvta_generic_to_shared(r3);
        uint32_t fad = r3b + (((p0 + lr)*132 + lc + cq*32) << 2);
        uint32_t af[4][4];
#pragma unroll
        for (int k = 0; k < 4; k++) ldsm4(af[k][0], af[k][1], af[k][2], af[k][3], fad + k*32);
#pragma unroll 1
        for (int nt = 0; nt < 4; nt++){
            int c0 = cq*32 + nt*8;
            int tile = cq*4 + nt;
            float4 acc = make_float4(0.f,0.f,0.f,0.f);
#pragma unroll
            for (int k = 0; k < 4; k++){
                float4 bw = __ldg(wtp4 + (tile*4 + k)*32 + lane);
                mma8(acc, af[k][0], af[k][1], af[k][2], af[k][3],
                     __float_as_uint(bw.x), __float_as_uint(bw.y));
                mma8(acc, af[k][0], af[k][1], af[k][2], af[k][3],
                     __float_as_uint(bw.z), __float_as_uint(bw.w));
            }
            int cc = c0 + 2*col_;
            *(float2*)(out + (size_t)(pix0 + pA)*128 + cc) = make_float2(acc.x, acc.y);
            *(float2*)(out + (size_t)(pix0 + pB)*128 + cc) = make_float2(acc.z, acc.w);
        }
    }
}

// ----------------------------------------------------------------
extern "C" void kernel_launch(void* const* d_in, const int* in_sizes, int n_in,
                              void* d_out, int out_size){
    const float* x        = (const float*)d_in[0];
    const float* w1       = (const float*)d_in[1];
    const float* dw       = (const float*)d_in[2];
    const float* in_proj  = (const float*)d_in[3];
    const float* conv1d_w = (const float*)d_in[4];
    const float* conv1d_b = (const float*)d_in[5];
    const float* x_proj_w = (const float*)d_in[6];
    const float* dt_proj_w= (const float*)d_in[7];
    const float* dt_proj_b= (const float*)d_in[8];
    const float* A_log    = (const float*)d_in[9];
    const float* D_param  = (const float*)d_in[10];
    const float* out_proj = (const float*)d_in[11];
    const float* gamma    = (const float*)d_in[12];
    const float* beta     = (const float*)d_in[13];
    const float* w2       = (const float*)d_in[14];
    const float* wout     = (const float*)d_in[15];
    float* out = (float*)d_out;

    float *t1, *xs, *u0, *z, *u, *dl, *Bm, *Cm, *Pg, *hE, *h0;
    float *wip, *wop, *w2p, *wtp, *wxp;
    cudaGetSymbolAddress((void**)&t1, g_t1);
    cudaGetSymbolAddress((void**)&xs, g_xs);
    cudaGetSymbolAddress((void**)&u0, g_u0);
    cudaGetSymbolAddress((void**)&z,  g_z);
    cudaGetSymbolAddress((void**)&u,  g_u);
    cudaGetSymbolAddress((void**)&dl, g_dl);
    cudaGetSymbolAddress((void**)&Bm, g_Bm);
    cudaGetSymbolAddress((void**)&Cm, g_Cm);
    cudaGetSymbolAddress((void**)&Pg, g_P);
    cudaGetSymbolAddress((void**)&hE, g_hE);
    cudaGetSymbolAddress((void**)&h0, g_h0);
    cudaGetSymbolAddress((void**)&wip, g_wip);
    cudaGetSymbolAddress((void**)&wop, g_wop);
    cudaGetSymbolAddress((void**)&w2p, g_w2p);
    cudaGetSymbolAddress((void**)&wtp, g_wtp);
    cudaGetSymbolAddress((void**)&wxp, g_wxp);

    const int smemI = (128*132) * sizeof(float);
    const int smemX = (8448 + 8448 + 64*XDS) * sizeof(float);
    const int smemM = (17408 + 8448 + 8448 + 64 + 64 + 256) * sizeof(float);
    static int attr_done = 0;
    if (!attr_done){
        cudaFuncSetAttribute(k_inproj, cudaFuncAttributeMaxDynamicSharedMemorySize, smemI);
        cudaFuncSetAttribute(k_cxp2,  cudaFuncAttributeMaxDynamicSharedMemorySize, smemX);
        cudaFuncSetAttribute(k_mega2, cudaFuncAttributeMaxDynamicSharedMemorySize, smemM);
        attr_done = 1;
    }

    k_prep<<<118, 256>>>(in_proj, out_proj, w2, wout, x_proj_w, wip, wop, w2p, wtp, wxp);
    k_g1<<<NPIX/32, 256>>>(x, w1, t1);
    k_dw<<<NPIX*32/256, 256>>>(t1, dw, xs);
    k_inproj<<<NPIX/128, 512, smemI>>>(xs, wip, u0, z);
    k_cxp2<<<NPIX/64, 512, smemX>>>(u0, conv1d_w, conv1d_b, wxp, dt_proj_w, dt_proj_b,
                                    A_log, u, dl, Bm, Cm, Pg, hE);
    k_scanB<<<64, 128>>>(Pg, hE, h0);
    k_mega2<<<BB*NC, 512, smemM>>>(dl, u, z, Bm, Cm, A_log, D_param, h0,
                                   wop, gamma, beta, x, w2p, wtp, out);
}

// round 14
// speedup vs baseline: 11.1087x; 1.1976x over previous
#include <cuda_runtime.h>
#include <math.h>
#include <stdint.h>

// Problem constants
#define BB 8
#define HH 64
#define WW 64
#define CC 128
#define DD 128
#define LL 4096            // H*W
#define NPIX (BB*LL)       // 32768
#define NS 8               // D_STATE
#define RR 8               // DT_RANK

#define CS 64              // chunk size (steps)
#define NC (LL/CS)         // 64 chunks per batch

// Scratch (device globals; no allocations allowed)
__device__ float g_t1[NPIX*DD];
__device__ float g_xs[NPIX*DD];
__device__ float g_u0[NPIX*DD];
__device__ float g_z [NPIX*DD];
__device__ float g_u [NPIX*DD];
__device__ float g_dl[NPIX*DD];
__device__ float g_Bm[NPIX*NS];
__device__ float g_Cm[NPIX*NS];
__device__ float g_P [BB*NC*1024];
__device__ float g_hE[BB*NC*1024];
__device__ float g_h0[BB*NC*1024];
// fragment-packed tf32 hi/lo weights: float4 {bh0, bh1, bl0, bl1} per (tile,k,lane)
__device__ float g_wip[65536];   // in_proj: 32 tiles x 16 k x 32 lanes
__device__ float g_wop[32768];   // out_proj: 16 tiles x 16 k x 32 lanes
__device__ float g_w2p[8192];    // w2 gate: 16 tiles x 4 k x 32 lanes
__device__ float g_wtp[8192];    // wout:    16 tiles x 4 k x 32 lanes
__device__ float g_wxp[6144];    // x_proj:  3 tiles x 16 k x 32 lanes

__device__ __forceinline__ float siluf(float v){ return v / (1.f + __expf(-v)); }

__device__ __forceinline__ uint32_t f2tf(float x){
    uint32_t r; asm("cvt.rna.tf32.f32 %0, %1;" : "=r"(r) : "f"(x)); return r;
}
__device__ __forceinline__ void mma8(float4& c, uint32_t a0, uint32_t a1, uint32_t a2, uint32_t a3,
                                     uint32_t b0, uint32_t b1){
    asm volatile("mma.sync.aligned.m16n8k8.row.col.f32.tf32.tf32.f32 "
                 "{%0,%1,%2,%3},{%4,%5,%6,%7},{%8,%9},{%0,%1,%2,%3};\n"
                 : "+f"(c.x), "+f"(c.y), "+f"(c.z), "+f"(c.w)
                 : "r"(a0), "r"(a1), "r"(a2), "r"(a3), "r"(b0), "r"(b1));
}
__device__ __forceinline__ void ldsm4(uint32_t& r0, uint32_t& r1, uint32_t& r2, uint32_t& r3,
                                      uint32_t addr){
    asm volatile("ldmatrix.sync.aligned.m8n8.x4.shared.b16 {%0,%1,%2,%3}, [%4];"
                 : "=r"(r0), "=r"(r1), "=r"(r2), "=r"(r3) : "r"(addr));
}
__device__ __forceinline__ float4 pack_hl(float v0, float v1){
    float h0 = __uint_as_float(f2tf(v0));
    float h1 = __uint_as_float(f2tf(v1));
    return make_float4(h0, h1, v0 - h0, v1 - h1);
}

// ---------------------------------------------------------------- K0: weight fragment-pack prep
__global__ void k_prep(const float* __restrict__ wi, const float* __restrict__ wo,
                       const float* __restrict__ w2, const float* __restrict__ wt,
                       const float* __restrict__ wx,
                       float* wip, float* wop, float* w2p, float* wtp, float* wxp){
    int i = blockIdx.x * 256 + threadIdx.x;
    if (i >= 30208) return;
    if (i < 16384){
        int lane = i & 31, k = (i >> 5) & 15, tile = i >> 9;
        int row = lane >> 2, col = lane & 3;
        int e = tile*8 + row, kc = k*8 + col;
        ((float4*)wip)[i] = pack_hl(wi[e*128 + kc], wi[e*128 + kc + 4]);
    } else if (i < 24576){
        int j = i - 16384;
        int lane = j & 31, k = (j >> 5) & 15, tile = j >> 9;
        int row = lane >> 2, col = lane & 3;
        int e = tile*8 + row, kc = k*8 + col;
        ((float4*)wop)[j] = pack_hl(wo[e*128 + kc], wo[e*128 + kc + 4]);
    } else if (i < 26624){
        int j = i - 24576;
        int lane = j & 31, k = (j >> 5) & 3, tile = j >> 7;
        int row = lane >> 2, col = lane & 3;
        int e = tile*8 + row;
        ((float4*)w2p)[j] = pack_hl(w2[e*32 + k*8 + col], w2[e*32 + k*8 + col + 4]);
    } else if (i < 28672){
        int j = i - 26624;
        int lane = j & 31, k = (j >> 5) & 3, tile = j >> 7;
        int row = lane >> 2, col = lane & 3;
        int e = tile*8 + row;
        ((float4*)wtp)[j] = pack_hl(wt[e*32 + k*8 + col], wt[e*32 + k*8 + col + 4]);
    } else {
        int j = i - 28672;
        int lane = j & 31, k = (j >> 5) & 15, tile = j >> 9;
        int row = lane >> 2, col = lane & 3;
        int e = tile*8 + row, kc = k*8 + col;
        ((float4*)wxp)[j] = pack_hl(wx[e*128 + kc], wx[e*128 + kc + 4]);
    }
}

// ---------------------------------------------------------------- K1: grouped 1x1
__global__ void __launch_bounds__(256) k_g1(const float* __restrict__ x,
                                            const float* __restrict__ w,
                                            float* __restrict__ out){
    __shared__ float xt[32*128];
    int pix0 = blockIdx.x * 32;
    const float4* x4 = (const float4*)(x + (size_t)pix0*128);
    for (int i = threadIdx.x; i < 32*32; i += 256) ((float4*)xt)[i] = x4[i];
    __syncthreads();
    int t = threadIdx.x;
    int c = t & 127, half = t >> 7;
    int g = c >> 5;
    float4 wr[8];
#pragma unroll
    for (int i = 0; i < 8; i++) wr[i] = ((const float4*)(w + c*32))[i];
    const float* xb = xt + (half*16)*128 + g*32;
    float* ob = out + ((size_t)pix0 + half*16)*128 + c;
#pragma unroll
    for (int p = 0; p < 16; p++){
        const float* xr = xb + p*128;
        float a = 0.f;
#pragma unroll
        for (int i = 0; i < 8; i++){
            float4 xv = *(const float4*)(xr + i*4);
            a = fmaf(wr[i].x, xv.x, a); a = fmaf(wr[i].y, xv.y, a);
            a = fmaf(wr[i].z, xv.z, a); a = fmaf(wr[i].w, xv.w, a);
        }
        ob[(size_t)p*128] = a;
    }
}

// ---------------------------------------------------------------- K2: depthwise 3x3 + silu
__global__ void k_dw(const float* __restrict__ t1, const float* __restrict__ dw,
                     float* __restrict__ out){
    int idx = blockIdx.x * 256 + threadIdx.x;
    int d4 = idx & 31; int pix = idx >> 5;
    int wc = pix & 63; int h = (pix >> 6) & 63; int b = pix >> 12;
    int d = d4 << 2;
    float4 acc = make_float4(0.f, 0.f, 0.f, 0.f);
#pragma unroll
    for (int kh = 0; kh < 3; kh++){
        int hh = h + kh - 1; if (hh < 0 || hh >= 64) continue;
#pragma unroll
        for (int kw = 0; kw < 3; kw++){
            int ww = wc + kw - 1; if (ww < 0 || ww >= 64) continue;
            float4 tv = *(const float4*)(t1 + (((b*64 + hh)*64 + ww) << 7) + d);
            float4 wv = *(const float4*)(dw + (kh*3 + kw)*128 + d);
            acc.x = fmaf(tv.x, wv.x, acc.x); acc.y = fmaf(tv.y, wv.y, acc.y);
            acc.z = fmaf(tv.z, wv.z, acc.z); acc.w = fmaf(tv.w, wv.w, acc.w);
        }
    }
    float4 r; r.x = siluf(acc.x); r.y = siluf(acc.y); r.z = siluf(acc.z); r.w = siluf(acc.w);
    *(float4*)(out + (size_t)pix*128 + d) = r;
}

// ---------------------------------------------------------------- K3: in_proj via tf32 mma (ldmatrix A, g-pair A reuse)
// 512 thr, 128 pixels/block, 256 blocks. warp = (mp 0..3: 32 px, nq 0..3)
__global__ void __launch_bounds__(512, 2) k_inproj(const float* __restrict__ xs,
                       const float* __restrict__ wip,
                       float* __restrict__ ub, float* __restrict__ zb){
    extern __shared__ float sm[];
    float* xt = sm;              // 128*132
    int tid = threadIdx.x;
    int pix0 = blockIdx.x * 128;
    {
        const float4* xs4 = (const float4*)(xs + (size_t)pix0*128);
        for (int i = tid; i < 128*32; i += 512){
            int p = i >> 5, q = i & 31;
            float4 v = xs4[i];
            v.x = __uint_as_float(f2tf(v.x)); v.y = __uint_as_float(f2tf(v.y));
            v.z = __uint_as_float(f2tf(v.z)); v.w = __uint_as_float(f2tf(v.w));
            *(float4*)(xt + p*132 + q*4) = v;
        }
    }
    __syncthreads();
    int warp = tid >> 5, lane = tid & 31;
    int row_ = lane >> 2, col_ = lane & 3;
    int mp = warp >> 2, nq = warp & 3;
    int m0 = mp * 32;
    int lr = lane & 15, lc = (lane >> 4) << 2;
    uint32_t xtb = (uint32_t)__cvta_generic_to_shared(xt);
    uint32_t aad0 = xtb + (((m0 + lr)*132 + lc) << 2);
    uint32_t aad1 = aad0 + (16*132 << 2);
    const float4* wip4 = (const float4*)wip;
#pragma unroll 1
    for (int gp = 0; gp < 2; gp++){
        float4 acc[2][4];               // [m][gg*2+tt]
#pragma unroll
        for (int mm = 0; mm < 2; mm++)
#pragma unroll
            for (int jj = 0; jj < 4; jj++) acc[mm][jj] = make_float4(0.f,0.f,0.f,0.f);
#pragma unroll 4
        for (int k = 0; k < 16; k++){
            uint32_t a0, a1, a2, a3, c0, c1, c2, c3;
            ldsm4(a0, a1, a2, a3, aad0 + k*32);
            ldsm4(c0, c1, c2, c3, aad1 + k*32);
#pragma unroll
            for (int jj = 0; jj < 4; jj++){
                int gg = jj >> 1, tt = jj & 1;
                int tile = (gp*2 + gg)*8 + nq*2 + tt;
                float4 bw = __ldg(wip4 + tile*512 + k*32 + lane);
                uint32_t bh0 = __float_as_uint(bw.x), bh1 = __float_as_uint(bw.y);
                uint32_t bl0 = __float_as_uint(bw.z), bl1 = __float_as_uint(bw.w);
                mma8(acc[0][jj], a0, a1, a2, a3, bh0, bh1);
                mma8(acc[0][jj], a0, a1, a2, a3, bl0, bl1);
                mma8(acc[1][jj], c0, c1, c2, c3, bh0, bh1);
                mma8(acc[1][jj], c0, c1, c2, c3, bl0, bl1);
            }
        }
#pragma unroll
        for (int jj = 0; jj < 4; jj++){
            int g = gp*2 + (jj >> 1), tt = jj & 1;
#pragma unroll
            for (int mm = 0; mm < 2; mm++){
                int pixA = pix0 + m0 + mm*16 + row_;
                int pixB = pixA + 8;
                int e0 = g*64 + (nq*2 + tt)*8 + 2*col_;
                float* basep = (g < 2) ? (ub + e0) : (zb + e0 - 128);
                *(float2*)(basep + (size_t)pixA*128) = make_float2(acc[mm][jj].x, acc[mm][jj].y);
                *(float2*)(basep + (size_t)pixB*128) = make_float2(acc[mm][jj].z, acc[mm][jj].w);
            }
        }
    }
}

// ---------------------------------------------------------------- K4: fused conv1d + x_proj(mma) + dt_proj + scanA
#define XDS 26
__global__ void __launch_bounds__(512, 2) k_cxp2(const float* __restrict__ u0,
                        const float* __restrict__ cw, const float* __restrict__ cb,
                        const float* __restrict__ wxp,
                        const float* __restrict__ dtw, const float* __restrict__ dtb,
                        const float* __restrict__ A_log,
                        float* __restrict__ ug,
                        float* __restrict__ dl, float* __restrict__ Bb, float* __restrict__ Cb,
                        float* __restrict__ Pg, float* __restrict__ hEg){
    extern __shared__ float sm[];
    float* u0s = sm;                 // 66*128 = 8448 ; aliased by sdl after conv
    float* su  = sm + 8448;          // 64*132
    float* xd  = sm + 16896;         // 64*XDS
    float* sdl = u0s;
    int pix0 = blockIdx.x * 64;
    int b = blockIdx.x >> 6;
    int c = blockIdx.x & 63;
    int l0 = pix0 & (LL - 1);
    int t = threadIdx.x, warp = t >> 5, lane = t & 31;
    {
        const float4* u4 = (const float4*)(u0 + ((size_t)pix0 - 2)*128);
        for (int i = t; i < 66*32; i += 512){
            int p = i >> 5;
            float4 v = make_float4(0.f,0.f,0.f,0.f);
            if (!(l0 == 0 && p < 2)) v = u4[i];
            ((float4*)u0s)[i] = v;
        }
    }
    __syncthreads();
    {
        int d = t & 127, ph = t >> 7;
        float w0 = cw[d*3], w1c = cw[d*3 + 1], w2c = cw[d*3 + 2];
        float bias = cb[d];
#pragma unroll 4
        for (int p = ph*16; p < ph*16 + 16; p++){
            float a = fmaf(w2c, u0s[(p + 2)*128 + d],
                      fmaf(w1c, u0s[(p + 1)*128 + d],
                      fmaf(w0,  u0s[p*128 + d], bias)));
            a = siluf(a);
            ug[(size_t)(pix0 + p)*128 + d] = a;
            su[p*132 + d] = a;
        }
    }
    __syncthreads();
    if (warp < 12){
        int m0 = (warp & 3) * 16;
        int ntile = warp >> 2;
        int row_ = lane >> 2, col_ = lane & 3;
        int lr = lane & 15, lc = (lane >> 4) << 2;
        uint32_t sub = (uint32_t)__cvta_generic_to_shared(su);
        uint32_t aad = sub + (((m0 + lr)*132 + lc) << 2);
        const float4* wxp4 = (const float4*)wxp;
        float4 acc = make_float4(0.f,0.f,0.f,0.f);
#pragma unroll 2
        for (int k = 0; k < 16; k++){
            uint32_t u0_, u1_, u2_, u3_;
            ldsm4(u0_, u1_, u2_, u3_, aad + k*32);
            float f0 = __uint_as_float(u0_), f1 = __uint_as_float(u1_);
            float f2 = __uint_as_float(u2_), f3 = __uint_as_float(u3_);
            uint32_t h0 = f2tf(f0), h1 = f2tf(f1), h2 = f2tf(f2), h3 = f2tf(f3);
            uint32_t l0_ = __float_as_uint(f0 - __uint_as_float(h0));
            uint32_t l1  = __float_as_uint(f1 - __uint_as_float(h1));
            uint32_t l2  = __float_as_uint(f2 - __uint_as_float(h2));
            uint32_t l3  = __float_as_uint(f3 - __uint_as_float(h3));
            float4 bw = __ldg(wxp4 + (ntile*16 + k)*32 + lane);
            uint32_t bh0 = __float_as_uint(bw.x), bh1 = __float_as_uint(bw.y);
            uint32_t bl0 = __float_as_uint(bw.z), bl1 = __float_as_uint(bw.w);
            mma8(acc, h0, h1, h2, h3, bh0, bh1);
            mma8(acc, h0, h1, h2, h3, bl0, bl1);
            mma8(acc, l0_, l1, l2, l3, bh0, bh1);
        }
        int pA = m0 + row_, pB = pA + 8;
        int cc = ntile*8 + 2*col_;
        *(float2*)(xd + pA*XDS + cc) = make_float2(acc.x, acc.y);
        *(float2*)(xd + pB*XDS + cc) = make_float2(acc.z, acc.w);
    }
    __syncthreads();
    {
        int d = t & 127, ph = t >> 7;
        float4 wa = ((const float4*)(dtw + d*8))[0];
        float4 wb = ((const float4*)(dtw + d*8))[1];
        float bias = dtb[d];
#pragma unroll 4
        for (int p = ph*16; p < ph*16 + 16; p++){
            const float* xr = xd + p*XDS;
            float a = bias;
            a = fmaf(xr[0], wa.x, a); a = fmaf(xr[1], wa.y, a);
            a = fmaf(xr[2], wa.z, a); a = fmaf(xr[3], wa.w, a);
            a = fmaf(xr[4], wb.x, a); a = fmaf(xr[5], wb.y, a);
            a = fmaf(xr[6], wb.z, a); a = fmaf(xr[7], wb.w, a);
            float sp = (a > 20.f) ? a : log1pf(__expf(a));
            dl[(size_t)(pix0 + p)*128 + d] = sp;
            sdl[p*128 + d] = sp;
        }
    }
    {
        int p = t >> 3, n = t & 7;
        Bb[(pix0 + p)*8 + n] = xd[p*XDS + 8 + n];
        Cb[(pix0 + p)*8 + n] = xd[p*XDS + 16 + n];
    }
    __syncthreads();
    {
        int d = t >> 2, np = (t & 3) * 2;
        float Av0 = -__expf(A_log[d*8 + np]);
        float Av1 = -__expf(A_log[d*8 + np + 1]);
        float h0 = 0.f, h1 = 0.f, P0 = 1.f, P1 = 1.f;
#pragma unroll 4
        for (int l = 0; l < CS; l++){
            float de = sdl[l*128 + d];
            float uu = su[l*132 + d];
            float du = de * uu;
            float2 Bv = *(const float2*)(xd + l*XDS + 8 + np);
            float dA0 = __expf(de * Av0);
            float dA1 = __expf(de * Av1);
            P0 *= dA0; P1 *= dA1;
            h0 = fmaf(dA0, h0, du * Bv.x);
            h1 = fmaf(dA1, h1, du * Bv.y);
        }
        size_t oidx = (size_t)(b*NC + c)*1024 + d*8 + np;
        *(float2*)(Pg + oidx) = make_float2(P0, P1);
        *(float2*)(hEg + oidx) = make_float2(h0, h1);
    }
}

// ---------------------------------------------------------------- K5: chunk combine
__global__ void k_scanB(const float* __restrict__ Pg, const float* __restrict__ hEg,
                        float* __restrict__ h0g){
    int j = blockIdx.x * 128 + threadIdx.x;
    int b = j >> 10, dn = j & 1023;
    float h = 0.f;
#pragma unroll 8
    for (int c = 0; c < NC; c++){
        int idx = (b*NC + c)*1024 + dn;
        h0g[idx] = h;
        h = fmaf(Pg[idx], h, hEg[idx]);
    }
}

// ---------------------------------------------------------------- K6: MEGA2 = scanC + out_proj + LN + gate GEMMs
// smem 104.5 KB -> 2 blocks/SM; scan reads dl/u direct from gmem (L1).
__global__ void __launch_bounds__(512, 2) k_mega2(
        const float* __restrict__ dl, const float* __restrict__ u,
        const float* __restrict__ z, const float* __restrict__ Bb,
        const float* __restrict__ Cb, const float* __restrict__ A_log,
        const float* __restrict__ Dp, const float* __restrict__ h0g,
        const float* __restrict__ wop,
        const float* __restrict__ gamma, const float* __restrict__ beta,
        const float* __restrict__ x,
        const float* __restrict__ w2p, const float* __restrict__ wtp,
        float* __restrict__ out){
    extern __shared__ float sm[];
    float* xt  = sm;              // 8448 (used phase 6+)
    float* r3  = sm + 8448;       // 8448: y -> fs
    float* mt  = sm + 16896;      // 8448
    float* sB  = sm + 25344;      // 512
    float* sC  = sB + 512;        // 512
    float* mus = sC + 512;        // 64
    float* rss = mus + 64;        // 64
    float* gb  = rss + 64;        // 256
    const float4* wop4 = (const float4*)wop;
    const float4* w2p4 = (const float4*)w2p;
    const float4* wtp4 = (const float4*)wtp;
    int b = blockIdx.x >> 6;
    int c = blockIdx.x & (NC - 1);
    int t = threadIdx.x, warp = t >> 5, lane = t & 31;
    int row_ = lane >> 2, col_ = lane & 3;
    int lr = lane & 15, lc = (lane >> 4) << 2;
    int pix0 = b*LL + c*CS;
    size_t base = (size_t)pix0*128;
    // phase 1: stage B/C + gamma/beta (dl/u read direct from gmem in scan)
    {
        int nb = pix0*8;
        if (t < CS*8){ sB[t] = Bb[nb + t]; sC[t] = Cb[nb + t]; }
        if (t < 128){ gb[t] = gamma[t]; gb[128 + t] = beta[t]; }
    }
    __syncthreads();
    // phase 2: scan (dl/u via L1; lines shared across the block's warps)
    {
        int d = t >> 2, np = (t & 3) * 2;
        float Av0 = -__expf(A_log[d*8 + np]);
        float Av1 = -__expf(A_log[d*8 + np + 1]);
        float2 h = *(const float2*)(h0g + (size_t)(b*NC + c)*1024 + d*8 + np);
        const float* dlp = dl + base + d;
        const float* up  = u + base + d;
#pragma unroll 4
        for (int l = 0; l < CS; l++){
            float de = __ldg(dlp + l*128);
            float uu = __ldg(up + l*128);
            float du = de * uu;
            float2 Bv = *(const float2*)(sB + l*8 + np);
            float2 Cv = *(const float2*)(sC + l*8 + np);
            h.x = fmaf(__expf(de * Av0), h.x, du * Bv.x);
            h.y = fmaf(__expf(de * Av1), h.y, du * Bv.y);
            float y = h.x * Cv.x + h.y * Cv.y;
            y += __shfl_xor_sync(0xffffffffu, y, 1);
            y += __shfl_xor_sync(0xffffffffu, y, 2);
            if ((t & 3) == 0) r3[l*132 + d] = y;
        }
    }
    __syncthreads();
    // phase 3: y + u*D, gate silu(z), tf32 (u re-read coalesced)
    {
        for (int i = t; i < CS*128; i += 512){
            int l = i >> 7, d = i & 127;
            float val = fmaf(__ldg(u + base + i), Dp[d], r3[l*132 + d]);
            val *= siluf(z[base + i]);
            r3[l*132 + d] = __uint_as_float(f2tf(val));
        }
    }
    __syncthreads();
    // phase 5: out_proj GEMM (warp = (mp 0..1, tp 0..7); ldmatrix A, B direct-LDG)
    {
        int mp = warp >> 3, tp = warp & 7;
        int m0 = mp * 32;
        uint32_t r3b = (uint32_t)__cvta_generic_to_shared(r3);
        uint32_t yad0 = r3b + (((m0 + lr)*132 + lc) << 2);
        uint32_t yad1 = yad0 + (16*132 << 2);
        float4 acc[2][2];
#pragma unroll
        for (int mm = 0; mm < 2; mm++)
#pragma unroll
            for (int tt = 0; tt < 2; tt++) acc[mm][tt] = make_float4(0.f,0.f,0.f,0.f);
#pragma unroll 4
        for (int k = 0; k < 16; k++){
            uint32_t a0, a1, a2, a3, c0, c1, c2, c3;
            ldsm4(a0, a1, a2, a3, yad0 + k*32);
            ldsm4(c0, c1, c2, c3, yad1 + k*32);
#pragma unroll
            for (int tt = 0; tt < 2; tt++){
                int tile = tp*2 + tt;
                float4 bw = __ldg(wop4 + tile*512 + k*32 + lane);
                uint32_t bh0 = __float_as_uint(bw.x), bh1 = __float_as_uint(bw.y);
                uint32_t bl0 = __float_as_uint(bw.z), bl1 = __float_as_uint(bw.w);
                mma8(acc[0][tt], a0, a1, a2, a3, bh0, bh1);
                mma8(acc[0][tt], a0, a1, a2, a3, bl0, bl1);
                mma8(acc[1][tt], c0, c1, c2, c3, bh0, bh1);
                mma8(acc[1][tt], c0, c1, c2, c3, bl0, bl1);
            }
        }
#pragma unroll
        for (int mm = 0; mm < 2; mm++){
            int pA = m0 + mm*16 + row_, pB = pA + 8;
#pragma unroll
            for (int tt = 0; tt < 2; tt++){
                int e = (tp*2 + tt)*8 + 2*col_;
                *(float2*)(mt + pA*132 + e) = make_float2(acc[mm][tt].x, acc[mm][tt].y);
                *(float2*)(mt + pB*132 + e) = make_float2(acc[mm][tt].z, acc[mm][tt].w);
            }
        }
    }
    __syncthreads();
    // phase 6: xt (tf32); LN stats
    {
        const float4* x4 = (const float4*)(x + base);
        for (int i = t; i < 64*32; i += 512){
            int p = i >> 5, q = i & 31;
            float4 v = x4[i];
            v.x = __uint_as_float(f2tf(v.x)); v.y = __uint_as_float(f2tf(v.y));
            v.z = __uint_as_float(f2tf(v.z)); v.w = __uint_as_float(f2tf(v.w));
            *(float4*)(xt + p*132 + q*4) = v;
        }
    }
    for (int p = warp*4; p < warp*4 + 4; p++){
        float4 v = *(const float4*)(mt + p*132 + lane*4);
        float s = v.x + v.y + v.z + v.w;
        s += __shfl_xor_sync(0xffffffffu, s, 16);
        s += __shfl_xor_sync(0xffffffffu, s, 8);
        s += __shfl_xor_sync(0xffffffffu, s, 4);
        s += __shfl_xor_sync(0xffffffffu, s, 2);
        s += __shfl_xor_sync(0xffffffffu, s, 1);
        float mu = s * (1.f/128.f);
        float dx = v.x - mu, dy = v.y - mu, dz = v.z - mu, dww = v.w - mu;
        float q = dx*dx + dy*dy + dz*dz + dww*dww;
        q += __shfl_xor_sync(0xffffffffu, q, 16);
        q += __shfl_xor_sync(0xffffffffu, q, 8);
        q += __shfl_xor_sync(0xffffffffu, q, 4);
        q += __shfl_xor_sync(0xffffffffu, q, 2);
        q += __shfl_xor_sync(0xffffffffu, q, 1);
        if (lane == 0){
            mus[p] = mu;
            rss[p] = rsqrtf(q * (1.f/128.f) + 1e-5f);
        }
    }
    __syncthreads();
    int p0 = (warp >> 2) * 16;
    int cq = warp & 3;
    int pA = p0 + row_, pB = pA + 8;
    // phase 7: gate GEMM + LN combine -> fs (r3, tf32); A hoisted via ldmatrix
    {
        uint32_t xtb = (uint32_t)__cvta_generic_to_shared(xt);
        uint32_t xad = xtb + (((p0 + lr)*132 + lc + cq*32) << 2);
        uint32_t af[4][4];
#pragma unroll
        for (int k = 0; k < 4; k++) ldsm4(af[k][0], af[k][1], af[k][2], af[k][3], xad + k*32);
#pragma unroll 1
        for (int nt = 0; nt < 4; nt++){
            int c0 = cq*32 + nt*8;
            int tile = cq*4 + nt;
            float4 acc = make_float4(0.f,0.f,0.f,0.f);
#pragma unroll
            for (int k = 0; k < 4; k++){
                float4 bw = __ldg(w2p4 + (tile*4 + k)*32 + lane);
                mma8(acc, af[k][0], af[k][1], af[k][2], af[k][3],
                     __float_as_uint(bw.x), __float_as_uint(bw.y));
                mma8(acc, af[k][0], af[k][1], af[k][2], af[k][3],
                     __float_as_uint(bw.z), __float_as_uint(bw.w));
            }
            int cc = c0 + 2*col_;
            float g0 = gb[cc], g1 = gb[cc + 1], b0 = gb[128 + cc], b1 = gb[128 + cc + 1];
            float vx = fmaf((mt[pA*132 + cc]     - mus[pA]) * rss[pA], g0, b0) * siluf(acc.x);
            float vy = fmaf((mt[pA*132 + cc + 1] - mus[pA]) * rss[pA], g1, b1) * siluf(acc.y);
            float vz = fmaf((mt[pB*132 + cc]     - mus[pB]) * rss[pB], g0, b0) * siluf(acc.z);
            float vw = fmaf((mt[pB*132 + cc + 1] - mus[pB]) * rss[pB], g1, b1) * siluf(acc.w);
            *(float2*)(r3 + pA*132 + cc) = make_float2(__uint_as_float(f2tf(vx)), __uint_as_float(f2tf(vy)));
            *(float2*)(r3 + pB*132 + cc) = make_float2(__uint_as_float(f2tf(vz)), __uint_as_float(f2tf(vw)));
        }
    }
    __syncwarp();
    // phase 8: final grouped1x1 -> out; A hoisted via ldmatrix
    {
        uint32_t r3b = (uint32_t)__cvta_generic_to_shared(r3);
        uint32_t fad = r3b + (((p0 + lr)*132 + lc + cq*32) << 2);
        uint32_t af[4][4];
#pragma unroll
        for (int k = 0; k < 4; k++) ldsm4(af[k][0], af[k][1], af[k][2], af[k][3], fad + k*32);
#pragma unroll 1
        for (int nt = 0; nt < 4; nt++){
            int c0 = cq*32 + nt*8;
            int tile = cq*4 + nt;
            float4 acc = make_float4(0.f,0.f,0.f,0.f);
#pragma unroll
            for (int k = 0; k < 4; k++){
                float4 bw = __ldg(wtp4 + (tile*4 + k)*32 + lane);
                mma8(acc, af[k][0], af[k][1], af[k][2], af[k][3],
                     __float_as_uint(bw.x), __float_as_uint(bw.y));
                mma8(acc, af[k][0], af[k][1], af[k][2], af[k][3],
                     __float_as_uint(bw.z), __float_as_uint(bw.w));
            }
            int cc = c0 + 2*col_;
            *(float2*)(out + (size_t)(pix0 + pA)*128 + cc) = make_float2(acc.x, acc.y);
            *(float2*)(out + (size_t)(pix0 + pB)*128 + cc) = make_float2(acc.z, acc.w);
        }
    }
}

// ----------------------------------------------------------------
extern "C" void kernel_launch(void* const* d_in, const int* in_sizes, int n_in,
                              void* d_out, int out_size){
    const float* x        = (const float*)d_in[0];
    const float* w1       = (const float*)d_in[1];
    const float* dw       = (const float*)d_in[2];
    const float* in_proj  = (const float*)d_in[3];
    const float* conv1d_w = (const float*)d_in[4];
    const float* conv1d_b = (const float*)d_in[5];
    const float* x_proj_w = (const float*)d_in[6];
    const float* dt_proj_w= (const float*)d_in[7];
    const float* dt_proj_b= (const float*)d_in[8];
    const float* A_log    = (const float*)d_in[9];
    const float* D_param  = (const float*)d_in[10];
    const float* out_proj = (const float*)d_in[11];
    const float* gamma    = (const float*)d_in[12];
    const float* beta     = (const float*)d_in[13];
    const float* w2       = (const float*)d_in[14];
    const float* wout     = (const float*)d_in[15];
    float* out = (float*)d_out;

    float *t1, *xs, *u0, *z, *u, *dl, *Bm, *Cm, *Pg, *hE, *h0;
    float *wip, *wop, *w2p, *wtp, *wxp;
    cudaGetSymbolAddress((void**)&t1, g_t1);
    cudaGetSymbolAddress((void**)&xs, g_xs);
    cudaGetSymbolAddress((void**)&u0, g_u0);
    cudaGetSymbolAddress((void**)&z,  g_z);
    cudaGetSymbolAddress((void**)&u,  g_u);
    cudaGetSymbolAddress((void**)&dl, g_dl);
    cudaGetSymbolAddress((void**)&Bm, g_Bm);
    cudaGetSymbolAddress((void**)&Cm, g_Cm);
    cudaGetSymbolAddress((void**)&Pg, g_P);
    cudaGetSymbolAddress((void**)&hE, g_hE);
    cudaGetSymbolAddress((void**)&h0, g_h0);
    cudaGetSymbolAddress((void**)&wip, g_wip);
    cudaGetSymbolAddress((void**)&wop, g_wop);
    cudaGetSymbolAddress((void**)&w2p, g_w2p);
    cudaGetSymbolAddress((void**)&wtp, g_wtp);
    cudaGetSymbolAddress((void**)&wxp, g_wxp);

    const int smemI = (128*132) * sizeof(float);
    const int smemX = (8448 + 8448 + 64*XDS) * sizeof(float);
    const int smemM = (8448 + 8448 + 8448 + 512 + 512 + 64 + 64 + 256) * sizeof(float); // 104.5 KB
    static int attr_done = 0;
    if (!attr_done){
        cudaFuncSetAttribute(k_inproj, cudaFuncAttributeMaxDynamicSharedMemorySize, smemI);
        cudaFuncSetAttribute(k_cxp2,  cudaFuncAttributeMaxDynamicSharedMemorySize, smemX);
        cudaFuncSetAttribute(k_mega2, cudaFuncAttributeMaxDynamicSharedMemorySize, smemM);
        attr_done = 1;
    }

    k_prep<<<118, 256>>>(in_proj, out_proj, w2, wout, x_proj_w, wip, wop, w2p, wtp, wxp);
    k_g1<<<NPIX/32, 256>>>(x, w1, t1);
    k_dw<<<NPIX*32/256, 256>>>(t1, dw, xs);
    k_inproj<<<NPIX/128, 512, smemI>>>(xs, wip, u0, z);
    k_cxp2<<<NPIX/64, 512, smemX>>>(u0, conv1d_w, conv1d_b, wxp, dt_proj_w, dt_proj_b,
                                    A_log, u, dl, Bm, Cm, Pg, hE);
    k_scanB<<<64, 128>>>(Pg, hE, h0);
    k_mega2<<<BB*NC, 512, smemM>>>(dl, u, z, Bm, Cm, A_log, D_param, h0,
                                   wop, gamma, beta, x, w2p, wtp, out);
}